// round 2
// baseline (speedup 1.0000x reference)
#include <cuda_runtime.h>
#include <math.h>

#define NN 50000      // nodes
#define NE 800000     // edges per layer
#define DD 128        // feature dim
#define NO 20         // output dim
#define NLH 6         // hidden (gated) layers
#define BN_EPS 1e-5f

// ---------------- scratch (static device globals; no allocation) ----------------
__device__ float g_x[NN * DD];
__device__ float g_sup[NN * DD];
__device__ float g_h[NN * DD];
__device__ float g_gate[NN * DD];
__device__ float g_sup20[NN * NO];
__device__ float g_h20[NN * NO];
__device__ float g_stats[2 * DD];
__device__ float g_acc[32];

// ---------------- kernels ----------------

// x[i, :] = emb[vertices[i], :]
__global__ void gather_kernel(const int* __restrict__ verts,
                              const float* __restrict__ emb,
                              float* __restrict__ x) {
    int idx = blockIdx.x * blockDim.x + threadIdx.x;
    if (idx >= NN * DD) return;
    int row = idx >> 7;
    int col = idx & 127;
    x[idx] = emb[(size_t)verts[row] * DD + col];
}

// C[NN,128] = A[NN,128] @ W[128,128]  (+= if accum)
// block: 256 threads, 64 rows; thread computes 8 rows x 4 cols
__global__ __launch_bounds__(256) void gemm128(const float* __restrict__ A,
                                               const float* __restrict__ W,
                                               float* __restrict__ C,
                                               int accum) {
    __shared__ float As[64][32];
    __shared__ float Ws[32][128];
    int tid = threadIdx.x;
    int warp = tid >> 5, lane = tid & 31;
    int row0 = blockIdx.x * 64;

    float acc[8][4];
#pragma unroll
    for (int r = 0; r < 8; r++)
#pragma unroll
        for (int c = 0; c < 4; c++) acc[r][c] = 0.f;

    for (int k0 = 0; k0 < 128; k0 += 32) {
#pragma unroll
        for (int j = 0; j < 8; j++) {
            int l = tid + 256 * j;
            int r = l >> 5, c = l & 31;
            int gr = row0 + r;
            As[r][c] = (gr < NN) ? A[(size_t)gr * 128 + k0 + c] : 0.f;
        }
#pragma unroll
        for (int j = 0; j < 16; j++) {
            int l = tid + 256 * j;
            int r = l >> 7, c = l & 127;
            Ws[r][c] = W[(size_t)(k0 + r) * 128 + c];
        }
        __syncthreads();
#pragma unroll
        for (int kk = 0; kk < 32; kk++) {
            float a[8], b[4];
#pragma unroll
            for (int r = 0; r < 8; r++) a[r] = As[warp * 8 + r][kk];
#pragma unroll
            for (int c = 0; c < 4; c++) b[c] = Ws[kk][lane + 32 * c];
#pragma unroll
            for (int r = 0; r < 8; r++)
#pragma unroll
                for (int c = 0; c < 4; c++) acc[r][c] += a[r] * b[c];
        }
        __syncthreads();
    }

#pragma unroll
    for (int r = 0; r < 8; r++) {
        int gr = row0 + warp * 8 + r;
        if (gr < NN) {
#pragma unroll
            for (int c = 0; c < 4; c++) {
                size_t o = (size_t)gr * 128 + lane + 32 * c;
                if (accum) C[o] += acc[r][c];
                else C[o] = acc[r][c];
            }
        }
    }
}

// C[NN,20] = A[NN,128] @ W[128,20]
__global__ __launch_bounds__(256) void gemm_out(const float* __restrict__ A,
                                                const float* __restrict__ W,
                                                float* __restrict__ C) {
    __shared__ float Ws[128 * NO];
    for (int l = threadIdx.x; l < 128 * NO; l += 256) Ws[l] = W[l];
    __syncthreads();
    int idx = blockIdx.x * 256 + threadIdx.x;
    if (idx >= NN * NO) return;
    int row = idx / NO, col = idx % NO;
    const float4* a4 = reinterpret_cast<const float4*>(A + (size_t)row * 128);
    float s = 0.f;
#pragma unroll
    for (int k = 0; k < 32; k++) {
        float4 a = a4[k];
        s += a.x * Ws[(k * 4 + 0) * NO + col];
        s += a.y * Ws[(k * 4 + 1) * NO + col];
        s += a.z * Ws[(k * 4 + 2) * NO + col];
        s += a.w * Ws[(k * 4 + 3) * NO + col];
    }
    C[idx] = s;
}

// h[dst] += w * sup[src]  — warp per edge, float4 lanes, vector RED
__global__ __launch_bounds__(256) void spmm128(const int* __restrict__ src,
                                               const int* __restrict__ dst,
                                               const float* __restrict__ w,
                                               const float* __restrict__ sup,
                                               float* __restrict__ h) {
    int gw = (blockIdx.x * blockDim.x + threadIdx.x) >> 5;
    int lane = threadIdx.x & 31;
    if (gw >= NE) return;
    int s = src[gw], d = dst[gw];
    float wt = w[gw];
    float4 v = reinterpret_cast<const float4*>(sup)[(size_t)s * 32 + lane];
    float4* outp = reinterpret_cast<float4*>(h) + (size_t)d * 32 + lane;
    asm volatile("red.global.add.v4.f32 [%0], {%1,%2,%3,%4};"
                 :: "l"(outp), "f"(wt * v.x), "f"(wt * v.y),
                    "f"(wt * v.z), "f"(wt * v.w)
                 : "memory");
}

// h20[dst] += w * sup20[src]  — warp per edge, lanes 0..19
__global__ __launch_bounds__(256) void spmm20(const int* __restrict__ src,
                                              const int* __restrict__ dst,
                                              const float* __restrict__ w,
                                              const float* __restrict__ sup,
                                              float* __restrict__ h) {
    int gw = (blockIdx.x * blockDim.x + threadIdx.x) >> 5;
    int lane = threadIdx.x & 31;
    if (gw >= NE) return;
    int s = src[gw], d = dst[gw];
    float wt = w[gw];
    if (lane < NO) {
        float v = sup[(size_t)s * NO + lane];
        atomicAdd(&h[(size_t)d * NO + lane], wt * v);
    }
}

// per-column sum & sumsq over the node axis (128 cols)
__global__ void colstats(const float* __restrict__ h, float* __restrict__ stats) {
    int col = threadIdx.x;  // 128 threads
    int rows_per = (NN + gridDim.x - 1) / gridDim.x;
    int r0 = blockIdx.x * rows_per;
    int r1 = min(r0 + rows_per, NN);
    float s = 0.f, ss = 0.f;
    for (int r = r0; r < r1; r++) {
        float v = h[(size_t)r * 128 + col];
        s += v; ss += v * v;
    }
    atomicAdd(&stats[col], s);
    atomicAdd(&stats[128 + col], ss);
}

// per-column stats for the 20-wide output
__global__ void colstats20(const float* __restrict__ h, float* __restrict__ stats) {
    int col = threadIdx.x;  // 32 threads, only <20 active
    if (col >= NO) return;
    int rows_per = (NN + gridDim.x - 1) / gridDim.x;
    int r0 = blockIdx.x * rows_per;
    int r1 = min(r0 + rows_per, NN);
    float s = 0.f, ss = 0.f;
    for (int r = r0; r < r1; r++) {
        float v = h[(size_t)r * NO + col];
        s += v; ss += v * v;
    }
    atomicAdd(&stats[col], s);
    atomicAdd(&stats[128 + col], ss);
}

// h = relu((h - mean) * rsqrt(var+eps) * gamma + beta)   (bias pre-BN cancels)
__global__ void bnrelu(float* __restrict__ h, const float* __restrict__ stats,
                       const float* __restrict__ gamma, const float* __restrict__ beta) {
    int idx = blockIdx.x * blockDim.x + threadIdx.x;
    if (idx >= NN * DD) return;
    int col = idx & 127;
    float mean = stats[col] * (1.f / NN);
    float var = stats[128 + col] * (1.f / NN) - mean * mean;
    float v = (h[idx] - mean) * rsqrtf(var + BN_EPS) * gamma[col] + beta[col];
    h[idx] = fmaxf(v, 0.f);
}

__global__ void bnrelu20(float* __restrict__ h, const float* __restrict__ stats,
                         const float* __restrict__ gamma, const float* __restrict__ beta) {
    int idx = blockIdx.x * blockDim.x + threadIdx.x;
    if (idx >= NN * NO) return;
    int col = idx % NO;
    float mean = stats[col] * (1.f / NN);
    float var = stats[128 + col] * (1.f / NN) - mean * mean;
    float v = (h[idx] - mean) * rsqrtf(var + BN_EPS) * gamma[col] + beta[col];
    h[idx] = fmaxf(v, 0.f);   // relu(x) after loop in reference
}

// g = sigmoid(gpre + b); x = g*h + (1-g)*x
__global__ void gate_apply(float* __restrict__ x, const float* __restrict__ h,
                           const float* __restrict__ gpre, const float* __restrict__ b) {
    int idx = blockIdx.x * blockDim.x + threadIdx.x;
    if (idx >= NN * DD) return;
    int col = idx & 127;
    float g = 1.f / (1.f + expf(-(gpre[idx] + b[col])));
    x[idx] = g * h[idx] + (1.f - g) * x[idx];
}

// acc[o] += sum_r mask_w[verts[r]] * x20[r, o]
__global__ void maskreduce(const float* __restrict__ x20, const int* __restrict__ verts,
                           const float* __restrict__ mask_w, float* __restrict__ acc) {
    int gw = (blockIdx.x * blockDim.x + threadIdx.x) >> 5;
    int lane = threadIdx.x & 31;
    int nwarps = (gridDim.x * blockDim.x) >> 5;
    float a = 0.f;
    for (int r = gw; r < NN; r += nwarps) {
        float mw = mask_w[verts[r]];
        if (lane < NO) a += mw * x20[(size_t)r * NO + lane];
    }
    if (lane < NO) atomicAdd(&acc[lane], a);
}

__global__ void finalize(const float* __restrict__ acc, const float* __restrict__ mask_b,
                         float* __restrict__ out) {
    int o = threadIdx.x;
    if (o < NO) out[o] = 1.f / (1.f + expf(-(acc[o] + mask_b[o])));
}

// ---------------- launch ----------------
extern "C" void kernel_launch(void* const* d_in, const int* in_sizes, int n_in,
                              void* d_out, int out_size) {
    const int*   vertices    = (const int*)d_in[0];
    const int*   edge_index  = (const int*)d_in[1];   // [7,2,NE]
    const float* edge_weight = (const float*)d_in[2]; // [7,NE]
    const float* emb         = (const float*)d_in[3];
    const float* w_h         = (const float*)d_in[4]; // [6,128,128]
    // d_in[5] gcn_b_hidden: cancels through BN
    const float* w_out       = (const float*)d_in[6]; // [128,20]
    // d_in[7] gcn_b_out: cancels through BN
    const float* bng         = (const float*)d_in[8];
    const float* bnb         = (const float*)d_in[9];
    const float* bng_o       = (const float*)d_in[10];
    const float* bnb_o       = (const float*)d_in[11];
    const float* te_wl       = (const float*)d_in[12];
    const float* te_wc       = (const float*)d_in[13];
    const float* te_b        = (const float*)d_in[14];
    const float* mask_w      = (const float*)d_in[15];
    const float* mask_b      = (const float*)d_in[16];
    float* out = (float*)d_out;

    float *x, *sup, *h, *gate, *sup20, *h20, *stats, *acc;
    cudaGetSymbolAddress((void**)&x,     g_x);
    cudaGetSymbolAddress((void**)&sup,   g_sup);
    cudaGetSymbolAddress((void**)&h,     g_h);
    cudaGetSymbolAddress((void**)&gate,  g_gate);
    cudaGetSymbolAddress((void**)&sup20, g_sup20);
    cudaGetSymbolAddress((void**)&h20,   g_h20);
    cudaGetSymbolAddress((void**)&stats, g_stats);
    cudaGetSymbolAddress((void**)&acc,   g_acc);

    const int EW_BLK = 256;
    const int ND_BLOCKS = (NN * DD + 255) / 256;
    const int SPMM_BLOCKS = (NE * 32 + EW_BLK - 1) / EW_BLK;
    const int GEMM_BLOCKS = (NN + 63) / 64;

    gather_kernel<<<ND_BLOCKS, 256>>>(vertices, emb, x);

    for (int i = 0; i < NLH; i++) {
        const int* src = edge_index + (size_t)i * 2 * NE;
        const int* dst = src + NE;
        const float* ew = edge_weight + (size_t)i * NE;

        gemm128<<<GEMM_BLOCKS, 256>>>(x, w_h + (size_t)i * DD * DD, sup, 0);
        cudaMemsetAsync(h, 0, (size_t)NN * DD * sizeof(float));
        spmm128<<<SPMM_BLOCKS, EW_BLK>>>(src, dst, ew, sup, h);
        cudaMemsetAsync(stats, 0, 2 * DD * sizeof(float));
        colstats<<<196, 128>>>(h, stats);
        bnrelu<<<ND_BLOCKS, 256>>>(h, stats, bng + i * DD, bnb + i * DD);

        int j = (i + 5) % 6;  // faithful to reference's (i-1) % (L-1)
        gemm128<<<GEMM_BLOCKS, 256>>>(x, te_wl + (size_t)j * DD * DD, gate, 0);
        gemm128<<<GEMM_BLOCKS, 256>>>(h, te_wc + (size_t)j * DD * DD, gate, 1);
        gate_apply<<<ND_BLOCKS, 256>>>(x, h, gate, te_b + j * DD);
    }

    // output layer (i = 6)
    {
        const int* src = edge_index + (size_t)6 * 2 * NE;
        const int* dst = src + NE;
        const float* ew = edge_weight + (size_t)6 * NE;

        gemm_out<<<(NN * NO + 255) / 256, 256>>>(x, w_out, sup20);
        cudaMemsetAsync(h20, 0, (size_t)NN * NO * sizeof(float));
        spmm20<<<SPMM_BLOCKS, EW_BLK>>>(src, dst, ew, sup20, h20);
        cudaMemsetAsync(stats, 0, 2 * DD * sizeof(float));
        colstats20<<<196, 32>>>(h20, stats);
        bnrelu20<<<(NN * NO + 255) / 256, 256>>>(h20, stats, bng_o, bnb_o);
    }

    cudaMemsetAsync(acc, 0, 32 * sizeof(float));
    maskreduce<<<200, 256>>>(h20, vertices, mask_w, acc);
    finalize<<<1, 32>>>(acc, mask_b, out);
}

// round 3
// speedup vs baseline: 1.3579x; 1.3579x over previous
#include <cuda_runtime.h>
#include <math.h>

#define NN 50000      // nodes
#define NE 800000     // edges per layer
#define DD 128        // feature dim
#define NO 20         // output dim
#define NLH 6         // hidden (gated) layers
#define BN_EPS 1e-5f

// ---------------- scratch (static device globals; no allocation) ----------------
__device__ __align__(16) float g_x[NN * DD];
__device__ __align__(16) float g_sup[NN * DD];
__device__ __align__(16) float g_h[NN * DD];
__device__ __align__(16) float g_sup20[NN * NO];
__device__ __align__(16) float g_h20[NN * NO];
__device__ float g_stats[2 * DD];
__device__ float g_acc[32];

// ---------------- tf32 helpers ----------------
__device__ __forceinline__ unsigned f2tf(float f) {
    unsigned u;
    asm("cvt.rna.tf32.f32 %0, %1;" : "=r"(u) : "f"(f));
    return u;
}

#define AS_STRIDE 36    // 128 rows x 32 cols A tile, padded: bank = 4g+c (conflict-free)
#define WS_STRIDE 136   // 32 rows x 128 cols W tile, padded: bank = 8c+g (conflict-free)

// Load A chunk [128 rows][cols kc*32..+32) at row0, tf32-converted, into smem.
__device__ __forceinline__ void load_A_chunk(const float* __restrict__ A, int row0, int kc,
                                             unsigned* As, int tid) {
#pragma unroll
    for (int t = 0; t < 4; t++) {
        int e = tid + 256 * t;
        int r = e >> 3, q = e & 7;
        int gr = row0 + r;
        float4 v = make_float4(0.f, 0.f, 0.f, 0.f);
        if (gr < NN) v = reinterpret_cast<const float4*>(A)[(size_t)gr * 32 + kc * 8 + q];
        unsigned* p = As + r * AS_STRIDE + q * 4;
        p[0] = f2tf(v.x); p[1] = f2tf(v.y); p[2] = f2tf(v.z); p[3] = f2tf(v.w);
    }
}

// Load W chunk [rows kc*32..+32)][128 cols], tf32-converted, into smem.
__device__ __forceinline__ void load_W_chunk(const float* __restrict__ W, int kc,
                                             unsigned* Ws, int tid) {
#pragma unroll
    for (int t = 0; t < 4; t++) {
        int e = tid + 256 * t;
        int k = e >> 5, q = e & 31;
        float4 v = reinterpret_cast<const float4*>(W)[(size_t)(kc * 32 + k) * 32 + q];
        unsigned* p = Ws + k * WS_STRIDE + q * 4;
        p[0] = f2tf(v.x); p[1] = f2tf(v.y); p[2] = f2tf(v.z); p[3] = f2tf(v.w);
    }
}

// One BK=32 chunk of mma.m16n8k8 tf32. Warp tile 64x32 (4 m-frags x 4 n-frags).
__device__ __forceinline__ void mma_chunk(const unsigned* As, const unsigned* Ws,
                                          float acc[4][4][4],
                                          int warp_m, int warp_n, int lane) {
    int g = lane >> 2, c = lane & 3;
#pragma unroll
    for (int kk = 0; kk < 4; kk++) {
        unsigned a[4][4];
#pragma unroll
        for (int mi = 0; mi < 4; mi++) {
            const unsigned* base = As + (warp_m * 64 + mi * 16 + g) * AS_STRIDE + kk * 8 + c;
            a[mi][0] = base[0];
            a[mi][1] = base[8 * AS_STRIDE];
            a[mi][2] = base[4];
            a[mi][3] = base[8 * AS_STRIDE + 4];
        }
        unsigned b[4][2];
#pragma unroll
        for (int nj = 0; nj < 4; nj++) {
            const unsigned* base = Ws + (kk * 8 + c) * WS_STRIDE + warp_n * 32 + nj * 8 + g;
            b[nj][0] = base[0];
            b[nj][1] = base[4 * WS_STRIDE];
        }
#pragma unroll
        for (int mi = 0; mi < 4; mi++)
#pragma unroll
            for (int nj = 0; nj < 4; nj++) {
                asm volatile(
                    "mma.sync.aligned.m16n8k8.row.col.f32.tf32.tf32.f32 "
                    "{%0,%1,%2,%3}, {%4,%5,%6,%7}, {%8,%9}, {%0,%1,%2,%3};\n"
                    : "+f"(acc[mi][nj][0]), "+f"(acc[mi][nj][1]),
                      "+f"(acc[mi][nj][2]), "+f"(acc[mi][nj][3])
                    : "r"(a[mi][0]), "r"(a[mi][1]), "r"(a[mi][2]), "r"(a[mi][3]),
                      "r"(b[nj][0]), "r"(b[nj][1]));
            }
    }
}

// C[NN,128] = A[NN,128] @ W[128,128]   (tensor-core tf32)
__global__ __launch_bounds__(256) void gemm_tc(const float* __restrict__ A,
                                               const float* __restrict__ W,
                                               float* __restrict__ C) {
    __shared__ unsigned As[128 * AS_STRIDE];
    __shared__ unsigned Ws[32 * WS_STRIDE];
    int tid = threadIdx.x, wid = tid >> 5, lane = tid & 31;
    int warp_m = wid & 1, warp_n = wid >> 1;
    int row0 = blockIdx.x * 128;

    float acc[4][4][4];
#pragma unroll
    for (int mi = 0; mi < 4; mi++)
#pragma unroll
        for (int nj = 0; nj < 4; nj++)
#pragma unroll
            for (int q = 0; q < 4; q++) acc[mi][nj][q] = 0.f;

#pragma unroll
    for (int kc = 0; kc < 4; kc++) {
        load_A_chunk(A, row0, kc, As, tid);
        load_W_chunk(W, kc, Ws, tid);
        __syncthreads();
        mma_chunk(As, Ws, acc, warp_m, warp_n, lane);
        __syncthreads();
    }

    int g = lane >> 2, c = lane & 3;
#pragma unroll
    for (int mi = 0; mi < 4; mi++) {
        int r0 = row0 + warp_m * 64 + mi * 16 + g;
#pragma unroll
        for (int nj = 0; nj < 4; nj++) {
            int col = warp_n * 32 + nj * 8 + c * 2;
            if (r0 < NN)
                *reinterpret_cast<float2*>(C + (size_t)r0 * 128 + col) =
                    make_float2(acc[mi][nj][0], acc[mi][nj][1]);
            if (r0 + 8 < NN)
                *reinterpret_cast<float2*>(C + (size_t)(r0 + 8) * 128 + col) =
                    make_float2(acc[mi][nj][2], acc[mi][nj][3]);
        }
    }
}

// Fused temporal gate: gpre = x@wl + h@wc; g = sigmoid(gpre + b);
// x = g*h + (1-g)*x  — all in one kernel (two accumulation passes + epilogue).
__global__ __launch_bounds__(256) void gate_gemm_tc(float* __restrict__ x,
                                                    const float* __restrict__ h,
                                                    const float* __restrict__ wl,
                                                    const float* __restrict__ wc,
                                                    const float* __restrict__ teb) {
    __shared__ unsigned As[128 * AS_STRIDE];
    __shared__ unsigned Ws[32 * WS_STRIDE];
    int tid = threadIdx.x, wid = tid >> 5, lane = tid & 31;
    int warp_m = wid & 1, warp_n = wid >> 1;
    int row0 = blockIdx.x * 128;

    float acc[4][4][4];
#pragma unroll
    for (int mi = 0; mi < 4; mi++)
#pragma unroll
        for (int nj = 0; nj < 4; nj++)
#pragma unroll
            for (int q = 0; q < 4; q++) acc[mi][nj][q] = 0.f;

    for (int pass = 0; pass < 2; pass++) {
        const float* A = pass ? h : x;
        const float* W = pass ? wc : wl;
#pragma unroll
        for (int kc = 0; kc < 4; kc++) {
            load_A_chunk(A, row0, kc, As, tid);
            load_W_chunk(W, kc, Ws, tid);
            __syncthreads();
            mma_chunk(As, Ws, acc, warp_m, warp_n, lane);
            __syncthreads();
        }
    }

    int g = lane >> 2, c = lane & 3;
#pragma unroll
    for (int mi = 0; mi < 4; mi++) {
#pragma unroll
        for (int nj = 0; nj < 4; nj++) {
            int col = warp_n * 32 + nj * 8 + c * 2;
            float b0 = teb[col], b1 = teb[col + 1];
#pragma unroll
            for (int half = 0; half < 2; half++) {
                int r = row0 + warp_m * 64 + mi * 16 + g + half * 8;
                if (r < NN) {
                    size_t o = (size_t)r * 128 + col;
                    float2 hv = *reinterpret_cast<const float2*>(h + o);
                    float2 xv = *reinterpret_cast<const float2*>(x + o);
                    float ga = 1.f / (1.f + expf(-(acc[mi][nj][half * 2 + 0] + b0)));
                    float gb = 1.f / (1.f + expf(-(acc[mi][nj][half * 2 + 1] + b1)));
                    float2 r2;
                    r2.x = ga * hv.x + (1.f - ga) * xv.x;
                    r2.y = gb * hv.y + (1.f - gb) * xv.y;
                    *reinterpret_cast<float2*>(x + o) = r2;
                }
            }
        }
    }
}

// ---------------- other kernels ----------------

__global__ void gather_kernel(const int* __restrict__ verts,
                              const float* __restrict__ emb,
                              float* __restrict__ x) {
    int idx = blockIdx.x * blockDim.x + threadIdx.x;
    if (idx >= NN * DD) return;
    int row = idx >> 7;
    int col = idx & 127;
    x[idx] = emb[(size_t)verts[row] * DD + col];
}

// C[NN,20] = A[NN,128] @ W[128,20]
__global__ __launch_bounds__(256) void gemm_out(const float* __restrict__ A,
                                                const float* __restrict__ W,
                                                float* __restrict__ C) {
    __shared__ float Ws[128 * NO];
    for (int l = threadIdx.x; l < 128 * NO; l += 256) Ws[l] = W[l];
    __syncthreads();
    int idx = blockIdx.x * 256 + threadIdx.x;
    if (idx >= NN * NO) return;
    int row = idx / NO, col = idx % NO;
    const float4* a4 = reinterpret_cast<const float4*>(A + (size_t)row * 128);
    float s = 0.f;
#pragma unroll
    for (int k = 0; k < 32; k++) {
        float4 a = a4[k];
        s += a.x * Ws[(k * 4 + 0) * NO + col];
        s += a.y * Ws[(k * 4 + 1) * NO + col];
        s += a.z * Ws[(k * 4 + 2) * NO + col];
        s += a.w * Ws[(k * 4 + 3) * NO + col];
    }
    C[idx] = s;
}

// h[dst] += w * sup[src]  — warp per edge, float4 lanes, vector RED
__global__ __launch_bounds__(256) void spmm128(const int* __restrict__ src,
                                               const int* __restrict__ dst,
                                               const float* __restrict__ w,
                                               const float* __restrict__ sup,
                                               float* __restrict__ h) {
    int gw = (blockIdx.x * blockDim.x + threadIdx.x) >> 5;
    int lane = threadIdx.x & 31;
    if (gw >= NE) return;
    int s = src[gw], d = dst[gw];
    float wt = w[gw];
    float4 v = reinterpret_cast<const float4*>(sup)[(size_t)s * 32 + lane];
    float4* outp = reinterpret_cast<float4*>(h) + (size_t)d * 32 + lane;
    asm volatile("red.global.add.v4.f32 [%0], {%1,%2,%3,%4};"
                 :: "l"(outp), "f"(wt * v.x), "f"(wt * v.y),
                    "f"(wt * v.z), "f"(wt * v.w)
                 : "memory");
}

__global__ __launch_bounds__(256) void spmm20(const int* __restrict__ src,
                                              const int* __restrict__ dst,
                                              const float* __restrict__ w,
                                              const float* __restrict__ sup,
                                              float* __restrict__ h) {
    int gw = (blockIdx.x * blockDim.x + threadIdx.x) >> 5;
    int lane = threadIdx.x & 31;
    if (gw >= NE) return;
    int s = src[gw], d = dst[gw];
    float wt = w[gw];
    if (lane < NO) {
        float v = sup[(size_t)s * NO + lane];
        atomicAdd(&h[(size_t)d * NO + lane], wt * v);
    }
}

// per-column sum & sumsq over the node axis (128 cols) — high-occupancy version
__global__ void colstats(const float* __restrict__ h, float* __restrict__ stats) {
    int col = threadIdx.x;  // 128 threads
    int rows_per = (NN + gridDim.x - 1) / gridDim.x;
    int r0 = blockIdx.x * rows_per;
    int r1 = min(r0 + rows_per, NN);
    float s = 0.f, ss = 0.f;
    for (int r = r0; r < r1; r++) {
        float v = h[(size_t)r * 128 + col];
        s += v; ss += v * v;
    }
    atomicAdd(&stats[col], s);
    atomicAdd(&stats[128 + col], ss);
}

__global__ void colstats20(const float* __restrict__ h, float* __restrict__ stats) {
    int col = threadIdx.x;
    if (col >= NO) return;
    int rows_per = (NN + gridDim.x - 1) / gridDim.x;
    int r0 = blockIdx.x * rows_per;
    int r1 = min(r0 + rows_per, NN);
    float s = 0.f, ss = 0.f;
    for (int r = r0; r < r1; r++) {
        float v = h[(size_t)r * NO + col];
        s += v; ss += v * v;
    }
    atomicAdd(&stats[col], s);
    atomicAdd(&stats[128 + col], ss);
}

__global__ void bnrelu(float* __restrict__ h, const float* __restrict__ stats,
                       const float* __restrict__ gamma, const float* __restrict__ beta) {
    int idx = blockIdx.x * blockDim.x + threadIdx.x;
    if (idx >= NN * DD) return;
    int col = idx & 127;
    float mean = stats[col] * (1.f / NN);
    float var = stats[128 + col] * (1.f / NN) - mean * mean;
    float v = (h[idx] - mean) * rsqrtf(var + BN_EPS) * gamma[col] + beta[col];
    h[idx] = fmaxf(v, 0.f);
}

__global__ void bnrelu20(float* __restrict__ h, const float* __restrict__ stats,
                         const float* __restrict__ gamma, const float* __restrict__ beta) {
    int idx = blockIdx.x * blockDim.x + threadIdx.x;
    if (idx >= NN * NO) return;
    int col = idx % NO;
    float mean = stats[col] * (1.f / NN);
    float var = stats[128 + col] * (1.f / NN) - mean * mean;
    float v = (h[idx] - mean) * rsqrtf(var + BN_EPS) * gamma[col] + beta[col];
    h[idx] = fmaxf(v, 0.f);
}

__global__ void maskreduce(const float* __restrict__ x20, const int* __restrict__ verts,
                           const float* __restrict__ mask_w, float* __restrict__ acc) {
    int gw = (blockIdx.x * blockDim.x + threadIdx.x) >> 5;
    int lane = threadIdx.x & 31;
    int nwarps = (gridDim.x * blockDim.x) >> 5;
    float a = 0.f;
    for (int r = gw; r < NN; r += nwarps) {
        float mw = mask_w[verts[r]];
        if (lane < NO) a += mw * x20[(size_t)r * NO + lane];
    }
    if (lane < NO) atomicAdd(&acc[lane], a);
}

__global__ void finalize(const float* __restrict__ acc, const float* __restrict__ mask_b,
                         float* __restrict__ out) {
    int o = threadIdx.x;
    if (o < NO) out[o] = 1.f / (1.f + expf(-(acc[o] + mask_b[o])));
}

// ---------------- launch ----------------
extern "C" void kernel_launch(void* const* d_in, const int* in_sizes, int n_in,
                              void* d_out, int out_size) {
    const int*   vertices    = (const int*)d_in[0];
    const int*   edge_index  = (const int*)d_in[1];   // [7,2,NE]
    const float* edge_weight = (const float*)d_in[2]; // [7,NE]
    const float* emb         = (const float*)d_in[3];
    const float* w_h         = (const float*)d_in[4]; // [6,128,128]
    // d_in[5] gcn_b_hidden: cancels through BN
    const float* w_out       = (const float*)d_in[6]; // [128,20]
    // d_in[7] gcn_b_out: cancels through BN
    const float* bng         = (const float*)d_in[8];
    const float* bnb         = (const float*)d_in[9];
    const float* bng_o       = (const float*)d_in[10];
    const float* bnb_o       = (const float*)d_in[11];
    const float* te_wl       = (const float*)d_in[12];
    const float* te_wc       = (const float*)d_in[13];
    const float* te_b        = (const float*)d_in[14];
    const float* mask_w      = (const float*)d_in[15];
    const float* mask_b      = (const float*)d_in[16];
    float* out = (float*)d_out;

    float *x, *sup, *h, *sup20, *h20, *stats, *acc;
    cudaGetSymbolAddress((void**)&x,     g_x);
    cudaGetSymbolAddress((void**)&sup,   g_sup);
    cudaGetSymbolAddress((void**)&h,     g_h);
    cudaGetSymbolAddress((void**)&sup20, g_sup20);
    cudaGetSymbolAddress((void**)&h20,   g_h20);
    cudaGetSymbolAddress((void**)&stats, g_stats);
    cudaGetSymbolAddress((void**)&acc,   g_acc);

    const int ND_BLOCKS = (NN * DD + 255) / 256;
    const int SPMM_BLOCKS = (NE * 32 + 255) / 256;
    const int TC_BLOCKS = (NN + 127) / 128;   // 391

    gather_kernel<<<ND_BLOCKS, 256>>>(vertices, emb, x);

    for (int i = 0; i < NLH; i++) {
        const int* src = edge_index + (size_t)i * 2 * NE;
        const int* dst = src + NE;
        const float* ew = edge_weight + (size_t)i * NE;

        gemm_tc<<<TC_BLOCKS, 256>>>(x, w_h + (size_t)i * DD * DD, sup);
        cudaMemsetAsync(h, 0, (size_t)NN * DD * sizeof(float));
        spmm128<<<SPMM_BLOCKS, 256>>>(src, dst, ew, sup, h);
        cudaMemsetAsync(stats, 0, 2 * DD * sizeof(float));
        colstats<<<1568, 128>>>(h, stats);
        bnrelu<<<ND_BLOCKS, 256>>>(h, stats, bng + i * DD, bnb + i * DD);

        int j = (i + 5) % 6;  // faithful to reference's (i-1) % (L-1)
        gate_gemm_tc<<<TC_BLOCKS, 256>>>(x, h,
                                         te_wl + (size_t)j * DD * DD,
                                         te_wc + (size_t)j * DD * DD,
                                         te_b + j * DD);
    }

    // output layer (i = 6)
    {
        const int* src = edge_index + (size_t)6 * 2 * NE;
        const int* dst = src + NE;
        const float* ew = edge_weight + (size_t)6 * NE;

        gemm_out<<<(NN * NO + 255) / 256, 256>>>(x, w_out, sup20);
        cudaMemsetAsync(h20, 0, (size_t)NN * NO * sizeof(float));
        spmm20<<<SPMM_BLOCKS, 256>>>(src, dst, ew, sup20, h20);
        cudaMemsetAsync(stats, 0, 2 * DD * sizeof(float));
        colstats20<<<784, 32>>>(h20, stats);
        bnrelu20<<<(NN * NO + 255) / 256, 256>>>(h20, stats, bng_o, bnb_o);
    }

    cudaMemsetAsync(acc, 0, 32 * sizeof(float));
    maskreduce<<<200, 256>>>(h20, vertices, mask_w, acc);
    finalize<<<1, 32>>>(acc, mask_b, out);
}

// round 4
// speedup vs baseline: 1.4916x; 1.0984x over previous
#include <cuda_runtime.h>
#include <math.h>

#define NN 50000      // nodes
#define NE 800000     // edges per layer
#define DD 128        // feature dim
#define NO 20         // output dim
#define NLH 6         // hidden (gated) layers
#define BN_EPS 1e-5f

// ---------------- scratch (static device globals; no allocation) ----------------
__device__ __align__(16) float g_x[NN * DD];
__device__ __align__(16) float g_sup[NN * DD];
__device__ __align__(16) float g_h[NN * DD];
__device__ __align__(16) float g_gl[NN * DD];
__device__ __align__(16) float g_sup20[NN * NO];
__device__ __align__(16) float g_h20[NN * NO];
__device__ __align__(16) float g_part[256 * 256];
__device__ float g_stats[2 * DD];
__device__ float g_acc[32];

// ---------------- tf32 helpers ----------------
__device__ __forceinline__ unsigned f2tf(float f) {
    unsigned u;
    asm("cvt.rna.tf32.f32 %0, %1;" : "=r"(u) : "f"(f));
    return u;
}

#define AS_STRIDE 36    // 128 rows x 32 cols A tile, padded (conflict-free)
#define WS_STRIDE 136   // 32 rows x 128 cols W tile, padded (conflict-free)
#define STAGE_U32 (128 * AS_STRIDE + 32 * WS_STRIDE)   // 8960 u32 per stage
#define GEMM_DYN_SMEM (2 * STAGE_U32 * 4)              // 71680 bytes

// prefetch one BK=32 chunk (A rows + W rows) into registers
__device__ __forceinline__ void ldg_chunk(const float* __restrict__ A,
                                          const float* __restrict__ W,
                                          int row0, int kc, int tid,
                                          float4 va[4], float4 vw[4]) {
#pragma unroll
    for (int t = 0; t < 4; t++) {
        int e = tid + 256 * t;
        int r = e >> 3, q = e & 7;
        int gr = row0 + r;
        va[t] = (gr < NN)
            ? __ldg(&reinterpret_cast<const float4*>(A)[(size_t)gr * 32 + kc * 8 + q])
            : make_float4(0.f, 0.f, 0.f, 0.f);
        int k = e >> 5, q2 = e & 31;
        vw[t] = __ldg(&reinterpret_cast<const float4*>(W)[(size_t)(kc * 32 + k) * 32 + q2]);
    }
}

// cvt + store a prefetched chunk; optionally BN+ReLU-normalize A values
__device__ __forceinline__ void sts_chunk(const float4 va[4], const float4 vw[4],
                                          unsigned* As, unsigned* Ws, int tid, int kc,
                                          const float* scale, const float* shift) {
#pragma unroll
    for (int t = 0; t < 4; t++) {
        int e = tid + 256 * t;
        int r = e >> 3, q = e & 7;
        float4 v = va[t];
        if (scale) {
            int c = kc * 32 + q * 4;
            v.x = fmaxf(fmaf(v.x, scale[c + 0], shift[c + 0]), 0.f);
            v.y = fmaxf(fmaf(v.y, scale[c + 1], shift[c + 1]), 0.f);
            v.z = fmaxf(fmaf(v.z, scale[c + 2], shift[c + 2]), 0.f);
            v.w = fmaxf(fmaf(v.w, scale[c + 3], shift[c + 3]), 0.f);
        }
        unsigned* p = As + r * AS_STRIDE + q * 4;
        p[0] = f2tf(v.x); p[1] = f2tf(v.y); p[2] = f2tf(v.z); p[3] = f2tf(v.w);
        int k = e >> 5, q2 = e & 31;
        float4 w = vw[t];
        unsigned* pw = Ws + k * WS_STRIDE + q2 * 4;
        pw[0] = f2tf(w.x); pw[1] = f2tf(w.y); pw[2] = f2tf(w.z); pw[3] = f2tf(w.w);
    }
}

// One BK=32 chunk of mma.m16n8k8 tf32. Warp tile 64x32 (4 m-frags x 4 n-frags).
__device__ __forceinline__ void mma_chunk(const unsigned* As, const unsigned* Ws,
                                          float acc[4][4][4],
                                          int warp_m, int warp_n, int lane) {
    int g = lane >> 2, c = lane & 3;
#pragma unroll
    for (int kk = 0; kk < 4; kk++) {
        unsigned a[4][4];
#pragma unroll
        for (int mi = 0; mi < 4; mi++) {
            const unsigned* base = As + (warp_m * 64 + mi * 16 + g) * AS_STRIDE + kk * 8 + c;
            a[mi][0] = base[0];
            a[mi][1] = base[8 * AS_STRIDE];
            a[mi][2] = base[4];
            a[mi][3] = base[8 * AS_STRIDE + 4];
        }
        unsigned b[4][2];
#pragma unroll
        for (int nj = 0; nj < 4; nj++) {
            const unsigned* base = Ws + (kk * 8 + c) * WS_STRIDE + warp_n * 32 + nj * 8 + g;
            b[nj][0] = base[0];
            b[nj][1] = base[4 * WS_STRIDE];
        }
#pragma unroll
        for (int mi = 0; mi < 4; mi++)
#pragma unroll
            for (int nj = 0; nj < 4; nj++) {
                asm volatile(
                    "mma.sync.aligned.m16n8k8.row.col.f32.tf32.tf32.f32 "
                    "{%0,%1,%2,%3}, {%4,%5,%6,%7}, {%8,%9}, {%0,%1,%2,%3};\n"
                    : "+f"(acc[mi][nj][0]), "+f"(acc[mi][nj][1]),
                      "+f"(acc[mi][nj][2]), "+f"(acc[mi][nj][3])
                    : "r"(a[mi][0]), "r"(a[mi][1]), "r"(a[mi][2]), "r"(a[mi][3]),
                      "r"(b[nj][0]), "r"(b[nj][1]));
            }
    }
}

// double-buffered 128x128xK128 main loop; acc in caller, norm optional
__device__ __forceinline__ void gemm_main(const float* __restrict__ A,
                                          const float* __restrict__ W,
                                          int row0, int tid, int warp_m, int warp_n,
                                          int lane, float acc[4][4][4],
                                          unsigned* dyn,
                                          const float* scale, const float* shift) {
    unsigned* As[2] = {dyn, dyn + STAGE_U32};
    unsigned* Ws[2] = {dyn + 128 * AS_STRIDE, dyn + STAGE_U32 + 128 * AS_STRIDE};
    float4 va[4], vw[4];
    ldg_chunk(A, W, row0, 0, tid, va, vw);
    sts_chunk(va, vw, As[0], Ws[0], tid, 0, scale, shift);
    __syncthreads();
#pragma unroll
    for (int kc = 0; kc < 4; kc++) {
        if (kc < 3) ldg_chunk(A, W, row0, kc + 1, tid, va, vw);
        mma_chunk(As[kc & 1], Ws[kc & 1], acc, warp_m, warp_n, lane);
        if (kc < 3) {
            sts_chunk(va, vw, As[(kc + 1) & 1], Ws[(kc + 1) & 1], tid, kc + 1, scale, shift);
            __syncthreads();
        }
    }
}

// C[NN,128] = A[NN,128] @ W[128,128]   (tensor-core tf32, double-buffered)
__global__ __launch_bounds__(256) void gemm_tc(const float* __restrict__ A,
                                               const float* __restrict__ W,
                                               float* __restrict__ C) {
    extern __shared__ unsigned dyn[];
    int tid = threadIdx.x, wid = tid >> 5, lane = tid & 31;
    int warp_m = wid & 1, warp_n = wid >> 1;
    int row0 = blockIdx.x * 128;

    float acc[4][4][4];
#pragma unroll
    for (int mi = 0; mi < 4; mi++)
#pragma unroll
        for (int nj = 0; nj < 4; nj++)
#pragma unroll
            for (int q = 0; q < 4; q++) acc[mi][nj][q] = 0.f;

    gemm_main(A, W, row0, tid, warp_m, warp_n, lane, acc, dyn, nullptr, nullptr);

    int g = lane >> 2, c = lane & 3;
#pragma unroll
    for (int mi = 0; mi < 4; mi++) {
        int r0 = row0 + warp_m * 64 + mi * 16 + g;
#pragma unroll
        for (int nj = 0; nj < 4; nj++) {
            int col = warp_n * 32 + nj * 8 + c * 2;
            if (r0 < NN)
                *reinterpret_cast<float2*>(C + (size_t)r0 * 128 + col) =
                    make_float2(acc[mi][nj][0], acc[mi][nj][1]);
            if (r0 + 8 < NN)
                *reinterpret_cast<float2*>(C + (size_t)(r0 + 8) * 128 + col) =
                    make_float2(acc[mi][nj][2], acc[mi][nj][3]);
        }
    }
}

// Fused: hn = relu(BN(h)); acc = hn @ wc; g = sigmoid(acc + gl + teb);
// x = g*hn + (1-g)*x.   BN scale/shift derived from raw column stats.
__global__ __launch_bounds__(256) void gate_gemm2(float* __restrict__ x,
                                                  const float* __restrict__ h,
                                                  const float* __restrict__ wc,
                                                  const float* __restrict__ gl,
                                                  const float* __restrict__ teb,
                                                  const float* __restrict__ stats,
                                                  const float* __restrict__ gamma,
                                                  const float* __restrict__ beta) {
    extern __shared__ unsigned dyn[];
    __shared__ float s_scale[128], s_shift[128];
    int tid = threadIdx.x, wid = tid >> 5, lane = tid & 31;
    int warp_m = wid & 1, warp_n = wid >> 1;
    int row0 = blockIdx.x * 128;

    if (tid < 128) {
        float m = stats[tid] * (1.f / NN);
        float var = stats[128 + tid] * (1.f / NN) - m * m;
        float sc = rsqrtf(var + BN_EPS) * gamma[tid];
        s_scale[tid] = sc;
        s_shift[tid] = beta[tid] - m * sc;
    }
    __syncthreads();

    float acc[4][4][4];
#pragma unroll
    for (int mi = 0; mi < 4; mi++)
#pragma unroll
        for (int nj = 0; nj < 4; nj++)
#pragma unroll
            for (int q = 0; q < 4; q++) acc[mi][nj][q] = 0.f;

    gemm_main(h, wc, row0, tid, warp_m, warp_n, lane, acc, dyn, s_scale, s_shift);

    int g = lane >> 2, c = lane & 3;
#pragma unroll
    for (int mi = 0; mi < 4; mi++) {
#pragma unroll
        for (int nj = 0; nj < 4; nj++) {
            int col = warp_n * 32 + nj * 8 + c * 2;
            float b0 = teb[col], b1 = teb[col + 1];
            float sc0 = s_scale[col], sc1 = s_scale[col + 1];
            float sh0 = s_shift[col], sh1 = s_shift[col + 1];
#pragma unroll
            for (int half = 0; half < 2; half++) {
                int r = row0 + warp_m * 64 + mi * 16 + g + half * 8;
                if (r < NN) {
                    size_t o = (size_t)r * 128 + col;
                    float2 hv = *reinterpret_cast<const float2*>(h + o);
                    float2 xv = *reinterpret_cast<const float2*>(x + o);
                    float2 gv = *reinterpret_cast<const float2*>(gl + o);
                    float hn0 = fmaxf(fmaf(hv.x, sc0, sh0), 0.f);
                    float hn1 = fmaxf(fmaf(hv.y, sc1, sh1), 0.f);
                    float ga = 1.f / (1.f + expf(-(acc[mi][nj][half * 2 + 0] + gv.x + b0)));
                    float gb = 1.f / (1.f + expf(-(acc[mi][nj][half * 2 + 1] + gv.y + b1)));
                    float2 r2;
                    r2.x = ga * hn0 + (1.f - ga) * xv.x;
                    r2.y = gb * hn1 + (1.f - gb) * xv.y;
                    *reinterpret_cast<float2*>(x + o) = r2;
                }
            }
        }
    }
}

// ---------------- other kernels ----------------

__global__ void gather_kernel(const int* __restrict__ verts,
                              const float* __restrict__ emb,
                              float* __restrict__ x) {
    int idx = blockIdx.x * blockDim.x + threadIdx.x;   // NN*32 float4s
    if (idx >= NN * 32) return;
    int row = idx >> 5, q = idx & 31;
    reinterpret_cast<float4*>(x)[idx] =
        reinterpret_cast<const float4*>(emb)[(size_t)verts[row] * 32 + q];
}

// C[NN,20] = A[NN,128] @ W[128,20]
__global__ __launch_bounds__(256) void gemm_out(const float* __restrict__ A,
                                                const float* __restrict__ W,
                                                float* __restrict__ C) {
    __shared__ float Ws[128 * NO];
    for (int l = threadIdx.x; l < 128 * NO; l += 256) Ws[l] = W[l];
    __syncthreads();
    int idx = blockIdx.x * 256 + threadIdx.x;
    if (idx >= NN * NO) return;
    int row = idx / NO, col = idx % NO;
    const float4* a4 = reinterpret_cast<const float4*>(A + (size_t)row * 128);
    float s = 0.f;
#pragma unroll
    for (int k = 0; k < 32; k++) {
        float4 a = a4[k];
        s += a.x * Ws[(k * 4 + 0) * NO + col];
        s += a.y * Ws[(k * 4 + 1) * NO + col];
        s += a.z * Ws[(k * 4 + 2) * NO + col];
        s += a.w * Ws[(k * 4 + 3) * NO + col];
    }
    C[idx] = s;
}

// h[dst] += w * sup[src]  — warp per edge, float4 lanes, vector RED
__global__ __launch_bounds__(256) void spmm128(const int* __restrict__ src,
                                               const int* __restrict__ dst,
                                               const float* __restrict__ w,
                                               const float* __restrict__ sup,
                                               float* __restrict__ h) {
    int gw = (blockIdx.x * blockDim.x + threadIdx.x) >> 5;
    int lane = threadIdx.x & 31;
    if (gw >= NE) return;
    int s = src[gw], d = dst[gw];
    float wt = w[gw];
    float4 v = reinterpret_cast<const float4*>(sup)[(size_t)s * 32 + lane];
    float4* outp = reinterpret_cast<float4*>(h) + (size_t)d * 32 + lane;
    asm volatile("red.global.add.v4.f32 [%0], {%1,%2,%3,%4};"
                 :: "l"(outp), "f"(wt * v.x), "f"(wt * v.y),
                    "f"(wt * v.z), "f"(wt * v.w)
                 : "memory");
}

__global__ __launch_bounds__(256) void spmm20(const int* __restrict__ src,
                                              const int* __restrict__ dst,
                                              const float* __restrict__ w,
                                              const float* __restrict__ sup,
                                              float* __restrict__ h) {
    int gw = (blockIdx.x * blockDim.x + threadIdx.x) >> 5;
    int lane = threadIdx.x & 31;
    if (gw >= NE) return;
    int s = src[gw], d = dst[gw];
    float wt = w[gw];
    if (lane < NO) {
        float v = sup[(size_t)s * NO + lane];
        atomicAdd(&h[(size_t)d * NO + lane], wt * v);
    }
}

// column sums/sumsq: partial per block (float4, no atomics)
__global__ __launch_bounds__(256) void colstats_part(const float* __restrict__ h,
                                                     float* __restrict__ part) {
    int lane = threadIdx.x & 31, w = threadIdx.x >> 5;
    int gw = blockIdx.x * 8 + w;   // 2048 warps total
    const float4* h4 = reinterpret_cast<const float4*>(h);
    float4 s = make_float4(0.f, 0.f, 0.f, 0.f);
    float4 ss = make_float4(0.f, 0.f, 0.f, 0.f);
#pragma unroll 4
    for (int r = gw; r < NN; r += 2048) {
        float4 v = h4[(size_t)r * 32 + lane];
        s.x += v.x; s.y += v.y; s.z += v.z; s.w += v.w;
        ss.x += v.x * v.x; ss.y += v.y * v.y; ss.z += v.z * v.z; ss.w += v.w * v.w;
    }
    __shared__ float sm[8][256];
    float* p = &sm[w][lane * 8];
    p[0] = s.x; p[1] = s.y; p[2] = s.z; p[3] = s.w;
    p[4] = ss.x; p[5] = ss.y; p[6] = ss.z; p[7] = ss.w;
    __syncthreads();
    int t = threadIdx.x;
    float a = sm[0][t] + sm[1][t] + sm[2][t] + sm[3][t]
            + sm[4][t] + sm[5][t] + sm[6][t] + sm[7][t];
    part[blockIdx.x * 256 + t] = a;
}

__global__ void colstats_reduce(const float* __restrict__ part,
                                float* __restrict__ stats) {
    int t = threadIdx.x;  // 256
    float a = 0.f;
#pragma unroll 16
    for (int b = 0; b < 256; b++) a += part[b * 256 + t];
    int lane = t >> 3, k = t & 7;
    int col = lane * 4 + (k & 3);
    int st = k >> 2;
    stats[st * 128 + col] = a;
}

__global__ void colstats20(const float* __restrict__ h, float* __restrict__ stats) {
    int col = threadIdx.x;
    if (col >= NO) return;
    int rows_per = (NN + gridDim.x - 1) / gridDim.x;
    int r0 = blockIdx.x * rows_per;
    int r1 = min(r0 + rows_per, NN);
    float s = 0.f, ss = 0.f;
    for (int r = r0; r < r1; r++) {
        float v = h[(size_t)r * NO + col];
        s += v; ss += v * v;
    }
    atomicAdd(&stats[col], s);
    atomicAdd(&stats[128 + col], ss);
}

__global__ void bnrelu20(float* __restrict__ h, const float* __restrict__ stats,
                         const float* __restrict__ gamma, const float* __restrict__ beta) {
    int idx = blockIdx.x * blockDim.x + threadIdx.x;
    if (idx >= NN * NO) return;
    int col = idx % NO;
    float mean = stats[col] * (1.f / NN);
    float var = stats[128 + col] * (1.f / NN) - mean * mean;
    float v = (h[idx] - mean) * rsqrtf(var + BN_EPS) * gamma[col] + beta[col];
    h[idx] = fmaxf(v, 0.f);
}

__global__ void maskreduce(const float* __restrict__ x20, const int* __restrict__ verts,
                           const float* __restrict__ mask_w, float* __restrict__ acc) {
    int gw = (blockIdx.x * blockDim.x + threadIdx.x) >> 5;
    int lane = threadIdx.x & 31;
    int nwarps = (gridDim.x * blockDim.x) >> 5;
    float a = 0.f;
    for (int r = gw; r < NN; r += nwarps) {
        float mw = mask_w[verts[r]];
        if (lane < NO) a += mw * x20[(size_t)r * NO + lane];
    }
    if (lane < NO) atomicAdd(&acc[lane], a);
}

__global__ void finalize(const float* __restrict__ acc, const float* __restrict__ mask_b,
                         float* __restrict__ out) {
    int o = threadIdx.x;
    if (o < NO) out[o] = 1.f / (1.f + expf(-(acc[o] + mask_b[o])));
}

// ---------------- one-time host resources (created at load, before harness baseline) ----
struct HostRes {
    cudaStream_t s1;
    cudaEvent_t evX, evM, evGL;
    HostRes() {
        cudaStreamCreateWithFlags(&s1, cudaStreamNonBlocking);
        cudaEventCreateWithFlags(&evX, cudaEventDisableTiming);
        cudaEventCreateWithFlags(&evM, cudaEventDisableTiming);
        cudaEventCreateWithFlags(&evGL, cudaEventDisableTiming);
        cudaFuncSetAttribute(gemm_tc, cudaFuncAttributeMaxDynamicSharedMemorySize, GEMM_DYN_SMEM);
        cudaFuncSetAttribute(gate_gemm2, cudaFuncAttributeMaxDynamicSharedMemorySize, GEMM_DYN_SMEM);
    }
};
static HostRes g_res;

// ---------------- launch ----------------
extern "C" void kernel_launch(void* const* d_in, const int* in_sizes, int n_in,
                              void* d_out, int out_size) {
    const int*   vertices    = (const int*)d_in[0];
    const int*   edge_index  = (const int*)d_in[1];   // [7,2,NE]
    const float* edge_weight = (const float*)d_in[2]; // [7,NE]
    const float* emb         = (const float*)d_in[3];
    const float* w_h         = (const float*)d_in[4]; // [6,128,128]
    // d_in[5] gcn_b_hidden: cancels through BN
    const float* w_out       = (const float*)d_in[6]; // [128,20]
    // d_in[7] gcn_b_out: cancels through BN
    const float* bng         = (const float*)d_in[8];
    const float* bnb         = (const float*)d_in[9];
    const float* bng_o       = (const float*)d_in[10];
    const float* bnb_o       = (const float*)d_in[11];
    const float* te_wl       = (const float*)d_in[12];
    const float* te_wc       = (const float*)d_in[13];
    const float* te_b        = (const float*)d_in[14];
    const float* mask_w      = (const float*)d_in[15];
    const float* mask_b      = (const float*)d_in[16];
    float* out = (float*)d_out;

    float *x, *sup, *h, *gl, *sup20, *h20, *part, *stats, *acc;
    cudaGetSymbolAddress((void**)&x,     g_x);
    cudaGetSymbolAddress((void**)&sup,   g_sup);
    cudaGetSymbolAddress((void**)&h,     g_h);
    cudaGetSymbolAddress((void**)&gl,    g_gl);
    cudaGetSymbolAddress((void**)&sup20, g_sup20);
    cudaGetSymbolAddress((void**)&h20,   g_h20);
    cudaGetSymbolAddress((void**)&part,  g_part);
    cudaGetSymbolAddress((void**)&stats, g_stats);
    cudaGetSymbolAddress((void**)&acc,   g_acc);

    cudaStream_t s1 = g_res.s1;
    const int SPMM_BLOCKS = (NE * 32 + 255) / 256;
    const int TC_BLOCKS = (NN + 127) / 128;   // 391

    gather_kernel<<<(NN * 32 + 255) / 256, 256>>>(vertices, emb, x);
    cudaEventRecord(g_res.evX, 0);

    for (int i = 0; i < NLH; i++) {
        const int* src = edge_index + (size_t)i * 2 * NE;
        const int* dst = src + NE;
        const float* ew = edge_weight + (size_t)i * NE;
        int j = (i + 5) % 6;  // faithful to reference's (i-1) % (L-1)

        // side stream: memset h + gate-partial gemm (x @ te_wl)
        cudaStreamWaitEvent(s1, g_res.evX, 0);
        cudaMemsetAsync(h, 0, (size_t)NN * DD * sizeof(float), s1);
        cudaEventRecord(g_res.evM, s1);
        gemm_tc<<<TC_BLOCKS, 256, GEMM_DYN_SMEM, s1>>>(x, te_wl + (size_t)j * DD * DD, gl);
        cudaEventRecord(g_res.evGL, s1);

        // main stream: sup gemm -> spmm -> stats -> fused BN+gate gemm
        gemm_tc<<<TC_BLOCKS, 256, GEMM_DYN_SMEM>>>(x, w_h + (size_t)i * DD * DD, sup);
        cudaStreamWaitEvent(0, g_res.evM, 0);
        spmm128<<<SPMM_BLOCKS, 256>>>(src, dst, ew, sup, h);
        colstats_part<<<256, 256>>>(h, part);
        colstats_reduce<<<1, 256>>>(part, stats);
        cudaStreamWaitEvent(0, g_res.evGL, 0);
        gate_gemm2<<<TC_BLOCKS, 256, GEMM_DYN_SMEM>>>(x, h,
                                                      te_wc + (size_t)j * DD * DD,
                                                      gl, te_b + j * DD,
                                                      stats, bng + i * DD, bnb + i * DD);
        cudaEventRecord(g_res.evX, 0);
    }

    // output layer (i = 6) — all on main stream
    {
        const int* src = edge_index + (size_t)6 * 2 * NE;
        const int* dst = src + NE;
        const float* ew = edge_weight + (size_t)6 * NE;

        gemm_out<<<(NN * NO + 255) / 256, 256>>>(x, w_out, sup20);
        cudaMemsetAsync(h20, 0, (size_t)NN * NO * sizeof(float));
        spmm20<<<SPMM_BLOCKS, 256>>>(src, dst, ew, sup20, h20);
        cudaMemsetAsync(stats, 0, 2 * DD * sizeof(float));
        colstats20<<<784, 32>>>(h20, stats);
        bnrelu20<<<(NN * NO + 255) / 256, 256>>>(h20, stats, bng_o, bnb_o);
    }

    cudaMemsetAsync(acc, 0, 32 * sizeof(float));
    maskreduce<<<200, 256>>>(h20, vertices, mask_w, acc);
    finalize<<<1, 32>>>(acc, mask_b, out);
}

// round 7
// speedup vs baseline: 1.5892x; 1.0654x over previous
#include <cuda_runtime.h>
#include <math.h>

#define NN 50000      // nodes
#define NE 800000     // edges per layer
#define DD 128        // feature dim
#define NO 20         // output dim
#define NLH 6         // hidden (gated) layers
#define BN_EPS 1e-5f

// ---------------- scratch (static device globals; no allocation) ----------------
__device__ __align__(16) float g_x[NN * DD];
__device__ __align__(16) float g_sup[NN * DD];
__device__ __align__(16) float g_h[NN * DD];
__device__ __align__(16) float g_gl[NN * DD];
__device__ __align__(16) float g_sup20[NN * NO];
__device__ __align__(16) float g_h20[NN * NO];
__device__ float g_stats[2 * DD];
__device__ float g_acc[32];
// CSR double-buffer (sorted edges, packed {w:int(src)} 8B)
__device__ __align__(16) long long g_esw[2][NE];
__device__ int g_rowptr[2][NN + 1];
__device__ int g_cnt[NN];
__device__ int g_woff[NN];

// ---------------- tf32 helpers ----------------
__device__ __forceinline__ unsigned f2tf(float f) {
    unsigned u;
    asm("cvt.rna.tf32.f32 %0, %1;" : "=r"(u) : "f"(f));
    return u;
}

#define AS_STRIDE 36    // 128 rows x 32 cols A tile, padded (conflict-free)
#define WS_STRIDE 136   // 32 rows x 128 cols W tile, padded (conflict-free)
#define STAGE_U32 (128 * AS_STRIDE + 32 * WS_STRIDE)   // 8960 u32 per stage
#define GEMM_DYN_SMEM (2 * STAGE_U32 * 4)              // 71680 bytes

__device__ __forceinline__ void ldg_chunk(const float* __restrict__ A,
                                          const float* __restrict__ W,
                                          int row0, int kc, int tid,
                                          float4 va[4], float4 vw[4]) {
#pragma unroll
    for (int t = 0; t < 4; t++) {
        int e = tid + 256 * t;
        int r = e >> 3, q = e & 7;
        int gr = row0 + r;
        va[t] = (gr < NN)
            ? __ldg(&reinterpret_cast<const float4*>(A)[(size_t)gr * 32 + kc * 8 + q])
            : make_float4(0.f, 0.f, 0.f, 0.f);
        int k = e >> 5, q2 = e & 31;
        vw[t] = __ldg(&reinterpret_cast<const float4*>(W)[(size_t)(kc * 32 + k) * 32 + q2]);
    }
}

__device__ __forceinline__ void sts_chunk(const float4 va[4], const float4 vw[4],
                                          unsigned* As, unsigned* Ws, int tid, int kc,
                                          const float* scale, const float* shift) {
#pragma unroll
    for (int t = 0; t < 4; t++) {
        int e = tid + 256 * t;
        int r = e >> 3, q = e & 7;
        float4 v = va[t];
        if (scale) {
            int c = kc * 32 + q * 4;
            v.x = fmaxf(fmaf(v.x, scale[c + 0], shift[c + 0]), 0.f);
            v.y = fmaxf(fmaf(v.y, scale[c + 1], shift[c + 1]), 0.f);
            v.z = fmaxf(fmaf(v.z, scale[c + 2], shift[c + 2]), 0.f);
            v.w = fmaxf(fmaf(v.w, scale[c + 3], shift[c + 3]), 0.f);
        }
        unsigned* p = As + r * AS_STRIDE + q * 4;
        p[0] = f2tf(v.x); p[1] = f2tf(v.y); p[2] = f2tf(v.z); p[3] = f2tf(v.w);
        int k = e >> 5, q2 = e & 31;
        float4 w = vw[t];
        unsigned* pw = Ws + k * WS_STRIDE + q2 * 4;
        pw[0] = f2tf(w.x); pw[1] = f2tf(w.y); pw[2] = f2tf(w.z); pw[3] = f2tf(w.w);
    }
}

__device__ __forceinline__ void mma_chunk(const unsigned* As, const unsigned* Ws,
                                          float acc[4][4][4],
                                          int warp_m, int warp_n, int lane) {
    int g = lane >> 2, c = lane & 3;
#pragma unroll
    for (int kk = 0; kk < 4; kk++) {
        unsigned a[4][4];
#pragma unroll
        for (int mi = 0; mi < 4; mi++) {
            const unsigned* base = As + (warp_m * 64 + mi * 16 + g) * AS_STRIDE + kk * 8 + c;
            a[mi][0] = base[0];
            a[mi][1] = base[8 * AS_STRIDE];
            a[mi][2] = base[4];
            a[mi][3] = base[8 * AS_STRIDE + 4];
        }
        unsigned b[4][2];
#pragma unroll
        for (int nj = 0; nj < 4; nj++) {
            const unsigned* base = Ws + (kk * 8 + c) * WS_STRIDE + warp_n * 32 + nj * 8 + g;
            b[nj][0] = base[0];
            b[nj][1] = base[4 * WS_STRIDE];
        }
#pragma unroll
        for (int mi = 0; mi < 4; mi++)
#pragma unroll
            for (int nj = 0; nj < 4; nj++) {
                asm volatile(
                    "mma.sync.aligned.m16n8k8.row.col.f32.tf32.tf32.f32 "
                    "{%0,%1,%2,%3}, {%4,%5,%6,%7}, {%8,%9}, {%0,%1,%2,%3};\n"
                    : "+f"(acc[mi][nj][0]), "+f"(acc[mi][nj][1]),
                      "+f"(acc[mi][nj][2]), "+f"(acc[mi][nj][3])
                    : "r"(a[mi][0]), "r"(a[mi][1]), "r"(a[mi][2]), "r"(a[mi][3]),
                      "r"(b[nj][0]), "r"(b[nj][1]));
            }
    }
}

__device__ __forceinline__ void gemm_main(const float* __restrict__ A,
                                          const float* __restrict__ W,
                                          int row0, int tid, int warp_m, int warp_n,
                                          int lane, float acc[4][4][4],
                                          unsigned* dyn,
                                          const float* scale, const float* shift) {
    unsigned* As[2] = {dyn, dyn + STAGE_U32};
    unsigned* Ws[2] = {dyn + 128 * AS_STRIDE, dyn + STAGE_U32 + 128 * AS_STRIDE};
    float4 va[4], vw[4];
    ldg_chunk(A, W, row0, 0, tid, va, vw);
    sts_chunk(va, vw, As[0], Ws[0], tid, 0, scale, shift);
    __syncthreads();
#pragma unroll
    for (int kc = 0; kc < 4; kc++) {
        if (kc < 3) ldg_chunk(A, W, row0, kc + 1, tid, va, vw);
        mma_chunk(As[kc & 1], Ws[kc & 1], acc, warp_m, warp_n, lane);
        if (kc < 3) {
            sts_chunk(va, vw, As[(kc + 1) & 1], Ws[(kc + 1) & 1], tid, kc + 1, scale, shift);
            __syncthreads();
        }
    }
}

// C[NN,128] = A[NN,128] @ W[128,128]
__global__ __launch_bounds__(256) void gemm_tc(const float* __restrict__ A,
                                               const float* __restrict__ W,
                                               float* __restrict__ C) {
    extern __shared__ unsigned dyn[];
    int tid = threadIdx.x, wid = tid >> 5, lane = tid & 31;
    int warp_m = wid & 1, warp_n = wid >> 1;
    int row0 = blockIdx.x * 128;

    float acc[4][4][4];
#pragma unroll
    for (int mi = 0; mi < 4; mi++)
#pragma unroll
        for (int nj = 0; nj < 4; nj++)
#pragma unroll
            for (int q = 0; q < 4; q++) acc[mi][nj][q] = 0.f;

    gemm_main(A, W, row0, tid, warp_m, warp_n, lane, acc, dyn, nullptr, nullptr);

    int g = lane >> 2, c = lane & 3;
#pragma unroll
    for (int mi = 0; mi < 4; mi++) {
        int r0 = row0 + warp_m * 64 + mi * 16 + g;
#pragma unroll
        for (int nj = 0; nj < 4; nj++) {
            int col = warp_n * 32 + nj * 8 + c * 2;
            if (r0 < NN)
                *reinterpret_cast<float2*>(C + (size_t)r0 * 128 + col) =
                    make_float2(acc[mi][nj][0], acc[mi][nj][1]);
            if (r0 + 8 < NN)
                *reinterpret_cast<float2*>(C + (size_t)(r0 + 8) * 128 + col) =
                    make_float2(acc[mi][nj][2], acc[mi][nj][3]);
        }
    }
}

// Fused: hn = relu(BN(h)); acc = hn @ wc; g = sigmoid(acc + gl + teb); x = g*hn + (1-g)*x
__global__ __launch_bounds__(256) void gate_gemm2(float* __restrict__ x,
                                                  const float* __restrict__ h,
                                                  const float* __restrict__ wc,
                                                  const float* __restrict__ gl,
                                                  const float* __restrict__ teb,
                                                  const float* __restrict__ stats,
                                                  const float* __restrict__ gamma,
                                                  const float* __restrict__ beta) {
    extern __shared__ unsigned dyn[];
    __shared__ float s_scale[128], s_shift[128];
    int tid = threadIdx.x, wid = tid >> 5, lane = tid & 31;
    int warp_m = wid & 1, warp_n = wid >> 1;
    int row0 = blockIdx.x * 128;

    if (tid < 128) {
        float m = stats[tid] * (1.f / NN);
        float var = stats[128 + tid] * (1.f / NN) - m * m;
        float sc = rsqrtf(var + BN_EPS) * gamma[tid];
        s_scale[tid] = sc;
        s_shift[tid] = beta[tid] - m * sc;
    }
    __syncthreads();

    float acc[4][4][4];
#pragma unroll
    for (int mi = 0; mi < 4; mi++)
#pragma unroll
        for (int nj = 0; nj < 4; nj++)
#pragma unroll
            for (int q = 0; q < 4; q++) acc[mi][nj][q] = 0.f;

    gemm_main(h, wc, row0, tid, warp_m, warp_n, lane, acc, dyn, s_scale, s_shift);

    int g = lane >> 2, c = lane & 3;
#pragma unroll
    for (int mi = 0; mi < 4; mi++) {
#pragma unroll
        for (int nj = 0; nj < 4; nj++) {
            int col = warp_n * 32 + nj * 8 + c * 2;
            float b0 = teb[col], b1 = teb[col + 1];
            float sc0 = s_scale[col], sc1 = s_scale[col + 1];
            float sh0 = s_shift[col], sh1 = s_shift[col + 1];
#pragma unroll
            for (int half = 0; half < 2; half++) {
                int r = row0 + warp_m * 64 + mi * 16 + g + half * 8;
                if (r < NN) {
                    size_t o = (size_t)r * 128 + col;
                    float2 hv = *reinterpret_cast<const float2*>(h + o);
                    float2 xv = *reinterpret_cast<const float2*>(x + o);
                    float2 gv = *reinterpret_cast<const float2*>(gl + o);
                    float hn0 = fmaxf(fmaf(hv.x, sc0, sh0), 0.f);
                    float hn1 = fmaxf(fmaf(hv.y, sc1, sh1), 0.f);
                    float ga = 1.f / (1.f + expf(-(acc[mi][nj][half * 2 + 0] + gv.x + b0)));
                    float gb = 1.f / (1.f + expf(-(acc[mi][nj][half * 2 + 1] + gv.y + b1)));
                    float2 r2;
                    r2.x = ga * hn0 + (1.f - ga) * xv.x;
                    r2.y = gb * hn1 + (1.f - gb) * xv.y;
                    *reinterpret_cast<float2*>(x + o) = r2;
                }
            }
        }
    }
}

// ---------------- CSR build ----------------

__global__ void hist_kernel(const int* __restrict__ dst, int* __restrict__ cnt) {
    int e = blockIdx.x * 256 + threadIdx.x;
    if (e < NE) atomicAdd(&cnt[dst[e]], 1);
}

__global__ void exscan_kernel(const int* __restrict__ cnt, int* __restrict__ rowptr,
                              int* __restrict__ woff) {
    __shared__ int sm[1024];
    int t = threadIdx.x;
    const int CH = (NN + 1023) / 1024;   // 49
    int base = t * CH;
    int s = 0;
    for (int k = 0; k < CH; k++) {
        int idx = base + k;
        if (idx < NN) s += cnt[idx];
    }
    sm[t] = s;
    __syncthreads();
    for (int off = 1; off < 1024; off <<= 1) {
        int v = (t >= off) ? sm[t - off] : 0;
        __syncthreads();
        sm[t] += v;
        __syncthreads();
    }
    int run = (t == 0) ? 0 : sm[t - 1];
    for (int k = 0; k < CH; k++) {
        int idx = base + k;
        if (idx < NN) {
            rowptr[idx] = run;
            woff[idx] = run;
            run += cnt[idx];
        }
    }
    if (t == 1023) rowptr[NN] = sm[1023];
}

__global__ void scatter_kernel(const int* __restrict__ src, const int* __restrict__ dst,
                               const float* __restrict__ w, int* __restrict__ woff,
                               long long* __restrict__ esw) {
    int e = blockIdx.x * 256 + threadIdx.x;
    if (e >= NE) return;
    int d = dst[e];
    int pos = atomicAdd(&woff[d], 1);
    unsigned long long pk =
        ((unsigned long long)__float_as_uint(w[e]) << 32) | (unsigned)src[e];
    esw[pos] = (long long)pk;
}

// CSR spmm: warp per dst row, register accumulate, fused column stats
__global__ __launch_bounds__(256) void spmm_csr(const long long* __restrict__ esw,
                                                const int* __restrict__ rowptr,
                                                const float* __restrict__ sup,
                                                float* __restrict__ h,
                                                float* __restrict__ stats) {
    int w = threadIdx.x >> 5, lane = threadIdx.x & 31;
    int row = blockIdx.x * 8 + w;
    const float4* sup4 = reinterpret_cast<const float4*>(sup);
    float4 acc = make_float4(0.f, 0.f, 0.f, 0.f);
    int b = rowptr[row], e = rowptr[row + 1];
    int i = b;
    for (; i + 1 < e; i += 2) {
        long long p0 = __ldg(&esw[i]);
        long long p1 = __ldg(&esw[i + 1]);
        int s0 = (int)((unsigned long long)p0 & 0xffffffffull);
        int s1 = (int)((unsigned long long)p1 & 0xffffffffull);
        float w0 = __uint_as_float((unsigned)((unsigned long long)p0 >> 32));
        float w1 = __uint_as_float((unsigned)((unsigned long long)p1 >> 32));
        float4 v0 = sup4[(size_t)s0 * 32 + lane];
        float4 v1 = sup4[(size_t)s1 * 32 + lane];
        acc.x += w0 * v0.x; acc.y += w0 * v0.y; acc.z += w0 * v0.z; acc.w += w0 * v0.w;
        acc.x += w1 * v1.x; acc.y += w1 * v1.y; acc.z += w1 * v1.z; acc.w += w1 * v1.w;
    }
    if (i < e) {
        long long p0 = __ldg(&esw[i]);
        int s0 = (int)((unsigned long long)p0 & 0xffffffffull);
        float w0 = __uint_as_float((unsigned)((unsigned long long)p0 >> 32));
        float4 v0 = sup4[(size_t)s0 * 32 + lane];
        acc.x += w0 * v0.x; acc.y += w0 * v0.y; acc.z += w0 * v0.z; acc.w += w0 * v0.w;
    }
    reinterpret_cast<float4*>(h)[(size_t)row * 32 + lane] = acc;

    // fused BN stats
    __shared__ float sm_s[8][128];
    __shared__ float sm_q[8][128];
    float* ps = &sm_s[w][lane * 4];
    float* pq = &sm_q[w][lane * 4];
    ps[0] = acc.x; ps[1] = acc.y; ps[2] = acc.z; ps[3] = acc.w;
    pq[0] = acc.x * acc.x; pq[1] = acc.y * acc.y;
    pq[2] = acc.z * acc.z; pq[3] = acc.w * acc.w;
    __syncthreads();
    int t = threadIdx.x;
    if (t < 128) {
        float a = 0.f;
#pragma unroll
        for (int r = 0; r < 8; r++) a += sm_s[r][t];
        atomicAdd(&stats[t], a);
    } else {
        int c = t - 128;
        float a = 0.f;
#pragma unroll
        for (int r = 0; r < 8; r++) a += sm_q[r][c];
        atomicAdd(&stats[128 + c], a);
    }
}

// CSR spmm for 20-wide output, fused stats
__global__ __launch_bounds__(256) void spmm20_csr(const long long* __restrict__ esw,
                                                  const int* __restrict__ rowptr,
                                                  const float* __restrict__ sup,
                                                  float* __restrict__ h,
                                                  float* __restrict__ stats) {
    int w = threadIdx.x >> 5, lane = threadIdx.x & 31;
    int row = blockIdx.x * 8 + w;
    float acc = 0.f;
    int b = rowptr[row], e = rowptr[row + 1];
    for (int i = b; i < e; i++) {
        long long p0 = __ldg(&esw[i]);
        int s0 = (int)((unsigned long long)p0 & 0xffffffffull);
        float w0 = __uint_as_float((unsigned)((unsigned long long)p0 >> 32));
        if (lane < NO) acc += w0 * sup[(size_t)s0 * NO + lane];
    }
    if (lane < NO) h[(size_t)row * NO + lane] = acc;

    __shared__ float sm_s[8][NO];
    __shared__ float sm_q[8][NO];
    if (lane < NO) {
        sm_s[w][lane] = acc;
        sm_q[w][lane] = acc * acc;
    }
    __syncthreads();
    int t = threadIdx.x;
    if (t < NO) {
        float a = 0.f;
#pragma unroll
        for (int r = 0; r < 8; r++) a += sm_s[r][t];
        atomicAdd(&stats[t], a);
    } else if (t >= 32 && t < 32 + NO) {
        int c = t - 32;
        float a = 0.f;
#pragma unroll
        for (int r = 0; r < 8; r++) a += sm_q[r][c];
        atomicAdd(&stats[128 + c], a);
    }
}

// ---------------- other kernels ----------------

__global__ void gather_kernel(const int* __restrict__ verts,
                              const float* __restrict__ emb,
                              float* __restrict__ x) {
    int idx = blockIdx.x * blockDim.x + threadIdx.x;
    if (idx >= NN * 32) return;
    int row = idx >> 5, q = idx & 31;
    reinterpret_cast<float4*>(x)[idx] =
        reinterpret_cast<const float4*>(emb)[(size_t)verts[row] * 32 + q];
}

__global__ __launch_bounds__(256) void gemm_out(const float* __restrict__ A,
                                                const float* __restrict__ W,
                                                float* __restrict__ C) {
    __shared__ float Ws[128 * NO];
    for (int l = threadIdx.x; l < 128 * NO; l += 256) Ws[l] = W[l];
    __syncthreads();
    int idx = blockIdx.x * 256 + threadIdx.x;
    if (idx >= NN * NO) return;
    int row = idx / NO, col = idx % NO;
    const float4* a4 = reinterpret_cast<const float4*>(A + (size_t)row * 128);
    float s = 0.f;
#pragma unroll
    for (int k = 0; k < 32; k++) {
        float4 a = a4[k];
        s += a.x * Ws[(k * 4 + 0) * NO + col];
        s += a.y * Ws[(k * 4 + 1) * NO + col];
        s += a.z * Ws[(k * 4 + 2) * NO + col];
        s += a.w * Ws[(k * 4 + 3) * NO + col];
    }
    C[idx] = s;
}

__global__ void bnrelu20(float* __restrict__ h, const float* __restrict__ stats,
                         const float* __restrict__ gamma, const float* __restrict__ beta) {
    int idx = blockIdx.x * blockDim.x + threadIdx.x;
    if (idx >= NN * NO) return;
    int col = idx % NO;
    float mean = stats[col] * (1.f / NN);
    float var = stats[128 + col] * (1.f / NN) - mean * mean;
    float v = (h[idx] - mean) * rsqrtf(var + BN_EPS) * gamma[col] + beta[col];
    h[idx] = fmaxf(v, 0.f);
}

__global__ void maskreduce(const float* __restrict__ x20, const int* __restrict__ verts,
                           const float* __restrict__ mask_w, float* __restrict__ acc) {
    int gw = (blockIdx.x * blockDim.x + threadIdx.x) >> 5;
    int lane = threadIdx.x & 31;
    int nwarps = (gridDim.x * blockDim.x) >> 5;
    float a = 0.f;
    for (int r = gw; r < NN; r += nwarps) {
        float mw = mask_w[verts[r]];
        if (lane < NO) a += mw * x20[(size_t)r * NO + lane];
    }
    if (lane < NO) atomicAdd(&acc[lane], a);
}

__global__ void finalize(const float* __restrict__ acc, const float* __restrict__ mask_b,
                         float* __restrict__ out) {
    int o = threadIdx.x;
    if (o < NO) out[o] = 1.f / (1.f + expf(-(acc[o] + mask_b[o])));
}

// ---------------- one-time host resources ----------------
struct HostRes {
    cudaStream_t s1, s2;
    cudaEvent_t evRoot, evX, evGL;
    cudaEvent_t evSort[7], evSpmm[7];
    HostRes() {
        cudaStreamCreateWithFlags(&s1, cudaStreamNonBlocking);
        cudaStreamCreateWithFlags(&s2, cudaStreamNonBlocking);
        cudaEventCreateWithFlags(&evRoot, cudaEventDisableTiming);
        cudaEventCreateWithFlags(&evX, cudaEventDisableTiming);
        cudaEventCreateWithFlags(&evGL, cudaEventDisableTiming);
        for (int i = 0; i < 7; i++) {
            cudaEventCreateWithFlags(&evSort[i], cudaEventDisableTiming);
            cudaEventCreateWithFlags(&evSpmm[i], cudaEventDisableTiming);
        }
        cudaFuncSetAttribute(gemm_tc, cudaFuncAttributeMaxDynamicSharedMemorySize, GEMM_DYN_SMEM);
        cudaFuncSetAttribute(gate_gemm2, cudaFuncAttributeMaxDynamicSharedMemorySize, GEMM_DYN_SMEM);
    }
};
static HostRes g_res;

// ---------------- launch ----------------
extern "C" void kernel_launch(void* const* d_in, const int* in_sizes, int n_in,
                              void* d_out, int out_size) {
    const int*   vertices    = (const int*)d_in[0];
    const int*   edge_index  = (const int*)d_in[1];   // [7,2,NE]
    const float* edge_weight = (const float*)d_in[2]; // [7,NE]
    const float* emb         = (const float*)d_in[3];
    const float* w_h         = (const float*)d_in[4]; // [6,128,128]
    const float* w_out       = (const float*)d_in[6]; // [128,20]
    const float* bng         = (const float*)d_in[8];
    const float* bnb         = (const float*)d_in[9];
    const float* bng_o       = (const float*)d_in[10];
    const float* bnb_o       = (const float*)d_in[11];
    const float* te_wl       = (const float*)d_in[12];
    const float* te_wc       = (const float*)d_in[13];
    const float* te_b        = (const float*)d_in[14];
    const float* mask_w      = (const float*)d_in[15];
    const float* mask_b      = (const float*)d_in[16];
    float* out = (float*)d_out;

    float *x, *sup, *h, *gl, *sup20, *h20, *stats, *acc;
    long long *esw0, *esw1;
    int *rp0, *rp1, *cnt, *woff;
    cudaGetSymbolAddress((void**)&x,     g_x);
    cudaGetSymbolAddress((void**)&sup,   g_sup);
    cudaGetSymbolAddress((void**)&h,     g_h);
    cudaGetSymbolAddress((void**)&gl,    g_gl);
    cudaGetSymbolAddress((void**)&sup20, g_sup20);
    cudaGetSymbolAddress((void**)&h20,   g_h20);
    cudaGetSymbolAddress((void**)&stats, g_stats);
    cudaGetSymbolAddress((void**)&acc,   g_acc);
    cudaGetSymbolAddress((void**)&esw0,  g_esw);
    esw1 = esw0 + NE;
    cudaGetSymbolAddress((void**)&rp0,   g_rowptr);
    rp1 = rp0 + (NN + 1);
    cudaGetSymbolAddress((void**)&cnt,   g_cnt);
    cudaGetSymbolAddress((void**)&woff,  g_woff);

    long long* eswS[2] = {esw0, esw1};
    int* rpS[2] = {rp0, rp1};

    cudaStream_t s1 = g_res.s1, s2 = g_res.s2;
    const int TC_BLOCKS = (NN + 127) / 128;
    const int EB = (NE + 255) / 256;

    auto do_sort = [&](int L, cudaStream_t st) {
        const int* src = edge_index + (size_t)L * 2 * NE;
        const int* dst = src + NE;
        const float* ew = edge_weight + (size_t)L * NE;
        cudaMemsetAsync(cnt, 0, NN * sizeof(int), st);
        hist_kernel<<<EB, 256, 0, st>>>(dst, cnt);
        exscan_kernel<<<1, 1024, 0, st>>>(cnt, rpS[L & 1], woff);
        scatter_kernel<<<EB, 256, 0, st>>>(src, dst, ew, woff, eswS[L & 1]);
        cudaEventRecord(g_res.evSort[L], st);
    };

    // ---- fork point: all side streams branch off the capture stream ----
    cudaEventRecord(g_res.evRoot, 0);
    cudaStreamWaitEvent(s2, g_res.evRoot, 0);

    // prologue: sort layers 0 and 1 on s2 (serialized on s2)
    do_sort(0, s2);
    do_sort(1, s2);

    gather_kernel<<<(NN * 32 + 255) / 256, 256>>>(vertices, emb, x);
    cudaEventRecord(g_res.evX, 0);

    for (int i = 0; i < NLH; i++) {
        int j = (i + 5) % 6;  // faithful to reference's (i-1) % (L-1)

        // sort layer i+1 one iteration ahead (slot (i+1)&1 was last read by spmm i-1)
        if (i >= 1) {
            cudaStreamWaitEvent(s2, g_res.evSpmm[i - 1], 0);
            do_sort(i + 1, s2);
        }

        // side stream: gate-partial gemm (x @ te_wl)
        cudaStreamWaitEvent(s1, g_res.evX, 0);
        gemm_tc<<<TC_BLOCKS, 256, GEMM_DYN_SMEM, s1>>>(x, te_wl + (size_t)j * DD * DD, gl);
        cudaEventRecord(g_res.evGL, s1);

        // main: sup gemm -> spmm_csr(+stats) -> fused BN+gate gemm
        gemm_tc<<<TC_BLOCKS, 256, GEMM_DYN_SMEM>>>(x, w_h + (size_t)i * DD * DD, sup);
        cudaMemsetAsync(stats, 0, 2 * DD * sizeof(float));
        cudaStreamWaitEvent(0, g_res.evSort[i], 0);
        spmm_csr<<<NN / 8, 256>>>(eswS[i & 1], rpS[i & 1], sup, h, stats);
        cudaEventRecord(g_res.evSpmm[i], 0);
        cudaStreamWaitEvent(0, g_res.evGL, 0);
        gate_gemm2<<<TC_BLOCKS, 256, GEMM_DYN_SMEM>>>(x, h,
                                                      te_wc + (size_t)j * DD * DD,
                                                      gl, te_b + j * DD,
                                                      stats, bng + i * DD, bnb + i * DD);
        cudaEventRecord(g_res.evX, 0);
    }

    // output layer (i = 6), sorted edges in slot 6&1 = 0
    {
        gemm_out<<<(NN * NO + 255) / 256, 256>>>(x, w_out, sup20);
        cudaMemsetAsync(stats, 0, 2 * DD * sizeof(float));
        cudaStreamWaitEvent(0, g_res.evSort[6], 0);
        spmm20_csr<<<NN / 8, 256>>>(eswS[0], rpS[0], sup20, h20, stats);
        bnrelu20<<<(NN * NO + 255) / 256, 256>>>(h20, stats, bng_o, bnb_o);
    }

    cudaMemsetAsync(acc, 0, 32 * sizeof(float));
    maskreduce<<<200, 256>>>(h20, vertices, mask_w, acc);
    finalize<<<1, 32>>>(acc, mask_b, out);
}

// round 9
// speedup vs baseline: 1.6626x; 1.0462x over previous
#include <cuda_runtime.h>
#include <math.h>

#define NN 50000      // nodes
#define NE 800000     // edges per layer
#define DD 128        // feature dim
#define NO 20         // output dim
#define NLH 6         // hidden (gated) layers
#define BN_EPS 1e-5f

// ---------------- scratch (static device globals; no allocation) ----------------
__device__ __align__(16) float g_x[NN * DD];
__device__ __align__(16) float g_sup[NN * DD];
__device__ __align__(16) float g_h[NN * DD];
__device__ __align__(16) float g_gl[NN * DD];
__device__ __align__(16) float g_sup20[NN * NO];
__device__ __align__(16) float g_h20[NN * NO];
__device__ float g_stats[7 * 256];   // per-layer {sum[128] | sumsq[128]} slots
__device__ float g_acc[32];
// CSR double-buffer (sorted edges, packed {w:int(src)} 8B)
__device__ __align__(16) long long g_esw[2][NE];
__device__ int g_rowptr[2][NN + 1];
__device__ int g_cnt[NN];
__device__ int g_woff[NN];

// ---------------- tf32 helpers ----------------
__device__ __forceinline__ unsigned f2tf(float f) {
    unsigned u;
    asm("cvt.rna.tf32.f32 %0, %1;" : "=r"(u) : "f"(f));
    return u;
}

#define AS_STRIDE 36    // 128 rows x 32 cols A tile, padded (conflict-free)
#define WS_STRIDE 136   // 32 rows x 128 cols W tile, padded (conflict-free)
#define STAGE_U32 (128 * AS_STRIDE + 32 * WS_STRIDE)   // 8960 u32 per stage
#define GEMM_DYN_SMEM (2 * STAGE_U32 * 4)              // 71680 bytes

__device__ __forceinline__ void ldg_chunk(const float* __restrict__ A,
                                          const float* __restrict__ W,
                                          int row0, int kc, int tid,
                                          float4 va[4], float4 vw[4]) {
#pragma unroll
    for (int t = 0; t < 4; t++) {
        int e = tid + 256 * t;
        int r = e >> 3, q = e & 7;
        int gr = row0 + r;
        va[t] = (gr < NN)
            ? __ldg(&reinterpret_cast<const float4*>(A)[(size_t)gr * 32 + kc * 8 + q])
            : make_float4(0.f, 0.f, 0.f, 0.f);
        int k = e >> 5, q2 = e & 31;
        vw[t] = __ldg(&reinterpret_cast<const float4*>(W)[(size_t)(kc * 32 + k) * 32 + q2]);
    }
}

__device__ __forceinline__ void sts_chunk(const float4 va[4], const float4 vw[4],
                                          unsigned* As, unsigned* Ws, int tid, int kc,
                                          const float* scale, const float* shift) {
#pragma unroll
    for (int t = 0; t < 4; t++) {
        int e = tid + 256 * t;
        int r = e >> 3, q = e & 7;
        float4 v = va[t];
        if (scale) {
            int c = kc * 32 + q * 4;
            v.x = fmaxf(fmaf(v.x, scale[c + 0], shift[c + 0]), 0.f);
            v.y = fmaxf(fmaf(v.y, scale[c + 1], shift[c + 1]), 0.f);
            v.z = fmaxf(fmaf(v.z, scale[c + 2], shift[c + 2]), 0.f);
            v.w = fmaxf(fmaf(v.w, scale[c + 3], shift[c + 3]), 0.f);
        }
        unsigned* p = As + r * AS_STRIDE + q * 4;
        p[0] = f2tf(v.x); p[1] = f2tf(v.y); p[2] = f2tf(v.z); p[3] = f2tf(v.w);
        int k = e >> 5, q2 = e & 31;
        float4 w = vw[t];
        unsigned* pw = Ws + k * WS_STRIDE + q2 * 4;
        pw[0] = f2tf(w.x); pw[1] = f2tf(w.y); pw[2] = f2tf(w.z); pw[3] = f2tf(w.w);
    }
}

__device__ __forceinline__ void mma_chunk(const unsigned* As, const unsigned* Ws,
                                          float acc[4][4][4],
                                          int warp_m, int warp_n, int lane) {
    int g = lane >> 2, c = lane & 3;
#pragma unroll
    for (int kk = 0; kk < 4; kk++) {
        unsigned a[4][4];
#pragma unroll
        for (int mi = 0; mi < 4; mi++) {
            const unsigned* base = As + (warp_m * 64 + mi * 16 + g) * AS_STRIDE + kk * 8 + c;
            a[mi][0] = base[0];
            a[mi][1] = base[8 * AS_STRIDE];
            a[mi][2] = base[4];
            a[mi][3] = base[8 * AS_STRIDE + 4];
        }
        unsigned b[4][2];
#pragma unroll
        for (int nj = 0; nj < 4; nj++) {
            const unsigned* base = Ws + (kk * 8 + c) * WS_STRIDE + warp_n * 32 + nj * 8 + g;
            b[nj][0] = base[0];
            b[nj][1] = base[4 * WS_STRIDE];
        }
#pragma unroll
        for (int mi = 0; mi < 4; mi++)
#pragma unroll
            for (int nj = 0; nj < 4; nj++) {
                asm volatile(
                    "mma.sync.aligned.m16n8k8.row.col.f32.tf32.tf32.f32 "
                    "{%0,%1,%2,%3}, {%4,%5,%6,%7}, {%8,%9}, {%0,%1,%2,%3};\n"
                    : "+f"(acc[mi][nj][0]), "+f"(acc[mi][nj][1]),
                      "+f"(acc[mi][nj][2]), "+f"(acc[mi][nj][3])
                    : "r"(a[mi][0]), "r"(a[mi][1]), "r"(a[mi][2]), "r"(a[mi][3]),
                      "r"(b[nj][0]), "r"(b[nj][1]));
            }
    }
}

__device__ __forceinline__ void gemm_main(const float* __restrict__ A,
                                          const float* __restrict__ W,
                                          int row0, int tid, int warp_m, int warp_n,
                                          int lane, float acc[4][4][4],
                                          unsigned* dyn,
                                          const float* scale, const float* shift) {
    unsigned* As[2] = {dyn, dyn + STAGE_U32};
    unsigned* Ws[2] = {dyn + 128 * AS_STRIDE, dyn + STAGE_U32 + 128 * AS_STRIDE};
    float4 va[4], vw[4];
    ldg_chunk(A, W, row0, 0, tid, va, vw);
    sts_chunk(va, vw, As[0], Ws[0], tid, 0, scale, shift);
    __syncthreads();
#pragma unroll
    for (int kc = 0; kc < 4; kc++) {
        if (kc < 3) ldg_chunk(A, W, row0, kc + 1, tid, va, vw);
        mma_chunk(As[kc & 1], Ws[kc & 1], acc, warp_m, warp_n, lane);
        if (kc < 3) {
            sts_chunk(va, vw, As[(kc + 1) & 1], Ws[(kc + 1) & 1], tid, kc + 1, scale, shift);
            __syncthreads();
        }
    }
}

// dual GEMM: y==0 -> C0 = A@W0 ; y==1 -> C1 = A@W1  (782 blocks, better wave fill)
__global__ __launch_bounds__(256) void dual_gemm(const float* __restrict__ A,
                                                 const float* __restrict__ W0,
                                                 const float* __restrict__ W1,
                                                 float* __restrict__ C0,
                                                 float* __restrict__ C1) {
    extern __shared__ unsigned dyn[];
    int tid = threadIdx.x, wid = tid >> 5, lane = tid & 31;
    int warp_m = wid & 1, warp_n = wid >> 1;
    int row0 = blockIdx.x * 128;
    const float* W = blockIdx.y ? W1 : W0;
    float* C = blockIdx.y ? C1 : C0;

    float acc[4][4][4];
#pragma unroll
    for (int mi = 0; mi < 4; mi++)
#pragma unroll
        for (int nj = 0; nj < 4; nj++)
#pragma unroll
            for (int q = 0; q < 4; q++) acc[mi][nj][q] = 0.f;

    gemm_main(A, W, row0, tid, warp_m, warp_n, lane, acc, dyn, nullptr, nullptr);

    int g = lane >> 2, c = lane & 3;
#pragma unroll
    for (int mi = 0; mi < 4; mi++) {
        int r0 = row0 + warp_m * 64 + mi * 16 + g;
#pragma unroll
        for (int nj = 0; nj < 4; nj++) {
            int col = warp_n * 32 + nj * 8 + c * 2;
            if (r0 < NN)
                *reinterpret_cast<float2*>(C + (size_t)r0 * 128 + col) =
                    make_float2(acc[mi][nj][0], acc[mi][nj][1]);
            if (r0 + 8 < NN)
                *reinterpret_cast<float2*>(C + (size_t)(r0 + 8) * 128 + col) =
                    make_float2(acc[mi][nj][2], acc[mi][nj][3]);
        }
    }
}

// Fused: hn = relu(BN(h)); acc = hn @ wc; g = sigmoid(acc + gl + teb); x = g*hn + (1-g)*x
__global__ __launch_bounds__(256) void gate_gemm2(float* __restrict__ x,
                                                  const float* __restrict__ h,
                                                  const float* __restrict__ wc,
                                                  const float* __restrict__ gl,
                                                  const float* __restrict__ teb,
                                                  const float* __restrict__ stats,
                                                  const float* __restrict__ gamma,
                                                  const float* __restrict__ beta) {
    extern __shared__ unsigned dyn[];
    __shared__ float s_scale[128], s_shift[128];
    int tid = threadIdx.x, wid = tid >> 5, lane = tid & 31;
    int warp_m = wid & 1, warp_n = wid >> 1;
    int row0 = blockIdx.x * 128;

    if (tid < 128) {
        float m = stats[tid] * (1.f / NN);
        float var = stats[128 + tid] * (1.f / NN) - m * m;
        float sc = rsqrtf(var + BN_EPS) * gamma[tid];
        s_scale[tid] = sc;
        s_shift[tid] = beta[tid] - m * sc;
    }
    __syncthreads();

    float acc[4][4][4];
#pragma unroll
    for (int mi = 0; mi < 4; mi++)
#pragma unroll
        for (int nj = 0; nj < 4; nj++)
#pragma unroll
            for (int q = 0; q < 4; q++) acc[mi][nj][q] = 0.f;

    gemm_main(h, wc, row0, tid, warp_m, warp_n, lane, acc, dyn, s_scale, s_shift);

    int g = lane >> 2, c = lane & 3;
#pragma unroll
    for (int mi = 0; mi < 4; mi++) {
#pragma unroll
        for (int nj = 0; nj < 4; nj++) {
            int col = warp_n * 32 + nj * 8 + c * 2;
            float b0 = teb[col], b1 = teb[col + 1];
            float sc0 = s_scale[col], sc1 = s_scale[col + 1];
            float sh0 = s_shift[col], sh1 = s_shift[col + 1];
#pragma unroll
            for (int half = 0; half < 2; half++) {
                int r = row0 + warp_m * 64 + mi * 16 + g + half * 8;
                if (r < NN) {
                    size_t o = (size_t)r * 128 + col;
                    float2 hv = *reinterpret_cast<const float2*>(h + o);
                    float2 xv = *reinterpret_cast<const float2*>(x + o);
                    float2 gv = *reinterpret_cast<const float2*>(gl + o);
                    float hn0 = fmaxf(fmaf(hv.x, sc0, sh0), 0.f);
                    float hn1 = fmaxf(fmaf(hv.y, sc1, sh1), 0.f);
                    float ga = 1.f / (1.f + expf(-(acc[mi][nj][half * 2 + 0] + gv.x + b0)));
                    float gb = 1.f / (1.f + expf(-(acc[mi][nj][half * 2 + 1] + gv.y + b1)));
                    float2 r2;
                    r2.x = ga * hn0 + (1.f - ga) * xv.x;
                    r2.y = gb * hn1 + (1.f - gb) * xv.y;
                    *reinterpret_cast<float2*>(x + o) = r2;
                }
            }
        }
    }
}

// ---------------- CSR build ----------------

__global__ void hist_kernel(const int* __restrict__ dst, int* __restrict__ cnt) {
    int e4 = blockIdx.x * 256 + threadIdx.x;   // NE/4 = 200000 threads
    if (e4 >= NE / 4) return;
    int4 d = __ldg(&reinterpret_cast<const int4*>(dst)[e4]);
    atomicAdd(&cnt[d.x], 1);
    atomicAdd(&cnt[d.y], 1);
    atomicAdd(&cnt[d.z], 1);
    atomicAdd(&cnt[d.w], 1);
}

// coalesced tiled exclusive scan over cnt[NN] -> rowptr/woff
__global__ __launch_bounds__(1024) void exscan_kernel(const int* __restrict__ cnt,
                                                      int* __restrict__ rowptr,
                                                      int* __restrict__ woff) {
    __shared__ int wsum[32];
    __shared__ int s_carry;
    int t = threadIdx.x, lane = t & 31, w = t >> 5;
    if (t == 0) s_carry = 0;
    __syncthreads();
    const int NT = (NN + 1023) / 1024;   // 49
    for (int tile = 0; tile < NT; tile++) {
        int idx = tile * 1024 + t;
        int v = (idx < NN) ? cnt[idx] : 0;
        int xs = v;
#pragma unroll
        for (int o = 1; o < 32; o <<= 1) {
            int y = __shfl_up_sync(0xffffffffu, xs, o);
            if (lane >= o) xs += y;
        }
        if (lane == 31) wsum[w] = xs;
        __syncthreads();
        if (w == 0) {
            int s = wsum[lane];
#pragma unroll
            for (int o = 1; o < 32; o <<= 1) {
                int y = __shfl_up_sync(0xffffffffu, s, o);
                if (lane >= o) s += y;
            }
            wsum[lane] = s;
        }
        __syncthreads();
        int base = s_carry + (w > 0 ? wsum[w - 1] : 0);
        int excl = base + xs - v;
        if (idx < NN) { rowptr[idx] = excl; woff[idx] = excl; }
        __syncthreads();
        if (t == 0) s_carry += wsum[31];
        __syncthreads();
    }
    if (t == 0) rowptr[NN] = s_carry;
}

__global__ void scatter_kernel(const int* __restrict__ src, const int* __restrict__ dst,
                               const float* __restrict__ w, int* __restrict__ woff,
                               long long* __restrict__ esw) {
    int e = blockIdx.x * 256 + threadIdx.x;
    if (e >= NE) return;
    int d = dst[e];
    int pos = atomicAdd(&woff[d], 1);
    unsigned long long pk =
        ((unsigned long long)__float_as_uint(w[e]) << 32) | (unsigned)src[e];
    esw[pos] = (long long)pk;
}

// CSR spmm: warp per dst row, register accumulate, fused column stats
__global__ __launch_bounds__(256) void spmm_csr(const long long* __restrict__ esw,
                                                const int* __restrict__ rowptr,
                                                const float* __restrict__ sup,
                                                float* __restrict__ h,
                                                float* __restrict__ stats) {
    int w = threadIdx.x >> 5, lane = threadIdx.x & 31;
    int row = blockIdx.x * 8 + w;
    const float4* sup4 = reinterpret_cast<const float4*>(sup);
    float4 acc = make_float4(0.f, 0.f, 0.f, 0.f);
    int b = rowptr[row], e = rowptr[row + 1];
    int i = b;
    for (; i + 1 < e; i += 2) {
        long long p0 = __ldg(&esw[i]);
        long long p1 = __ldg(&esw[i + 1]);
        int s0 = (int)((unsigned long long)p0 & 0xffffffffull);
        int s1 = (int)((unsigned long long)p1 & 0xffffffffull);
        float w0 = __uint_as_float((unsigned)((unsigned long long)p0 >> 32));
        float w1 = __uint_as_float((unsigned)((unsigned long long)p1 >> 32));
        float4 v0 = sup4[(size_t)s0 * 32 + lane];
        float4 v1 = sup4[(size_t)s1 * 32 + lane];
        acc.x += w0 * v0.x; acc.y += w0 * v0.y; acc.z += w0 * v0.z; acc.w += w0 * v0.w;
        acc.x += w1 * v1.x; acc.y += w1 * v1.y; acc.z += w1 * v1.z; acc.w += w1 * v1.w;
    }
    if (i < e) {
        long long p0 = __ldg(&esw[i]);
        int s0 = (int)((unsigned long long)p0 & 0xffffffffull);
        float w0 = __uint_as_float((unsigned)((unsigned long long)p0 >> 32));
        float4 v0 = sup4[(size_t)s0 * 32 + lane];
        acc.x += w0 * v0.x; acc.y += w0 * v0.y; acc.z += w0 * v0.z; acc.w += w0 * v0.w;
    }
    reinterpret_cast<float4*>(h)[(size_t)row * 32 + lane] = acc;

    // fused BN stats
    __shared__ float sm_s[8][128];
    __shared__ float sm_q[8][128];
    float* ps = &sm_s[w][lane * 4];
    float* pq = &sm_q[w][lane * 4];
    ps[0] = acc.x; ps[1] = acc.y; ps[2] = acc.z; ps[3] = acc.w;
    pq[0] = acc.x * acc.x; pq[1] = acc.y * acc.y;
    pq[2] = acc.z * acc.z; pq[3] = acc.w * acc.w;
    __syncthreads();
    int t = threadIdx.x;
    if (t < 128) {
        float a = 0.f;
#pragma unroll
        for (int r = 0; r < 8; r++) a += sm_s[r][t];
        atomicAdd(&stats[t], a);
    } else {
        int c = t - 128;
        float a = 0.f;
#pragma unroll
        for (int r = 0; r < 8; r++) a += sm_q[r][c];
        atomicAdd(&stats[128 + c], a);
    }
}

// CSR spmm for 20-wide output, fused stats
__global__ __launch_bounds__(256) void spmm20_csr(const long long* __restrict__ esw,
                                                  const int* __restrict__ rowptr,
                                                  const float* __restrict__ sup,
                                                  float* __restrict__ h,
                                                  float* __restrict__ stats) {
    int w = threadIdx.x >> 5, lane = threadIdx.x & 31;
    int row = blockIdx.x * 8 + w;
    float acc = 0.f;
    int b = rowptr[row], e = rowptr[row + 1];
    for (int i = b; i < e; i++) {
        long long p0 = __ldg(&esw[i]);
        int s0 = (int)((unsigned long long)p0 & 0xffffffffull);
        float w0 = __uint_as_float((unsigned)((unsigned long long)p0 >> 32));
        if (lane < NO) acc += w0 * sup[(size_t)s0 * NO + lane];
    }
    if (lane < NO) h[(size_t)row * NO + lane] = acc;

    __shared__ float sm_s[8][NO];
    __shared__ float sm_q[8][NO];
    if (lane < NO) {
        sm_s[w][lane] = acc;
        sm_q[w][lane] = acc * acc;
    }
    __syncthreads();
    int t = threadIdx.x;
    if (t < NO) {
        float a = 0.f;
#pragma unroll
        for (int r = 0; r < 8; r++) a += sm_s[r][t];
        atomicAdd(&stats[t], a);
    } else if (t >= 32 && t < 32 + NO) {
        int c = t - 32;
        float a = 0.f;
#pragma unroll
        for (int r = 0; r < 8; r++) a += sm_q[r][c];
        atomicAdd(&stats[128 + c], a);
    }
}

// ---------------- other kernels ----------------

__global__ void gather_kernel(const int* __restrict__ verts,
                              const float* __restrict__ emb,
                              float* __restrict__ x) {
    int idx = blockIdx.x * blockDim.x + threadIdx.x;
    if (idx >= NN * 32) return;
    int row = idx >> 5, q = idx & 31;
    reinterpret_cast<float4*>(x)[idx] =
        reinterpret_cast<const float4*>(emb)[(size_t)verts[row] * 32 + q];
}

// C[NN,20] = A[NN,128] @ W[128,20] — warp per row, row read once
__global__ __launch_bounds__(256) void gemm_out_w(const float* __restrict__ A,
                                                  const float* __restrict__ W,
                                                  float* __restrict__ C) {
    __shared__ float Ws[128 * NO];
    for (int l = threadIdx.x; l < 128 * NO; l += 256) Ws[l] = W[l];
    __syncthreads();
    int w = threadIdx.x >> 5, lane = threadIdx.x & 31;
    int row = blockIdx.x * 8 + w;
    float4 a = reinterpret_cast<const float4*>(A)[(size_t)row * 32 + lane];
    float acc[NO];
    const float* w0 = &Ws[(4 * lane + 0) * NO];
    const float* w1 = &Ws[(4 * lane + 1) * NO];
    const float* w2 = &Ws[(4 * lane + 2) * NO];
    const float* w3 = &Ws[(4 * lane + 3) * NO];
#pragma unroll
    for (int c = 0; c < NO; c++)
        acc[c] = a.x * w0[c] + a.y * w1[c] + a.z * w2[c] + a.w * w3[c];
#pragma unroll
    for (int o = 16; o; o >>= 1)
#pragma unroll
        for (int c = 0; c < NO; c++)
            acc[c] += __shfl_xor_sync(0xffffffffu, acc[c], o);
    if (lane < NO) C[(size_t)row * NO + lane] = acc[lane];
}

// fused BN+relu+mask reduce: acc[o] += mask_w[verts[r]] * relu(BN(h20[r,o]))
__global__ void maskreduce_f(const float* __restrict__ h20, const int* __restrict__ verts,
                             const float* __restrict__ mask_w,
                             const float* __restrict__ stats,
                             const float* __restrict__ gamma, const float* __restrict__ beta,
                             float* __restrict__ acc) {
    int gw = (blockIdx.x * blockDim.x + threadIdx.x) >> 5;
    int lane = threadIdx.x & 31;
    int nwarps = (gridDim.x * blockDim.x) >> 5;
    float sc = 0.f, sh = 0.f;
    if (lane < NO) {
        float m = stats[lane] * (1.f / NN);
        float var = stats[128 + lane] * (1.f / NN) - m * m;
        sc = rsqrtf(var + BN_EPS) * gamma[lane];
        sh = beta[lane] - m * sc;
    }
    float a = 0.f;
    for (int r = gw; r < NN; r += nwarps) {
        float mw = mask_w[verts[r]];
        if (lane < NO) {
            float hn = fmaxf(fmaf(h20[(size_t)r * NO + lane], sc, sh), 0.f);
            a += mw * hn;
        }
    }
    if (lane < NO) atomicAdd(&acc[lane], a);
}

__global__ void finalize(const float* __restrict__ acc, const float* __restrict__ mask_b,
                         float* __restrict__ out) {
    int o = threadIdx.x;
    if (o < NO) out[o] = 1.f / (1.f + expf(-(acc[o] + mask_b[o])));
}

// ---------------- one-time host resources ----------------
struct HostRes {
    cudaStream_t s2;
    cudaEvent_t evRoot;
    cudaEvent_t evSort[7], evSpmm[7];
    HostRes() {
        cudaStreamCreateWithFlags(&s2, cudaStreamNonBlocking);
        cudaEventCreateWithFlags(&evRoot, cudaEventDisableTiming);
        for (int i = 0; i < 7; i++) {
            cudaEventCreateWithFlags(&evSort[i], cudaEventDisableTiming);
            cudaEventCreateWithFlags(&evSpmm[i], cudaEventDisableTiming);
        }
        cudaFuncSetAttribute(dual_gemm, cudaFuncAttributeMaxDynamicSharedMemorySize, GEMM_DYN_SMEM);
        cudaFuncSetAttribute(gate_gemm2, cudaFuncAttributeMaxDynamicSharedMemorySize, GEMM_DYN_SMEM);
    }
};
static HostRes g_res;

// ---------------- launch ----------------
extern "C" void kernel_launch(void* const* d_in, const int* in_sizes, int n_in,
                              void* d_out, int out_size) {
    const int*   vertices    = (const int*)d_in[0];
    const int*   edge_index  = (const int*)d_in[1];   // [7,2,NE]
    const float* edge_weight = (const float*)d_in[2]; // [7,NE]
    const float* emb         = (const float*)d_in[3];
    const float* w_h         = (const float*)d_in[4]; // [6,128,128]
    const float* w_out       = (const float*)d_in[6]; // [128,20]
    const float* bng         = (const float*)d_in[8];
    const float* bnb         = (const float*)d_in[9];
    const float* bng_o       = (const float*)d_in[10];
    const float* bnb_o       = (const float*)d_in[11];
    const float* te_wl       = (const float*)d_in[12];
    const float* te_wc       = (const float*)d_in[13];
    const float* te_b        = (const float*)d_in[14];
    const float* mask_w      = (const float*)d_in[15];
    const float* mask_b      = (const float*)d_in[16];
    float* out = (float*)d_out;

    float *x, *sup, *h, *gl, *sup20, *h20, *stats, *acc;
    long long *esw0, *esw1;
    int *rp0, *rp1, *cnt, *woff;
    cudaGetSymbolAddress((void**)&x,     g_x);
    cudaGetSymbolAddress((void**)&sup,   g_sup);
    cudaGetSymbolAddress((void**)&h,     g_h);
    cudaGetSymbolAddress((void**)&gl,    g_gl);
    cudaGetSymbolAddress((void**)&sup20, g_sup20);
    cudaGetSymbolAddress((void**)&h20,   g_h20);
    cudaGetSymbolAddress((void**)&stats, g_stats);
    cudaGetSymbolAddress((void**)&acc,   g_acc);
    cudaGetSymbolAddress((void**)&esw0,  g_esw);
    esw1 = esw0 + NE;
    cudaGetSymbolAddress((void**)&rp0,   g_rowptr);
    rp1 = rp0 + (NN + 1);
    cudaGetSymbolAddress((void**)&cnt,   g_cnt);
    cudaGetSymbolAddress((void**)&woff,  g_woff);

    long long* eswS[2] = {esw0, esw1};
    int* rpS[2] = {rp0, rp1};

    cudaStream_t s2 = g_res.s2;
    const int TC_BLOCKS = (NN + 127) / 128;   // 391
    const int EB = (NE + 255) / 256;

    auto do_sort = [&](int L, cudaStream_t st) {
        const int* src = edge_index + (size_t)L * 2 * NE;
        const int* dst = src + NE;
        const float* ew = edge_weight + (size_t)L * NE;
        cudaMemsetAsync(cnt, 0, NN * sizeof(int), st);
        hist_kernel<<<(NE / 4 + 255) / 256, 256, 0, st>>>(dst, cnt);
        exscan_kernel<<<1, 1024, 0, st>>>(cnt, rpS[L & 1], woff);
        scatter_kernel<<<EB, 256, 0, st>>>(src, dst, ew, woff, eswS[L & 1]);
        cudaEventRecord(g_res.evSort[L], st);
    };

    // ---- fork point: side stream branches off the capture stream ----
    cudaEventRecord(g_res.evRoot, 0);
    cudaStreamWaitEvent(s2, g_res.evRoot, 0);

    // prologue: sort layers 0 and 1 on s2
    do_sort(0, s2);
    do_sort(1, s2);

    cudaMemsetAsync(stats, 0, 7 * 256 * sizeof(float));
    cudaMemsetAsync(acc, 0, 32 * sizeof(float));
    gather_kernel<<<(NN * 32 + 255) / 256, 256>>>(vertices, emb, x);

    for (int i = 0; i < NLH; i++) {
        int j = (i + 5) % 6;  // faithful to reference's (i-1) % (L-1)

        // sort layer i+1 one iteration ahead (slot (i+1)&1 last read by spmm i-1)
        if (i >= 1) {
            cudaStreamWaitEvent(s2, g_res.evSpmm[i - 1], 0);
            do_sort(i + 1, s2);
        }

        // main: dual gemm (sup + gl) -> spmm_csr(+stats) -> fused BN+gate gemm
        dual_gemm<<<dim3(TC_BLOCKS, 2), 256, GEMM_DYN_SMEM>>>(
            x, w_h + (size_t)i * DD * DD, te_wl + (size_t)j * DD * DD, sup, gl);
        cudaStreamWaitEvent(0, g_res.evSort[i], 0);
        spmm_csr<<<NN / 8, 256>>>(eswS[i & 1], rpS[i & 1], sup, h, stats + i * 256);
        cudaEventRecord(g_res.evSpmm[i], 0);
        gate_gemm2<<<TC_BLOCKS, 256, GEMM_DYN_SMEM>>>(x, h,
                                                      te_wc + (size_t)j * DD * DD,
                                                      gl, te_b + j * DD,
                                                      stats + i * 256,
                                                      bng + i * DD, bnb + i * DD);
    }

    // output layer (i = 6), sorted edges in slot 6&1 = 0
    {
        gemm_out_w<<<NN / 8, 256>>>(x, w_out, sup20);
        cudaStreamWaitEvent(0, g_res.evSort[6], 0);
        spmm20_csr<<<NN / 8, 256>>>(eswS[0], rpS[0], sup20, h20, stats + 6 * 256);
        maskreduce_f<<<200, 256>>>(h20, vertices, mask_w, stats + 6 * 256,
                                   bng_o, bnb_o, acc);
    }

    finalize<<<1, 32>>>(acc, mask_b, out);
}

// round 11
// speedup vs baseline: 1.7673x; 1.0630x over previous
#include <cuda_runtime.h>
#include <cuda_fp16.h>
#include <math.h>

#define NN 50000      // nodes
#define NE 800000     // edges per layer
#define DD 128        // feature dim
#define NO 20         // output dim
#define NLH 6         // hidden (gated) layers
#define BN_EPS 1e-5f

// ---------------- scratch (static device globals; no allocation) ----------------
__device__ __align__(16) float  g_x[NN * DD];
__device__ __align__(16) __half g_sup[NN * DD];
__device__ __align__(16) __half g_h[NN * DD];
__device__ __align__(16) __half g_gl[NN * DD];
__device__ __align__(16) float  g_sup20[NN * NO];
__device__ __align__(16) float  g_h20[NN * NO];
__device__ float g_stats[7 * 256];   // per-layer {sum[128] | sumsq[128]} slots
__device__ float g_acc[32];
// CSR double-buffer (sorted edges, packed {w:int(src)} 8B)
__device__ __align__(16) long long g_esw[2][NE];
__device__ int g_rowptr[2][NN + 1];
__device__ int g_cnt[NN];
__device__ int g_woff[NN];

// ---------------- tf32 helpers ----------------
__device__ __forceinline__ unsigned f2tf(float f) {
    unsigned u;
    asm("cvt.rna.tf32.f32 %0, %1;" : "=r"(u) : "f"(f));
    return u;
}

#define AS_STRIDE 36    // 128 rows x 32 cols A tile, padded (conflict-free)
#define WS_STRIDE 136   // 32 rows x 128 cols W tile, padded (conflict-free)
#define STAGE_U32 (128 * AS_STRIDE + 32 * WS_STRIDE)   // 8960 u32 per stage
#define GEMM_DYN_SMEM (2 * STAGE_U32 * 4)              // 71680 bytes

// fp32-A chunk prefetch
__device__ __forceinline__ void ldg_chunk_f(const float* __restrict__ A,
                                            const float* __restrict__ W,
                                            int row0, int kc, int tid,
                                            float4 va[4], float4 vw[4]) {
#pragma unroll
    for (int t = 0; t < 4; t++) {
        int e = tid + 256 * t;
        int r = e >> 3, q = e & 7;
        int gr = row0 + r;
        va[t] = (gr < NN)
            ? __ldg(&reinterpret_cast<const float4*>(A)[(size_t)gr * 32 + kc * 8 + q])
            : make_float4(0.f, 0.f, 0.f, 0.f);
        int k = e >> 5, q2 = e & 31;
        vw[t] = __ldg(&reinterpret_cast<const float4*>(W)[(size_t)(kc * 32 + k) * 32 + q2]);
    }
}

// fp16-A chunk prefetch (dequantize to float)
__device__ __forceinline__ void ldg_chunk_h(const __half* __restrict__ A,
                                            const float* __restrict__ W,
                                            int row0, int kc, int tid,
                                            float4 va[4], float4 vw[4]) {
#pragma unroll
    for (int t = 0; t < 4; t++) {
        int e = tid + 256 * t;
        int r = e >> 3, q = e & 7;
        int gr = row0 + r;
        if (gr < NN) {
            uint2 raw = __ldg(reinterpret_cast<const uint2*>(
                A + ((size_t)gr * 128 + kc * 32 + q * 4)));
            float2 f01 = __half22float2(*reinterpret_cast<__half2*>(&raw.x));
            float2 f23 = __half22float2(*reinterpret_cast<__half2*>(&raw.y));
            va[t] = make_float4(f01.x, f01.y, f23.x, f23.y);
        } else {
            va[t] = make_float4(0.f, 0.f, 0.f, 0.f);
        }
        int k = e >> 5, q2 = e & 31;
        vw[t] = __ldg(&reinterpret_cast<const float4*>(W)[(size_t)(kc * 32 + k) * 32 + q2]);
    }
}

__device__ __forceinline__ void sts_chunk(const float4 va[4], const float4 vw[4],
                                          unsigned* As, unsigned* Ws, int tid, int kc,
                                          const float* scale, const float* shift) {
#pragma unroll
    for (int t = 0; t < 4; t++) {
        int e = tid + 256 * t;
        int r = e >> 3, q = e & 7;
        float4 v = va[t];
        if (scale) {
            int c = kc * 32 + q * 4;
            v.x = fmaxf(fmaf(v.x, scale[c + 0], shift[c + 0]), 0.f);
            v.y = fmaxf(fmaf(v.y, scale[c + 1], shift[c + 1]), 0.f);
            v.z = fmaxf(fmaf(v.z, scale[c + 2], shift[c + 2]), 0.f);
            v.w = fmaxf(fmaf(v.w, scale[c + 3], shift[c + 3]), 0.f);
        }
        unsigned* p = As + r * AS_STRIDE + q * 4;
        p[0] = f2tf(v.x); p[1] = f2tf(v.y); p[2] = f2tf(v.z); p[3] = f2tf(v.w);
        int k = e >> 5, q2 = e & 31;
        float4 w = vw[t];
        unsigned* pw = Ws + k * WS_STRIDE + q2 * 4;
        pw[0] = f2tf(w.x); pw[1] = f2tf(w.y); pw[2] = f2tf(w.z); pw[3] = f2tf(w.w);
    }
}

__device__ __forceinline__ void mma_chunk(const unsigned* As, const unsigned* Ws,
                                          float acc[4][4][4],
                                          int warp_m, int warp_n, int lane) {
    int g = lane >> 2, c = lane & 3;
#pragma unroll
    for (int kk = 0; kk < 4; kk++) {
        unsigned a[4][4];
#pragma unroll
        for (int mi = 0; mi < 4; mi++) {
            const unsigned* base = As + (warp_m * 64 + mi * 16 + g) * AS_STRIDE + kk * 8 + c;
            a[mi][0] = base[0];
            a[mi][1] = base[8 * AS_STRIDE];
            a[mi][2] = base[4];
            a[mi][3] = base[8 * AS_STRIDE + 4];
        }
        unsigned b[4][2];
#pragma unroll
        for (int nj = 0; nj < 4; nj++) {
            const unsigned* base = Ws + (kk * 8 + c) * WS_STRIDE + warp_n * 32 + nj * 8 + g;
            b[nj][0] = base[0];
            b[nj][1] = base[4 * WS_STRIDE];
        }
#pragma unroll
        for (int mi = 0; mi < 4; mi++)
#pragma unroll
            for (int nj = 0; nj < 4; nj++) {
                asm volatile(
                    "mma.sync.aligned.m16n8k8.row.col.f32.tf32.tf32.f32 "
                    "{%0,%1,%2,%3}, {%4,%5,%6,%7}, {%8,%9}, {%0,%1,%2,%3};\n"
                    : "+f"(acc[mi][nj][0]), "+f"(acc[mi][nj][1]),
                      "+f"(acc[mi][nj][2]), "+f"(acc[mi][nj][3])
                    : "r"(a[mi][0]), "r"(a[mi][1]), "r"(a[mi][2]), "r"(a[mi][3]),
                      "r"(b[nj][0]), "r"(b[nj][1]));
            }
    }
}

// fp32-A double-buffered main loop
__device__ __forceinline__ void gemm_main_f(const float* __restrict__ A,
                                            const float* __restrict__ W,
                                            int row0, int tid, int warp_m, int warp_n,
                                            int lane, float acc[4][4][4],
                                            unsigned* dyn) {
    unsigned* As[2] = {dyn, dyn + STAGE_U32};
    unsigned* Ws[2] = {dyn + 128 * AS_STRIDE, dyn + STAGE_U32 + 128 * AS_STRIDE};
    float4 va[4], vw[4];
    ldg_chunk_f(A, W, row0, 0, tid, va, vw);
    sts_chunk(va, vw, As[0], Ws[0], tid, 0, nullptr, nullptr);
    __syncthreads();
#pragma unroll
    for (int kc = 0; kc < 4; kc++) {
        if (kc < 3) ldg_chunk_f(A, W, row0, kc + 1, tid, va, vw);
        mma_chunk(As[kc & 1], Ws[kc & 1], acc, warp_m, warp_n, lane);
        if (kc < 3) {
            sts_chunk(va, vw, As[(kc + 1) & 1], Ws[(kc + 1) & 1], tid, kc + 1,
                      nullptr, nullptr);
            __syncthreads();
        }
    }
}

// fp16-A (+ BN/ReLU normalize) double-buffered main loop
__device__ __forceinline__ void gemm_main_h(const __half* __restrict__ A,
                                            const float* __restrict__ W,
                                            int row0, int tid, int warp_m, int warp_n,
                                            int lane, float acc[4][4][4],
                                            unsigned* dyn,
                                            const float* scale, const float* shift) {
    unsigned* As[2] = {dyn, dyn + STAGE_U32};
    unsigned* Ws[2] = {dyn + 128 * AS_STRIDE, dyn + STAGE_U32 + 128 * AS_STRIDE};
    float4 va[4], vw[4];
    ldg_chunk_h(A, W, row0, 0, tid, va, vw);
    sts_chunk(va, vw, As[0], Ws[0], tid, 0, scale, shift);
    __syncthreads();
#pragma unroll
    for (int kc = 0; kc < 4; kc++) {
        if (kc < 3) ldg_chunk_h(A, W, row0, kc + 1, tid, va, vw);
        mma_chunk(As[kc & 1], Ws[kc & 1], acc, warp_m, warp_n, lane);
        if (kc < 3) {
            sts_chunk(va, vw, As[(kc + 1) & 1], Ws[(kc + 1) & 1], tid, kc + 1,
                      scale, shift);
            __syncthreads();
        }
    }
}

// dual GEMM: y==0 -> sup = x@W0 ; y==1 -> gl = x@W1   (fp16 outputs)
__global__ __launch_bounds__(256) void dual_gemm(const float* __restrict__ A,
                                                 const float* __restrict__ W0,
                                                 const float* __restrict__ W1,
                                                 __half* __restrict__ C0,
                                                 __half* __restrict__ C1) {
    extern __shared__ unsigned dyn[];
    int tid = threadIdx.x, wid = tid >> 5, lane = tid & 31;
    int warp_m = wid & 1, warp_n = wid >> 1;
    int row0 = blockIdx.x * 128;
    const float* W = blockIdx.y ? W1 : W0;
    __half* C = blockIdx.y ? C1 : C0;

    float acc[4][4][4];
#pragma unroll
    for (int mi = 0; mi < 4; mi++)
#pragma unroll
        for (int nj = 0; nj < 4; nj++)
#pragma unroll
            for (int q = 0; q < 4; q++) acc[mi][nj][q] = 0.f;

    gemm_main_f(A, W, row0, tid, warp_m, warp_n, lane, acc, dyn);

    int g = lane >> 2, c = lane & 3;
#pragma unroll
    for (int mi = 0; mi < 4; mi++) {
        int r0 = row0 + warp_m * 64 + mi * 16 + g;
#pragma unroll
        for (int nj = 0; nj < 4; nj++) {
            int col = warp_n * 32 + nj * 8 + c * 2;
            if (r0 < NN)
                *reinterpret_cast<__half2*>(C + (size_t)r0 * 128 + col) =
                    __floats2half2_rn(acc[mi][nj][0], acc[mi][nj][1]);
            if (r0 + 8 < NN)
                *reinterpret_cast<__half2*>(C + (size_t)(r0 + 8) * 128 + col) =
                    __floats2half2_rn(acc[mi][nj][2], acc[mi][nj][3]);
        }
    }
}

// Fused: hn = relu(BN(h)); acc = hn @ wc; g = sigmoid(acc + gl + teb); x = g*hn + (1-g)*x
__global__ __launch_bounds__(256) void gate_gemm2(float* __restrict__ x,
                                                  const __half* __restrict__ h,
                                                  const float* __restrict__ wc,
                                                  const __half* __restrict__ gl,
                                                  const float* __restrict__ teb,
                                                  const float* __restrict__ stats,
                                                  const float* __restrict__ gamma,
                                                  const float* __restrict__ beta) {
    extern __shared__ unsigned dyn[];
    __shared__ float s_scale[128], s_shift[128];
    int tid = threadIdx.x, wid = tid >> 5, lane = tid & 31;
    int warp_m = wid & 1, warp_n = wid >> 1;
    int row0 = blockIdx.x * 128;

    if (tid < 128) {
        float m = stats[tid] * (1.f / NN);
        float var = stats[128 + tid] * (1.f / NN) - m * m;
        float sc = rsqrtf(var + BN_EPS) * gamma[tid];
        s_scale[tid] = sc;
        s_shift[tid] = beta[tid] - m * sc;
    }
    __syncthreads();

    float acc[4][4][4];
#pragma unroll
    for (int mi = 0; mi < 4; mi++)
#pragma unroll
        for (int nj = 0; nj < 4; nj++)
#pragma unroll
            for (int q = 0; q < 4; q++) acc[mi][nj][q] = 0.f;

    gemm_main_h(h, wc, row0, tid, warp_m, warp_n, lane, acc, dyn, s_scale, s_shift);

    int g = lane >> 2, c = lane & 3;
#pragma unroll
    for (int mi = 0; mi < 4; mi++) {
#pragma unroll
        for (int nj = 0; nj < 4; nj++) {
            int col = warp_n * 32 + nj * 8 + c * 2;
            float b0 = teb[col], b1 = teb[col + 1];
            float sc0 = s_scale[col], sc1 = s_scale[col + 1];
            float sh0 = s_shift[col], sh1 = s_shift[col + 1];
#pragma unroll
            for (int half = 0; half < 2; half++) {
                int r = row0 + warp_m * 64 + mi * 16 + g + half * 8;
                if (r < NN) {
                    size_t o = (size_t)r * 128 + col;
                    float2 hv = __half22float2(
                        *reinterpret_cast<const __half2*>(h + o));
                    float2 gv = __half22float2(
                        *reinterpret_cast<const __half2*>(gl + o));
                    float2 xv = *reinterpret_cast<const float2*>(x + o);
                    float hn0 = fmaxf(fmaf(hv.x, sc0, sh0), 0.f);
                    float hn1 = fmaxf(fmaf(hv.y, sc1, sh1), 0.f);
                    float ga = 1.f / (1.f + expf(-(acc[mi][nj][half * 2 + 0] + gv.x + b0)));
                    float gb = 1.f / (1.f + expf(-(acc[mi][nj][half * 2 + 1] + gv.y + b1)));
                    float2 r2;
                    r2.x = ga * hn0 + (1.f - ga) * xv.x;
                    r2.y = gb * hn1 + (1.f - gb) * xv.y;
                    *reinterpret_cast<float2*>(x + o) = r2;
                }
            }
        }
    }
}

// ---------------- CSR build ----------------

__global__ void hist_kernel(const int* __restrict__ dst, int* __restrict__ cnt) {
    int e4 = blockIdx.x * 256 + threadIdx.x;
    if (e4 >= NE / 4) return;
    int4 d = __ldg(&reinterpret_cast<const int4*>(dst)[e4]);
    atomicAdd(&cnt[d.x], 1);
    atomicAdd(&cnt[d.y], 1);
    atomicAdd(&cnt[d.z], 1);
    atomicAdd(&cnt[d.w], 1);
}

__global__ __launch_bounds__(1024) void exscan_kernel(const int* __restrict__ cnt,
                                                      int* __restrict__ rowptr,
                                                      int* __restrict__ woff) {
    __shared__ int wsum[32];
    __shared__ int s_carry;
    int t = threadIdx.x, lane = t & 31, w = t >> 5;
    if (t == 0) s_carry = 0;
    __syncthreads();
    const int NT = (NN + 1023) / 1024;   // 49
    for (int tile = 0; tile < NT; tile++) {
        int idx = tile * 1024 + t;
        int v = (idx < NN) ? cnt[idx] : 0;
        int xs = v;
#pragma unroll
        for (int o = 1; o < 32; o <<= 1) {
            int y = __shfl_up_sync(0xffffffffu, xs, o);
            if (lane >= o) xs += y;
        }
        if (lane == 31) wsum[w] = xs;
        __syncthreads();
        if (w == 0) {
            int s = wsum[lane];
#pragma unroll
            for (int o = 1; o < 32; o <<= 1) {
                int y = __shfl_up_sync(0xffffffffu, s, o);
                if (lane >= o) s += y;
            }
            wsum[lane] = s;
        }
        __syncthreads();
        int base = s_carry + (w > 0 ? wsum[w - 1] : 0);
        int excl = base + xs - v;
        if (idx < NN) { rowptr[idx] = excl; woff[idx] = excl; }
        __syncthreads();
        if (t == 0) s_carry += wsum[31];
        __syncthreads();
    }
    if (t == 0) rowptr[NN] = s_carry;
}

__global__ void scatter_kernel(const int* __restrict__ src, const int* __restrict__ dst,
                               const float* __restrict__ w, int* __restrict__ woff,
                               long long* __restrict__ esw) {
    int e = blockIdx.x * 256 + threadIdx.x;
    if (e >= NE) return;
    int d = dst[e];
    int pos = atomicAdd(&woff[d], 1);
    unsigned long long pk =
        ((unsigned long long)__float_as_uint(w[e]) << 32) | (unsigned)src[e];
    esw[pos] = (long long)pk;
}

// CSR spmm: warp per dst row, fp16 sup in, fp16 h out, fp32 fused column stats
__global__ __launch_bounds__(256) void spmm_csr(const long long* __restrict__ esw,
                                                const int* __restrict__ rowptr,
                                                const __half* __restrict__ sup,
                                                __half* __restrict__ h,
                                                float* __restrict__ stats) {
    int w = threadIdx.x >> 5, lane = threadIdx.x & 31;
    int row = blockIdx.x * 8 + w;
    const uint2* sup2 = reinterpret_cast<const uint2*>(sup);  // 4 halfs per uint2
    float4 acc = make_float4(0.f, 0.f, 0.f, 0.f);
    int b = rowptr[row], e = rowptr[row + 1];
    int i = b;
    for (; i + 1 < e; i += 2) {
        long long p0 = __ldg(&esw[i]);
        long long p1 = __ldg(&esw[i + 1]);
        int s0 = (int)((unsigned long long)p0 & 0xffffffffull);
        int s1 = (int)((unsigned long long)p1 & 0xffffffffull);
        float w0 = __uint_as_float((unsigned)((unsigned long long)p0 >> 32));
        float w1 = __uint_as_float((unsigned)((unsigned long long)p1 >> 32));
        uint2 r0 = __ldg(&sup2[(size_t)s0 * 32 + lane]);
        uint2 r1 = __ldg(&sup2[(size_t)s1 * 32 + lane]);
        float2 a01 = __half22float2(*reinterpret_cast<__half2*>(&r0.x));
        float2 a23 = __half22float2(*reinterpret_cast<__half2*>(&r0.y));
        float2 b01 = __half22float2(*reinterpret_cast<__half2*>(&r1.x));
        float2 b23 = __half22float2(*reinterpret_cast<__half2*>(&r1.y));
        acc.x += w0 * a01.x; acc.y += w0 * a01.y; acc.z += w0 * a23.x; acc.w += w0 * a23.y;
        acc.x += w1 * b01.x; acc.y += w1 * b01.y; acc.z += w1 * b23.x; acc.w += w1 * b23.y;
    }
    if (i < e) {
        long long p0 = __ldg(&esw[i]);
        int s0 = (int)((unsigned long long)p0 & 0xffffffffull);
        float w0 = __uint_as_float((unsigned)((unsigned long long)p0 >> 32));
        uint2 r0 = __ldg(&sup2[(size_t)s0 * 32 + lane]);
        float2 a01 = __half22float2(*reinterpret_cast<__half2*>(&r0.x));
        float2 a23 = __half22float2(*reinterpret_cast<__half2*>(&r0.y));
        acc.x += w0 * a01.x; acc.y += w0 * a01.y; acc.z += w0 * a23.x; acc.w += w0 * a23.y;
    }
    // store h as fp16 (4 halfs per lane)
    uint2 o;
    *reinterpret_cast<__half2*>(&o.x) = __floats2half2_rn(acc.x, acc.y);
    *reinterpret_cast<__half2*>(&o.y) = __floats2half2_rn(acc.z, acc.w);
    reinterpret_cast<uint2*>(h)[(size_t)row * 32 + lane] = o;

    // fused BN stats from exact fp32 accumulators
    __shared__ float sm_s[8][128];
    __shared__ float sm_q[8][128];
    float* ps = &sm_s[w][lane * 4];
    float* pq = &sm_q[w][lane * 4];
    ps[0] = acc.x; ps[1] = acc.y; ps[2] = acc.z; ps[3] = acc.w;
    pq[0] = acc.x * acc.x; pq[1] = acc.y * acc.y;
    pq[2] = acc.z * acc.z; pq[3] = acc.w * acc.w;
    __syncthreads();
    int t = threadIdx.x;
    if (t < 128) {
        float a = 0.f;
#pragma unroll
        for (int r = 0; r < 8; r++) a += sm_s[r][t];
        atomicAdd(&stats[t], a);
    } else {
        int c = t - 128;
        float a = 0.f;
#pragma unroll
        for (int r = 0; r < 8; r++) a += sm_q[r][c];
        atomicAdd(&stats[128 + c], a);
    }
}

// CSR spmm for 20-wide output (fp32), fused stats
__global__ __launch_bounds__(256) void spmm20_csr(const long long* __restrict__ esw,
                                                  const int* __restrict__ rowptr,
                                                  const float* __restrict__ sup,
                                                  float* __restrict__ h,
                                                  float* __restrict__ stats) {
    int w = threadIdx.x >> 5, lane = threadIdx.x & 31;
    int row = blockIdx.x * 8 + w;
    float acc = 0.f;
    int b = rowptr[row], e = rowptr[row + 1];
    for (int i = b; i < e; i++) {
        long long p0 = __ldg(&esw[i]);
        int s0 = (int)((unsigned long long)p0 & 0xffffffffull);
        float w0 = __uint_as_float((unsigned)((unsigned long long)p0 >> 32));
        if (lane < NO) acc += w0 * sup[(size_t)s0 * NO + lane];
    }
    if (lane < NO) h[(size_t)row * NO + lane] = acc;

    __shared__ float sm_s[8][NO];
    __shared__ float sm_q[8][NO];
    if (lane < NO) {
        sm_s[w][lane] = acc;
        sm_q[w][lane] = acc * acc;
    }
    __syncthreads();
    int t = threadIdx.x;
    if (t < NO) {
        float a = 0.f;
#pragma unroll
        for (int r = 0; r < 8; r++) a += sm_s[r][t];
        atomicAdd(&stats[t], a);
    } else if (t >= 32 && t < 32 + NO) {
        int c = t - 32;
        float a = 0.f;
#pragma unroll
        for (int r = 0; r < 8; r++) a += sm_q[r][c];
        atomicAdd(&stats[128 + c], a);
    }
}

// ---------------- other kernels ----------------

__global__ void gather_kernel(const int* __restrict__ verts,
                              const float* __restrict__ emb,
                              float* __restrict__ x) {
    int idx = blockIdx.x * blockDim.x + threadIdx.x;
    if (idx >= NN * 32) return;
    int row = idx >> 5, q = idx & 31;
    reinterpret_cast<float4*>(x)[idx] =
        reinterpret_cast<const float4*>(emb)[(size_t)verts[row] * 32 + q];
}

// C[NN,20] = A[NN,128] @ W[128,20] — warp per row, row read once
__global__ __launch_bounds__(256) void gemm_out_w(const float* __restrict__ A,
                                                  const float* __restrict__ W,
                                                  float* __restrict__ C) {
    __shared__ float Ws[128 * NO];
    for (int l = threadIdx.x; l < 128 * NO; l += 256) Ws[l] = W[l];
    __syncthreads();
    int w = threadIdx.x >> 5, lane = threadIdx.x & 31;
    int row = blockIdx.x * 8 + w;
    float4 a = reinterpret_cast<const float4*>(A)[(size_t)row * 32 + lane];
    float acc[NO];
    const float* w0 = &Ws[(4 * lane + 0) * NO];
    const float* w1 = &Ws[(4 * lane + 1) * NO];
    const float* w2 = &Ws[(4 * lane + 2) * NO];
    const float* w3 = &Ws[(4 * lane + 3) * NO];
#pragma unroll
    for (int c = 0; c < NO; c++)
        acc[c] = a.x * w0[c] + a.y * w1[c] + a.z * w2[c] + a.w * w3[c];
#pragma unroll
    for (int o = 16; o; o >>= 1)
#pragma unroll
        for (int c = 0; c < NO; c++)
            acc[c] += __shfl_xor_sync(0xffffffffu, acc[c], o);
    if (lane < NO) C[(size_t)row * NO + lane] = acc[lane];
}

// fused BN+relu+mask reduce
__global__ void maskreduce_f(const float* __restrict__ h20, const int* __restrict__ verts,
                             const float* __restrict__ mask_w,
                             const float* __restrict__ stats,
                             const float* __restrict__ gamma, const float* __restrict__ beta,
                             float* __restrict__ acc) {
    int gw = (blockIdx.x * blockDim.x + threadIdx.x) >> 5;
    int lane = threadIdx.x & 31;
    int nwarps = (gridDim.x * blockDim.x) >> 5;
    float sc = 0.f, sh = 0.f;
    if (lane < NO) {
        float m = stats[lane] * (1.f / NN);
        float var = stats[128 + lane] * (1.f / NN) - m * m;
        sc = rsqrtf(var + BN_EPS) * gamma[lane];
        sh = beta[lane] - m * sc;
    }
    float a = 0.f;
    for (int r = gw; r < NN; r += nwarps) {
        float mw = mask_w[verts[r]];
        if (lane < NO) {
            float hn = fmaxf(fmaf(h20[(size_t)r * NO + lane], sc, sh), 0.f);
            a += mw * hn;
        }
    }
    if (lane < NO) atomicAdd(&acc[lane], a);
}

__global__ void finalize(const float* __restrict__ acc, const float* __restrict__ mask_b,
                         float* __restrict__ out) {
    int o = threadIdx.x;
    if (o < NO) out[o] = 1.f / (1.f + expf(-(acc[o] + mask_b[o])));
}

// ---------------- one-time host resources ----------------
struct HostRes {
    cudaStream_t s2;
    cudaEvent_t evRoot;
    cudaEvent_t evSort[7], evSpmm[7];
    HostRes() {
        cudaStreamCreateWithFlags(&s2, cudaStreamNonBlocking);
        cudaEventCreateWithFlags(&evRoot, cudaEventDisableTiming);
        for (int i = 0; i < 7; i++) {
            cudaEventCreateWithFlags(&evSort[i], cudaEventDisableTiming);
            cudaEventCreateWithFlags(&evSpmm[i], cudaEventDisableTiming);
        }
        cudaFuncSetAttribute(dual_gemm, cudaFuncAttributeMaxDynamicSharedMemorySize, GEMM_DYN_SMEM);
        cudaFuncSetAttribute(gate_gemm2, cudaFuncAttributeMaxDynamicSharedMemorySize, GEMM_DYN_SMEM);
    }
};
static HostRes g_res;

// ---------------- launch ----------------
extern "C" void kernel_launch(void* const* d_in, const int* in_sizes, int n_in,
                              void* d_out, int out_size) {
    const int*   vertices    = (const int*)d_in[0];
    const int*   edge_index  = (const int*)d_in[1];   // [7,2,NE]
    const float* edge_weight = (const float*)d_in[2]; // [7,NE]
    const float* emb         = (const float*)d_in[3];
    const float* w_h         = (const float*)d_in[4]; // [6,128,128]
    const float* w_out       = (const float*)d_in[6]; // [128,20]
    const float* bng         = (const float*)d_in[8];
    const float* bnb         = (const float*)d_in[9];
    const float* bng_o       = (const float*)d_in[10];
    const float* bnb_o       = (const float*)d_in[11];
    const float* te_wl       = (const float*)d_in[12];
    const float* te_wc       = (const float*)d_in[13];
    const float* te_b        = (const float*)d_in[14];
    const float* mask_w      = (const float*)d_in[15];
    const float* mask_b      = (const float*)d_in[16];
    float* out = (float*)d_out;

    float *x, *sup20, *h20, *stats, *acc;
    __half *sup, *h, *gl;
    long long *esw0, *esw1;
    int *rp0, *rp1, *cnt, *woff;
    cudaGetSymbolAddress((void**)&x,     g_x);
    cudaGetSymbolAddress((void**)&sup,   g_sup);
    cudaGetSymbolAddress((void**)&h,     g_h);
    cudaGetSymbolAddress((void**)&gl,    g_gl);
    cudaGetSymbolAddress((void**)&sup20, g_sup20);
    cudaGetSymbolAddress((void**)&h20,   g_h20);
    cudaGetSymbolAddress((void**)&stats, g_stats);
    cudaGetSymbolAddress((void**)&acc,   g_acc);
    cudaGetSymbolAddress((void**)&esw0,  g_esw);
    esw1 = esw0 + NE;
    cudaGetSymbolAddress((void**)&rp0,   g_rowptr);
    rp1 = rp0 + (NN + 1);
    cudaGetSymbolAddress((void**)&cnt,   g_cnt);
    cudaGetSymbolAddress((void**)&woff,  g_woff);

    long long* eswS[2] = {esw0, esw1};
    int* rpS[2] = {rp0, rp1};

    cudaStream_t s2 = g_res.s2;
    const int TC_BLOCKS = (NN + 127) / 128;   // 391
    const int EB = (NE + 255) / 256;

    auto do_sort = [&](int L, cudaStream_t st) {
        const int* src = edge_index + (size_t)L * 2 * NE;
        const int* dst = src + NE;
        const float* ew = edge_weight + (size_t)L * NE;
        cudaMemsetAsync(cnt, 0, NN * sizeof(int), st);
        hist_kernel<<<(NE / 4 + 255) / 256, 256, 0, st>>>(dst, cnt);
        exscan_kernel<<<1, 1024, 0, st>>>(cnt, rpS[L & 1], woff);
        scatter_kernel<<<EB, 256, 0, st>>>(src, dst, ew, woff, eswS[L & 1]);
        cudaEventRecord(g_res.evSort[L], st);
    };

    // ---- fork point: side stream branches off the capture stream ----
    cudaEventRecord(g_res.evRoot, 0);
    cudaStreamWaitEvent(s2, g_res.evRoot, 0);

    // prologue: sort layers 0 and 1 on s2
    do_sort(0, s2);
    do_sort(1, s2);

    cudaMemsetAsync(stats, 0, 7 * 256 * sizeof(float));
    cudaMemsetAsync(acc, 0, 32 * sizeof(float));
    gather_kernel<<<(NN * 32 + 255) / 256, 256>>>(vertices, emb, x);

    for (int i = 0; i < NLH; i++) {
        int j = (i + 5) % 6;  // faithful to reference's (i-1) % (L-1)

        // sort layer i+1 one iteration ahead (slot (i+1)&1 last read by spmm i-1)
        if (i >= 1) {
            cudaStreamWaitEvent(s2, g_res.evSpmm[i - 1], 0);
            do_sort(i + 1, s2);
        }

        // main: dual gemm (sup + gl, fp16) -> spmm_csr(+stats) -> fused BN+gate gemm
        dual_gemm<<<dim3(TC_BLOCKS, 2), 256, GEMM_DYN_SMEM>>>(
            x, w_h + (size_t)i * DD * DD, te_wl + (size_t)j * DD * DD, sup, gl);
        cudaStreamWaitEvent(0, g_res.evSort[i], 0);
        spmm_csr<<<NN / 8, 256>>>(eswS[i & 1], rpS[i & 1], sup, h, stats + i * 256);
        cudaEventRecord(g_res.evSpmm[i], 0);
        gate_gemm2<<<TC_BLOCKS, 256, GEMM_DYN_SMEM>>>(x, h,
                                                      te_wc + (size_t)j * DD * DD,
                                                      gl, te_b + j * DD,
                                                      stats + i * 256,
                                                      bng + i * DD, bnb + i * DD);
    }

    // output layer (i = 6), sorted edges in slot 6&1 = 0
    {
        gemm_out_w<<<NN / 8, 256>>>(x, w_out, sup20);
        cudaStreamWaitEvent(0, g_res.evSort[6], 0);
        spmm20_csr<<<NN / 8, 256>>>(eswS[0], rpS[0], sup20, h20, stats + 6 * 256);
        maskreduce_f<<<200, 256>>>(h20, vertices, mask_w, stats + 6 * 256,
                                   bng_o, bnb_o, acc);
    }

    finalize<<<1, 32>>>(acc, mask_b, out);
}

// round 12
// speedup vs baseline: 1.7752x; 1.0045x over previous
#include <cuda_runtime.h>
#include <cuda_fp16.h>
#include <math.h>

#define NN 50000      // nodes
#define NE 800000     // edges per layer
#define DD 128        // feature dim
#define NO 20         // output dim
#define NLH 6         // hidden (gated) layers
#define BN_EPS 1e-5f

// ---------------- scratch (static device globals; no allocation) ----------------
__device__ __align__(16) float  g_x[NN * DD];
__device__ __align__(16) __half g_sup[NN * DD];
__device__ __align__(16) __half g_h[NN * DD];
__device__ __align__(16) __half g_gl[NN * DD];
__device__ __align__(16) float  g_sup20[NN * NO];
__device__ __align__(16) float  g_h20[NN * NO];
__device__ float g_stats[7 * 256];   // per-layer {sum[128] | sumsq[128]} slots
__device__ float g_acc[32];
// CSR double-buffer (sorted edges, packed {w:int(src)} 8B)
__device__ __align__(16) long long g_esw[2][NE];
__device__ int g_rowptr[2][NN + 1];
__device__ int g_cnt[NN];
__device__ int g_woff[NN];

// ---------------- tf32 helpers ----------------
__device__ __forceinline__ unsigned f2tf(float f) {
    unsigned u;
    asm("cvt.rna.tf32.f32 %0, %1;" : "=r"(u) : "f"(f));
    return u;
}

#define AS_STRIDE 36    // 128 rows x 32 cols A tile, padded (conflict-free)
#define WS_STRIDE 136   // 32 rows x 128 cols W tile, padded (conflict-free)
#define STAGE_U32 (128 * AS_STRIDE + 32 * WS_STRIDE)   // 8960 u32 per stage
#define GEMM_DYN_SMEM (2 * STAGE_U32 * 4)              // 71680 bytes

// fp32-A chunk prefetch
__device__ __forceinline__ void ldg_chunk_f(const float* __restrict__ A,
                                            const float* __restrict__ W,
                                            int row0, int kc, int tid,
                                            float4 va[4], float4 vw[4]) {
#pragma unroll
    for (int t = 0; t < 4; t++) {
        int e = tid + 256 * t;
        int r = e >> 3, q = e & 7;
        int gr = row0 + r;
        va[t] = (gr < NN)
            ? __ldg(&reinterpret_cast<const float4*>(A)[(size_t)gr * 32 + kc * 8 + q])
            : make_float4(0.f, 0.f, 0.f, 0.f);
        int k = e >> 5, q2 = e & 31;
        vw[t] = __ldg(&reinterpret_cast<const float4*>(W)[(size_t)(kc * 32 + k) * 32 + q2]);
    }
}

// fp16-A chunk prefetch (dequantize to float)
__device__ __forceinline__ void ldg_chunk_h(const __half* __restrict__ A,
                                            const float* __restrict__ W,
                                            int row0, int kc, int tid,
                                            float4 va[4], float4 vw[4]) {
#pragma unroll
    for (int t = 0; t < 4; t++) {
        int e = tid + 256 * t;
        int r = e >> 3, q = e & 7;
        int gr = row0 + r;
        if (gr < NN) {
            uint2 raw = __ldg(reinterpret_cast<const uint2*>(
                A + ((size_t)gr * 128 + kc * 32 + q * 4)));
            float2 f01 = __half22float2(*reinterpret_cast<__half2*>(&raw.x));
            float2 f23 = __half22float2(*reinterpret_cast<__half2*>(&raw.y));
            va[t] = make_float4(f01.x, f01.y, f23.x, f23.y);
        } else {
            va[t] = make_float4(0.f, 0.f, 0.f, 0.f);
        }
        int k = e >> 5, q2 = e & 31;
        vw[t] = __ldg(&reinterpret_cast<const float4*>(W)[(size_t)(kc * 32 + k) * 32 + q2]);
    }
}

__device__ __forceinline__ void sts_chunk(const float4 va[4], const float4 vw[4],
                                          unsigned* As, unsigned* Ws, int tid, int kc,
                                          const float* scale, const float* shift) {
#pragma unroll
    for (int t = 0; t < 4; t++) {
        int e = tid + 256 * t;
        int r = e >> 3, q = e & 7;
        float4 v = va[t];
        if (scale) {
            int c = kc * 32 + q * 4;
            v.x = fmaxf(fmaf(v.x, scale[c + 0], shift[c + 0]), 0.f);
            v.y = fmaxf(fmaf(v.y, scale[c + 1], shift[c + 1]), 0.f);
            v.z = fmaxf(fmaf(v.z, scale[c + 2], shift[c + 2]), 0.f);
            v.w = fmaxf(fmaf(v.w, scale[c + 3], shift[c + 3]), 0.f);
        }
        unsigned* p = As + r * AS_STRIDE + q * 4;
        p[0] = f2tf(v.x); p[1] = f2tf(v.y); p[2] = f2tf(v.z); p[3] = f2tf(v.w);
        int k = e >> 5, q2 = e & 31;
        float4 w = vw[t];
        unsigned* pw = Ws + k * WS_STRIDE + q2 * 4;
        pw[0] = f2tf(w.x); pw[1] = f2tf(w.y); pw[2] = f2tf(w.z); pw[3] = f2tf(w.w);
    }
}

__device__ __forceinline__ void mma_chunk(const unsigned* As, const unsigned* Ws,
                                          float acc[4][4][4],
                                          int warp_m, int warp_n, int lane) {
    int g = lane >> 2, c = lane & 3;
#pragma unroll
    for (int kk = 0; kk < 4; kk++) {
        unsigned a[4][4];
#pragma unroll
        for (int mi = 0; mi < 4; mi++) {
            const unsigned* base = As + (warp_m * 64 + mi * 16 + g) * AS_STRIDE + kk * 8 + c;
            a[mi][0] = base[0];
            a[mi][1] = base[8 * AS_STRIDE];
            a[mi][2] = base[4];
            a[mi][3] = base[8 * AS_STRIDE + 4];
        }
        unsigned b[4][2];
#pragma unroll
        for (int nj = 0; nj < 4; nj++) {
            const unsigned* base = Ws + (kk * 8 + c) * WS_STRIDE + warp_n * 32 + nj * 8 + g;
            b[nj][0] = base[0];
            b[nj][1] = base[4 * WS_STRIDE];
        }
#pragma unroll
        for (int mi = 0; mi < 4; mi++)
#pragma unroll
            for (int nj = 0; nj < 4; nj++) {
                asm volatile(
                    "mma.sync.aligned.m16n8k8.row.col.f32.tf32.tf32.f32 "
                    "{%0,%1,%2,%3}, {%4,%5,%6,%7}, {%8,%9}, {%0,%1,%2,%3};\n"
                    : "+f"(acc[mi][nj][0]), "+f"(acc[mi][nj][1]),
                      "+f"(acc[mi][nj][2]), "+f"(acc[mi][nj][3])
                    : "r"(a[mi][0]), "r"(a[mi][1]), "r"(a[mi][2]), "r"(a[mi][3]),
                      "r"(b[nj][0]), "r"(b[nj][1]));
            }
    }
}

// fp32-A double-buffered main loop
__device__ __forceinline__ void gemm_main_f(const float* __restrict__ A,
                                            const float* __restrict__ W,
                                            int row0, int tid, int warp_m, int warp_n,
                                            int lane, float acc[4][4][4],
                                            unsigned* dyn) {
    unsigned* As[2] = {dyn, dyn + STAGE_U32};
    unsigned* Ws[2] = {dyn + 128 * AS_STRIDE, dyn + STAGE_U32 + 128 * AS_STRIDE};
    float4 va[4], vw[4];
    ldg_chunk_f(A, W, row0, 0, tid, va, vw);
    sts_chunk(va, vw, As[0], Ws[0], tid, 0, nullptr, nullptr);
    __syncthreads();
#pragma unroll
    for (int kc = 0; kc < 4; kc++) {
        if (kc < 3) ldg_chunk_f(A, W, row0, kc + 1, tid, va, vw);
        mma_chunk(As[kc & 1], Ws[kc & 1], acc, warp_m, warp_n, lane);
        if (kc < 3) {
            sts_chunk(va, vw, As[(kc + 1) & 1], Ws[(kc + 1) & 1], tid, kc + 1,
                      nullptr, nullptr);
            __syncthreads();
        }
    }
}

// fp16-A (+ BN/ReLU normalize) double-buffered main loop
__device__ __forceinline__ void gemm_main_h(const __half* __restrict__ A,
                                            const float* __restrict__ W,
                                            int row0, int tid, int warp_m, int warp_n,
                                            int lane, float acc[4][4][4],
                                            unsigned* dyn,
                                            const float* scale, const float* shift) {
    unsigned* As[2] = {dyn, dyn + STAGE_U32};
    unsigned* Ws[2] = {dyn + 128 * AS_STRIDE, dyn + STAGE_U32 + 128 * AS_STRIDE};
    float4 va[4], vw[4];
    ldg_chunk_h(A, W, row0, 0, tid, va, vw);
    sts_chunk(va, vw, As[0], Ws[0], tid, 0, scale, shift);
    __syncthreads();
#pragma unroll
    for (int kc = 0; kc < 4; kc++) {
        if (kc < 3) ldg_chunk_h(A, W, row0, kc + 1, tid, va, vw);
        mma_chunk(As[kc & 1], Ws[kc & 1], acc, warp_m, warp_n, lane);
        if (kc < 3) {
            sts_chunk(va, vw, As[(kc + 1) & 1], Ws[(kc + 1) & 1], tid, kc + 1,
                      scale, shift);
            __syncthreads();
        }
    }
}

// C(fp16)[NN,128] = A(fp32)[NN,128] @ W[128,128]
__global__ __launch_bounds__(256) void gemm_f2h(const float* __restrict__ A,
                                                const float* __restrict__ W,
                                                __half* __restrict__ C) {
    extern __shared__ unsigned dyn[];
    int tid = threadIdx.x, wid = tid >> 5, lane = tid & 31;
    int warp_m = wid & 1, warp_n = wid >> 1;
    int row0 = blockIdx.x * 128;

    float acc[4][4][4];
#pragma unroll
    for (int mi = 0; mi < 4; mi++)
#pragma unroll
        for (int nj = 0; nj < 4; nj++)
#pragma unroll
            for (int q = 0; q < 4; q++) acc[mi][nj][q] = 0.f;

    gemm_main_f(A, W, row0, tid, warp_m, warp_n, lane, acc, dyn);

    int g = lane >> 2, c = lane & 3;
#pragma unroll
    for (int mi = 0; mi < 4; mi++) {
        int r0 = row0 + warp_m * 64 + mi * 16 + g;
#pragma unroll
        for (int nj = 0; nj < 4; nj++) {
            int col = warp_n * 32 + nj * 8 + c * 2;
            if (r0 < NN)
                *reinterpret_cast<__half2*>(C + (size_t)r0 * 128 + col) =
                    __floats2half2_rn(acc[mi][nj][0], acc[mi][nj][1]);
            if (r0 + 8 < NN)
                *reinterpret_cast<__half2*>(C + (size_t)(r0 + 8) * 128 + col) =
                    __floats2half2_rn(acc[mi][nj][2], acc[mi][nj][3]);
        }
    }
}

// Fused: hn = relu(BN(h)); acc = hn @ wc; g = sigmoid(acc + gl + teb); x = g*hn + (1-g)*x
__global__ __launch_bounds__(256) void gate_gemm2(float* __restrict__ x,
                                                  const __half* __restrict__ h,
                                                  const float* __restrict__ wc,
                                                  const __half* __restrict__ gl,
                                                  const float* __restrict__ teb,
                                                  const float* __restrict__ stats,
                                                  const float* __restrict__ gamma,
                                                  const float* __restrict__ beta) {
    extern __shared__ unsigned dyn[];
    __shared__ float s_scale[128], s_shift[128];
    int tid = threadIdx.x, wid = tid >> 5, lane = tid & 31;
    int warp_m = wid & 1, warp_n = wid >> 1;
    int row0 = blockIdx.x * 128;

    if (tid < 128) {
        float m = stats[tid] * (1.f / NN);
        float var = stats[128 + tid] * (1.f / NN) - m * m;
        float sc = rsqrtf(var + BN_EPS) * gamma[tid];
        s_scale[tid] = sc;
        s_shift[tid] = beta[tid] - m * sc;
    }
    __syncthreads();

    float acc[4][4][4];
#pragma unroll
    for (int mi = 0; mi < 4; mi++)
#pragma unroll
        for (int nj = 0; nj < 4; nj++)
#pragma unroll
            for (int q = 0; q < 4; q++) acc[mi][nj][q] = 0.f;

    gemm_main_h(h, wc, row0, tid, warp_m, warp_n, lane, acc, dyn, s_scale, s_shift);

    int g = lane >> 2, c = lane & 3;
#pragma unroll
    for (int mi = 0; mi < 4; mi++) {
#pragma unroll
        for (int nj = 0; nj < 4; nj++) {
            int col = warp_n * 32 + nj * 8 + c * 2;
            float b0 = teb[col], b1 = teb[col + 1];
            float sc0 = s_scale[col], sc1 = s_scale[col + 1];
            float sh0 = s_shift[col], sh1 = s_shift[col + 1];
#pragma unroll
            for (int half = 0; half < 2; half++) {
                int r = row0 + warp_m * 64 + mi * 16 + g + half * 8;
                if (r < NN) {
                    size_t o = (size_t)r * 128 + col;
                    float2 hv = __half22float2(
                        *reinterpret_cast<const __half2*>(h + o));
                    float2 gv = __half22float2(
                        *reinterpret_cast<const __half2*>(gl + o));
                    float2 xv = *reinterpret_cast<const float2*>(x + o);
                    float hn0 = fmaxf(fmaf(hv.x, sc0, sh0), 0.f);
                    float hn1 = fmaxf(fmaf(hv.y, sc1, sh1), 0.f);
                    float ga = 1.f / (1.f + expf(-(acc[mi][nj][half * 2 + 0] + gv.x + b0)));
                    float gb = 1.f / (1.f + expf(-(acc[mi][nj][half * 2 + 1] + gv.y + b1)));
                    float2 r2;
                    r2.x = ga * hn0 + (1.f - ga) * xv.x;
                    r2.y = gb * hn1 + (1.f - gb) * xv.y;
                    *reinterpret_cast<float2*>(x + o) = r2;
                }
            }
        }
    }
}

// ---------------- CSR build ----------------

__global__ void hist_kernel(const int* __restrict__ dst, int* __restrict__ cnt) {
    int e4 = blockIdx.x * 256 + threadIdx.x;
    if (e4 >= NE / 4) return;
    int4 d = __ldg(&reinterpret_cast<const int4*>(dst)[e4]);
    atomicAdd(&cnt[d.x], 1);
    atomicAdd(&cnt[d.y], 1);
    atomicAdd(&cnt[d.z], 1);
    atomicAdd(&cnt[d.w], 1);
}

__global__ __launch_bounds__(1024) void exscan_kernel(const int* __restrict__ cnt,
                                                      int* __restrict__ rowptr,
                                                      int* __restrict__ woff) {
    __shared__ int wsum[32];
    __shared__ int s_carry;
    int t = threadIdx.x, lane = t & 31, w = t >> 5;
    if (t == 0) s_carry = 0;
    __syncthreads();
    const int NT = (NN + 1023) / 1024;   // 49
    for (int tile = 0; tile < NT; tile++) {
        int idx = tile * 1024 + t;
        int v = (idx < NN) ? cnt[idx] : 0;
        int xs = v;
#pragma unroll
        for (int o = 1; o < 32; o <<= 1) {
            int y = __shfl_up_sync(0xffffffffu, xs, o);
            if (lane >= o) xs += y;
        }
        if (lane == 31) wsum[w] = xs;
        __syncthreads();
        if (w == 0) {
            int s = wsum[lane];
#pragma unroll
            for (int o = 1; o < 32; o <<= 1) {
                int y = __shfl_up_sync(0xffffffffu, s, o);
                if (lane >= o) s += y;
            }
            wsum[lane] = s;
        }
        __syncthreads();
        int base = s_carry + (w > 0 ? wsum[w - 1] : 0);
        int excl = base + xs - v;
        if (idx < NN) { rowptr[idx] = excl; woff[idx] = excl; }
        __syncthreads();
        if (t == 0) s_carry += wsum[31];
        __syncthreads();
    }
    if (t == 0) rowptr[NN] = s_carry;
}

__global__ void scatter_kernel(const int* __restrict__ src, const int* __restrict__ dst,
                               const float* __restrict__ w, int* __restrict__ woff,
                               long long* __restrict__ esw) {
    int e = blockIdx.x * 256 + threadIdx.x;
    if (e >= NE) return;
    int d = dst[e];
    int pos = atomicAdd(&woff[d], 1);
    unsigned long long pk =
        ((unsigned long long)__float_as_uint(w[e]) << 32) | (unsigned)src[e];
    esw[pos] = (long long)pk;
}

// CSR spmm: warp per dst row, fp16 sup in, fp16 h out, fp32 fused column stats
__global__ __launch_bounds__(256) void spmm_csr(const long long* __restrict__ esw,
                                                const int* __restrict__ rowptr,
                                                const __half* __restrict__ sup,
                                                __half* __restrict__ h,
                                                float* __restrict__ stats) {
    int w = threadIdx.x >> 5, lane = threadIdx.x & 31;
    int row = blockIdx.x * 8 + w;
    const uint2* sup2 = reinterpret_cast<const uint2*>(sup);  // 4 halfs per uint2
    float4 acc = make_float4(0.f, 0.f, 0.f, 0.f);
    int b = rowptr[row], e = rowptr[row + 1];
    int i = b;
    // 4-wide unroll for MLP
    for (; i + 3 < e; i += 4) {
        long long p0 = __ldg(&esw[i]);
        long long p1 = __ldg(&esw[i + 1]);
        long long p2 = __ldg(&esw[i + 2]);
        long long p3 = __ldg(&esw[i + 3]);
        int s0 = (int)((unsigned long long)p0 & 0xffffffffull);
        int s1 = (int)((unsigned long long)p1 & 0xffffffffull);
        int s2 = (int)((unsigned long long)p2 & 0xffffffffull);
        int s3 = (int)((unsigned long long)p3 & 0xffffffffull);
        float w0 = __uint_as_float((unsigned)((unsigned long long)p0 >> 32));
        float w1 = __uint_as_float((unsigned)((unsigned long long)p1 >> 32));
        float w2 = __uint_as_float((unsigned)((unsigned long long)p2 >> 32));
        float w3 = __uint_as_float((unsigned)((unsigned long long)p3 >> 32));
        uint2 r0 = __ldg(&sup2[(size_t)s0 * 32 + lane]);
        uint2 r1 = __ldg(&sup2[(size_t)s1 * 32 + lane]);
        uint2 r2 = __ldg(&sup2[(size_t)s2 * 32 + lane]);
        uint2 r3 = __ldg(&sup2[(size_t)s3 * 32 + lane]);
        float2 a01 = __half22float2(*reinterpret_cast<__half2*>(&r0.x));
        float2 a23 = __half22float2(*reinterpret_cast<__half2*>(&r0.y));
        acc.x += w0 * a01.x; acc.y += w0 * a01.y; acc.z += w0 * a23.x; acc.w += w0 * a23.y;
        float2 b01 = __half22float2(*reinterpret_cast<__half2*>(&r1.x));
        float2 b23 = __half22float2(*reinterpret_cast<__half2*>(&r1.y));
        acc.x += w1 * b01.x; acc.y += w1 * b01.y; acc.z += w1 * b23.x; acc.w += w1 * b23.y;
        float2 c01 = __half22float2(*reinterpret_cast<__half2*>(&r2.x));
        float2 c23 = __half22float2(*reinterpret_cast<__half2*>(&r2.y));
        acc.x += w2 * c01.x; acc.y += w2 * c01.y; acc.z += w2 * c23.x; acc.w += w2 * c23.y;
        float2 d01 = __half22float2(*reinterpret_cast<__half2*>(&r3.x));
        float2 d23 = __half22float2(*reinterpret_cast<__half2*>(&r3.y));
        acc.x += w3 * d01.x; acc.y += w3 * d01.y; acc.z += w3 * d23.x; acc.w += w3 * d23.y;
    }
    for (; i < e; i++) {
        long long p0 = __ldg(&esw[i]);
        int s0 = (int)((unsigned long long)p0 & 0xffffffffull);
        float w0 = __uint_as_float((unsigned)((unsigned long long)p0 >> 32));
        uint2 r0 = __ldg(&sup2[(size_t)s0 * 32 + lane]);
        float2 a01 = __half22float2(*reinterpret_cast<__half2*>(&r0.x));
        float2 a23 = __half22float2(*reinterpret_cast<__half2*>(&r0.y));
        acc.x += w0 * a01.x; acc.y += w0 * a01.y; acc.z += w0 * a23.x; acc.w += w0 * a23.y;
    }
    // store h as fp16 (4 halfs per lane)
    uint2 o;
    *reinterpret_cast<__half2*>(&o.x) = __floats2half2_rn(acc.x, acc.y);
    *reinterpret_cast<__half2*>(&o.y) = __floats2half2_rn(acc.z, acc.w);
    reinterpret_cast<uint2*>(h)[(size_t)row * 32 + lane] = o;

    // fused BN stats from exact fp32 accumulators
    __shared__ float sm_s[8][128];
    __shared__ float sm_q[8][128];
    float* ps = &sm_s[w][lane * 4];
    float* pq = &sm_q[w][lane * 4];
    ps[0] = acc.x; ps[1] = acc.y; ps[2] = acc.z; ps[3] = acc.w;
    pq[0] = acc.x * acc.x; pq[1] = acc.y * acc.y;
    pq[2] = acc.z * acc.z; pq[3] = acc.w * acc.w;
    __syncthreads();
    int t = threadIdx.x;
    if (t < 128) {
        float a = 0.f;
#pragma unroll
        for (int r = 0; r < 8; r++) a += sm_s[r][t];
        atomicAdd(&stats[t], a);
    } else {
        int c = t - 128;
        float a = 0.f;
#pragma unroll
        for (int r = 0; r < 8; r++) a += sm_q[r][c];
        atomicAdd(&stats[128 + c], a);
    }
}

// CSR spmm for 20-wide output (fp32), fused stats
__global__ __launch_bounds__(256) void spmm20_csr(const long long* __restrict__ esw,
                                                  const int* __restrict__ rowptr,
                                                  const float* __restrict__ sup,
                                                  float* __restrict__ h,
                                                  float* __restrict__ stats) {
    int w = threadIdx.x >> 5, lane = threadIdx.x & 31;
    int row = blockIdx.x * 8 + w;
    float acc = 0.f;
    int b = rowptr[row], e = rowptr[row + 1];
    for (int i = b; i < e; i++) {
        long long p0 = __ldg(&esw[i]);
        int s0 = (int)((unsigned long long)p0 & 0xffffffffull);
        float w0 = __uint_as_float((unsigned)((unsigned long long)p0 >> 32));
        if (lane < NO) acc += w0 * sup[(size_t)s0 * NO + lane];
    }
    if (lane < NO) h[(size_t)row * NO + lane] = acc;

    __shared__ float sm_s[8][NO];
    __shared__ float sm_q[8][NO];
    if (lane < NO) {
        sm_s[w][lane] = acc;
        sm_q[w][lane] = acc * acc;
    }
    __syncthreads();
    int t = threadIdx.x;
    if (t < NO) {
        float a = 0.f;
#pragma unroll
        for (int r = 0; r < 8; r++) a += sm_s[r][t];
        atomicAdd(&stats[t], a);
    } else if (t >= 32 && t < 32 + NO) {
        int c = t - 32;
        float a = 0.f;
#pragma unroll
        for (int r = 0; r < 8; r++) a += sm_q[r][c];
        atomicAdd(&stats[128 + c], a);
    }
}

// ---------------- other kernels ----------------

__global__ void gather_kernel(const int* __restrict__ verts,
                              const float* __restrict__ emb,
                              float* __restrict__ x) {
    int idx = blockIdx.x * blockDim.x + threadIdx.x;
    if (idx >= NN * 32) return;
    int row = idx >> 5, q = idx & 31;
    reinterpret_cast<float4*>(x)[idx] =
        reinterpret_cast<const float4*>(emb)[(size_t)verts[row] * 32 + q];
}

// C[NN,20] = A[NN,128] @ W[128,20] — warp per row, row read once
__global__ __launch_bounds__(256) void gemm_out_w(const float* __restrict__ A,
                                                  const float* __restrict__ W,
                                                  float* __restrict__ C) {
    __shared__ float Ws[128 * NO];
    for (int l = threadIdx.x; l < 128 * NO; l += 256) Ws[l] = W[l];
    __syncthreads();
    int w = threadIdx.x >> 5, lane = threadIdx.x & 31;
    int row = blockIdx.x * 8 + w;
    float4 a = reinterpret_cast<const float4*>(A)[(size_t)row * 32 + lane];
    float acc[NO];
    const float* w0 = &Ws[(4 * lane + 0) * NO];
    const float* w1 = &Ws[(4 * lane + 1) * NO];
    const float* w2 = &Ws[(4 * lane + 2) * NO];
    const float* w3 = &Ws[(4 * lane + 3) * NO];
#pragma unroll
    for (int c = 0; c < NO; c++)
        acc[c] = a.x * w0[c] + a.y * w1[c] + a.z * w2[c] + a.w * w3[c];
#pragma unroll
    for (int o = 16; o; o >>= 1)
#pragma unroll
        for (int c = 0; c < NO; c++)
            acc[c] += __shfl_xor_sync(0xffffffffu, acc[c], o);
    if (lane < NO) C[(size_t)row * NO + lane] = acc[lane];
}

// fused BN+relu+mask reduce
__global__ void maskreduce_f(const float* __restrict__ h20, const int* __restrict__ verts,
                             const float* __restrict__ mask_w,
                             const float* __restrict__ stats,
                             const float* __restrict__ gamma, const float* __restrict__ beta,
                             float* __restrict__ acc) {
    int gw = (blockIdx.x * blockDim.x + threadIdx.x) >> 5;
    int lane = threadIdx.x & 31;
    int nwarps = (gridDim.x * blockDim.x) >> 5;
    float sc = 0.f, sh = 0.f;
    if (lane < NO) {
        float m = stats[lane] * (1.f / NN);
        float var = stats[128 + lane] * (1.f / NN) - m * m;
        sc = rsqrtf(var + BN_EPS) * gamma[lane];
        sh = beta[lane] - m * sc;
    }
    float a = 0.f;
    for (int r = gw; r < NN; r += nwarps) {
        float mw = mask_w[verts[r]];
        if (lane < NO) {
            float hn = fmaxf(fmaf(h20[(size_t)r * NO + lane], sc, sh), 0.f);
            a += mw * hn;
        }
    }
    if (lane < NO) atomicAdd(&acc[lane], a);
}

__global__ void finalize(const float* __restrict__ acc, const float* __restrict__ mask_b,
                         float* __restrict__ out) {
    int o = threadIdx.x;
    if (o < NO) out[o] = 1.f / (1.f + expf(-(acc[o] + mask_b[o])));
}

// ---------------- one-time host resources ----------------
struct HostRes {
    cudaStream_t s1, s2;
    cudaEvent_t evRoot, evX, evGL;
    cudaEvent_t evSort[7], evSpmm[7];
    HostRes() {
        cudaStreamCreateWithFlags(&s1, cudaStreamNonBlocking);
        cudaStreamCreateWithFlags(&s2, cudaStreamNonBlocking);
        cudaEventCreateWithFlags(&evRoot, cudaEventDisableTiming);
        cudaEventCreateWithFlags(&evX, cudaEventDisableTiming);
        cudaEventCreateWithFlags(&evGL, cudaEventDisableTiming);
        for (int i = 0; i < 7; i++) {
            cudaEventCreateWithFlags(&evSort[i], cudaEventDisableTiming);
            cudaEventCreateWithFlags(&evSpmm[i], cudaEventDisableTiming);
        }
        cudaFuncSetAttribute(gemm_f2h, cudaFuncAttributeMaxDynamicSharedMemorySize, GEMM_DYN_SMEM);
        cudaFuncSetAttribute(gate_gemm2, cudaFuncAttributeMaxDynamicSharedMemorySize, GEMM_DYN_SMEM);
    }
};
static HostRes g_res;

// ---------------- launch ----------------
extern "C" void kernel_launch(void* const* d_in, const int* in_sizes, int n_in,
                              void* d_out, int out_size) {
    const int*   vertices    = (const int*)d_in[0];
    const int*   edge_index  = (const int*)d_in[1];   // [7,2,NE]
    const float* edge_weight = (const float*)d_in[2]; // [7,NE]
    const float* emb         = (const float*)d_in[3];
    const float* w_h         = (const float*)d_in[4]; // [6,128,128]
    const float* w_out       = (const float*)d_in[6]; // [128,20]
    const float* bng         = (const float*)d_in[8];
    const float* bnb         = (const float*)d_in[9];
    const float* bng_o       = (const float*)d_in[10];
    const float* bnb_o       = (const float*)d_in[11];
    const float* te_wl       = (const float*)d_in[12];
    const float* te_wc       = (const float*)d_in[13];
    const float* te_b        = (const float*)d_in[14];
    const float* mask_w      = (const float*)d_in[15];
    const float* mask_b      = (const float*)d_in[16];
    float* out = (float*)d_out;

    float *x, *sup20, *h20, *stats, *acc;
    __half *sup, *h, *gl;
    long long *esw0, *esw1;
    int *rp0, *rp1, *cnt, *woff;
    cudaGetSymbolAddress((void**)&x,     g_x);
    cudaGetSymbolAddress((void**)&sup,   g_sup);
    cudaGetSymbolAddress((void**)&h,     g_h);
    cudaGetSymbolAddress((void**)&gl,    g_gl);
    cudaGetSymbolAddress((void**)&sup20, g_sup20);
    cudaGetSymbolAddress((void**)&h20,   g_h20);
    cudaGetSymbolAddress((void**)&stats, g_stats);
    cudaGetSymbolAddress((void**)&acc,   g_acc);
    cudaGetSymbolAddress((void**)&esw0,  g_esw);
    esw1 = esw0 + NE;
    cudaGetSymbolAddress((void**)&rp0,   g_rowptr);
    rp1 = rp0 + (NN + 1);
    cudaGetSymbolAddress((void**)&cnt,   g_cnt);
    cudaGetSymbolAddress((void**)&woff,  g_woff);

    long long* eswS[2] = {esw0, esw1};
    int* rpS[2] = {rp0, rp1};

    cudaStream_t s1 = g_res.s1, s2 = g_res.s2;
    const int TC_BLOCKS = (NN + 127) / 128;   // 391
    const int EB = (NE + 255) / 256;

    auto do_sort = [&](int L, cudaStream_t st) {
        const int* src = edge_index + (size_t)L * 2 * NE;
        const int* dst = src + NE;
        const float* ew = edge_weight + (size_t)L * NE;
        cudaMemsetAsync(cnt, 0, NN * sizeof(int), st);
        hist_kernel<<<(NE / 4 + 255) / 256, 256, 0, st>>>(dst, cnt);
        exscan_kernel<<<1, 1024, 0, st>>>(cnt, rpS[L & 1], woff);
        scatter_kernel<<<EB, 256, 0, st>>>(src, dst, ew, woff, eswS[L & 1]);
        cudaEventRecord(g_res.evSort[L], st);
    };

    // ---- fork point: side streams branch off the capture stream ----
    cudaEventRecord(g_res.evRoot, 0);
    cudaStreamWaitEvent(s2, g_res.evRoot, 0);

    // prologue: sort layers 0 and 1 on s2
    do_sort(0, s2);
    do_sort(1, s2);

    cudaMemsetAsync(stats, 0, 7 * 256 * sizeof(float));
    cudaMemsetAsync(acc, 0, 32 * sizeof(float));
    gather_kernel<<<(NN * 32 + 255) / 256, 256>>>(vertices, emb, x);
    cudaEventRecord(g_res.evX, 0);

    for (int i = 0; i < NLH; i++) {
        int j = (i + 5) % 6;  // faithful to reference's (i-1) % (L-1)

        // sort layer i+1 one iteration ahead (slot (i+1)&1 last read by spmm i-1)
        if (i >= 1) {
            cudaStreamWaitEvent(s2, g_res.evSpmm[i - 1], 0);
            do_sort(i + 1, s2);
        }

        // side stream s1: gl = x @ te_wl (hidden under sup-gemm + spmm)
        cudaStreamWaitEvent(s1, g_res.evX, 0);
        gemm_f2h<<<TC_BLOCKS, 256, GEMM_DYN_SMEM, s1>>>(
            x, te_wl + (size_t)j * DD * DD, gl);
        cudaEventRecord(g_res.evGL, s1);

        // main: sup gemm -> spmm_csr(+stats) -> fused BN+gate gemm
        gemm_f2h<<<TC_BLOCKS, 256, GEMM_DYN_SMEM>>>(
            x, w_h + (size_t)i * DD * DD, sup);
        cudaStreamWaitEvent(0, g_res.evSort[i], 0);
        spmm_csr<<<NN / 8, 256>>>(eswS[i & 1], rpS[i & 1], sup, h, stats + i * 256);
        cudaEventRecord(g_res.evSpmm[i], 0);
        cudaStreamWaitEvent(0, g_res.evGL, 0);
        gate_gemm2<<<TC_BLOCKS, 256, GEMM_DYN_SMEM>>>(x, h,
                                                      te_wc + (size_t)j * DD * DD,
                                                      gl, te_b + j * DD,
                                                      stats + i * 256,
                                                      bng + i * DD, bnb + i * DD);
        cudaEventRecord(g_res.evX, 0);
    }

    // output layer (i = 6), sorted edges in slot 6&1 = 0
    {
        gemm_out_w<<<NN / 8, 256>>>(x, w_out, sup20);
        cudaStreamWaitEvent(0, g_res.evSort[6], 0);
        spmm20_csr<<<NN / 8, 256>>>(eswS[0], rpS[0], sup20, h20, stats + 6 * 256);
        maskreduce_f<<<200, 256>>>(h20, vertices, mask_w, stats + 6 * 256,
                                   bng_o, bnb_o, acc);
    }

    finalize<<<1, 32>>>(acc, mask_b, out);
}

// round 15
// speedup vs baseline: 1.8565x; 1.0458x over previous
#include <cuda_runtime.h>
#include <cuda_fp16.h>
#include <math.h>

#define NN 50000      // nodes
#define NE 800000     // edges per layer
#define DD 128        // feature dim
#define NO 20         // output dim
#define NLH 6         // hidden (gated) layers
#define BN_EPS 1e-5f

// ---------------- scratch (static device globals; no allocation) ----------------
__device__ __align__(16) float  g_x[NN * DD];
__device__ __align__(16) __half g_sup[NN * DD];
__device__ __align__(16) __half g_h[NN * DD];
__device__ __align__(16) float  g_gl[NN * DD];
__device__ __align__(16) float  g_sup20[NN * NO];
__device__ __align__(16) float  g_h20[NN * NO];
__device__ float g_stats[7 * 256];   // per-layer {sum[128] | sumsq[128]} slots
__device__ float g_acc[32];
// CSR double-buffer (sorted edges, packed {w:int(src)} 8B)
__device__ __align__(16) long long g_esw[2][NE];
__device__ int g_rowptr[2][NN + 1];
__device__ int g_cnt[NN];
__device__ int g_woff[NN];

// ---------------- fp16 GEMM tiles ----------------
// A tile: 128 rows x 32 k halfs = 128 x 16 u32(half2), stride 20 (banks 20g+c distinct)
// W tile: 32 k x 128 n halfs, packed k-pairs: 16 x 128 u32(half2{k,k+1}), stride 136
#define AS2 20
#define WS2 136
#define STAGE2 (128 * AS2 + 16 * WS2)   // 4736 u32 per stage
#define DYN2 (2 * STAGE2 * 4)           // 37888 bytes

__device__ __forceinline__ unsigned packh2(float a, float b) {
    __half2 h = __floats2half2_rn(a, b);
    return *reinterpret_cast<unsigned*>(&h);
}

// prefetch one BK=32 chunk from fp32 A + fp32 W
__device__ __forceinline__ void ldg2_f(const float* __restrict__ A,
                                       const float* __restrict__ W,
                                       int row0, int kc, int tid,
                                       float4 va[4], float4 vw0[2], float4 vw1[2]) {
#pragma unroll
    for (int t = 0; t < 4; t++) {
        int e = tid + 256 * t;
        int r = e >> 3, q = e & 7;
        int gr = row0 + r;
        va[t] = (gr < NN)
            ? __ldg(&reinterpret_cast<const float4*>(A)[(size_t)gr * 32 + kc * 8 + q])
            : make_float4(0.f, 0.f, 0.f, 0.f);
    }
#pragma unroll
    for (int t = 0; t < 2; t++) {
        int e = tid + 256 * t;
        int k2r = e >> 5, nq = e & 31;
        const float* Wr = W + (size_t)(kc * 32 + 2 * k2r) * 128 + 4 * nq;
        vw0[t] = __ldg(reinterpret_cast<const float4*>(Wr));
        vw1[t] = __ldg(reinterpret_cast<const float4*>(Wr + 128));
    }
}

// prefetch one BK=32 chunk from fp16 A + fp32 W
__device__ __forceinline__ void ldg2_h(const __half* __restrict__ A,
                                       const float* __restrict__ W,
                                       int row0, int kc, int tid,
                                       float4 va[4], float4 vw0[2], float4 vw1[2]) {
#pragma unroll
    for (int t = 0; t < 4; t++) {
        int e = tid + 256 * t;
        int r = e >> 3, q = e & 7;
        int gr = row0 + r;
        if (gr < NN) {
            uint2 raw = __ldg(&reinterpret_cast<const uint2*>(A)[(size_t)gr * 32 + kc * 8 + q]);
            float2 f01 = __half22float2(*reinterpret_cast<__half2*>(&raw.x));
            float2 f23 = __half22float2(*reinterpret_cast<__half2*>(&raw.y));
            va[t] = make_float4(f01.x, f01.y, f23.x, f23.y);
        } else {
            va[t] = make_float4(0.f, 0.f, 0.f, 0.f);
        }
    }
#pragma unroll
    for (int t = 0; t < 2; t++) {
        int e = tid + 256 * t;
        int k2r = e >> 5, nq = e & 31;
        const float* Wr = W + (size_t)(kc * 32 + 2 * k2r) * 128 + 4 * nq;
        vw0[t] = __ldg(reinterpret_cast<const float4*>(Wr));
        vw1[t] = __ldg(reinterpret_cast<const float4*>(Wr + 128));
    }
}

// cvt + store prefetched chunk to smem; optional BN+ReLU on A values
__device__ __forceinline__ void sts2(const float4 va[4], const float4 vw0[2],
                                     const float4 vw1[2],
                                     unsigned* As, unsigned* Ws, int tid, int kc,
                                     const float* scale, const float* shift) {
#pragma unroll
    for (int t = 0; t < 4; t++) {
        int e = tid + 256 * t;
        int r = e >> 3, q = e & 7;
        float4 v = va[t];
        if (scale) {
            int c = kc * 32 + q * 4;
            v.x = fmaxf(fmaf(v.x, scale[c + 0], shift[c + 0]), 0.f);
            v.y = fmaxf(fmaf(v.y, scale[c + 1], shift[c + 1]), 0.f);
            v.z = fmaxf(fmaf(v.z, scale[c + 2], shift[c + 2]), 0.f);
            v.w = fmaxf(fmaf(v.w, scale[c + 3], shift[c + 3]), 0.f);
        }
        As[r * AS2 + 2 * q]     = packh2(v.x, v.y);
        As[r * AS2 + 2 * q + 1] = packh2(v.z, v.w);
    }
#pragma unroll
    for (int t = 0; t < 2; t++) {
        int e = tid + 256 * t;
        int k2r = e >> 5, nq = e & 31;
        unsigned* p = Ws + k2r * WS2 + 4 * nq;
        p[0] = packh2(vw0[t].x, vw1[t].x);
        p[1] = packh2(vw0[t].y, vw1[t].y);
        p[2] = packh2(vw0[t].z, vw1[t].z);
        p[3] = packh2(vw0[t].w, vw1[t].w);
    }
}

// one BK=32 chunk: 2 x m16n8k16 f16 mma steps; warp tile 64x32
__device__ __forceinline__ void mma2_chunk(const unsigned* As, const unsigned* Ws,
                                           float acc[4][4][4],
                                           int warp_m, int warp_n, int lane) {
    int g = lane >> 2, c = lane & 3;
#pragma unroll
    for (int kk = 0; kk < 2; kk++) {
        unsigned a[4][4];
#pragma unroll
        for (int mi = 0; mi < 4; mi++) {
            const unsigned* base = As + (warp_m * 64 + mi * 16 + g) * AS2 + kk * 8 + c;
            a[mi][0] = base[0];
            a[mi][1] = base[8 * AS2];
            a[mi][2] = base[4];
            a[mi][3] = base[8 * AS2 + 4];
        }
        unsigned b[4][2];
#pragma unroll
        for (int nj = 0; nj < 4; nj++) {
            const unsigned* base = Ws + (kk * 8 + c) * WS2 + warp_n * 32 + nj * 8 + g;
            b[nj][0] = base[0];
            b[nj][1] = base[4 * WS2];
        }
#pragma unroll
        for (int mi = 0; mi < 4; mi++)
#pragma unroll
            for (int nj = 0; nj < 4; nj++) {
                asm volatile(
                    "mma.sync.aligned.m16n8k16.row.col.f32.f16.f16.f32 "
                    "{%0,%1,%2,%3}, {%4,%5,%6,%7}, {%8,%9}, {%0,%1,%2,%3};\n"
                    : "+f"(acc[mi][nj][0]), "+f"(acc[mi][nj][1]),
                      "+f"(acc[mi][nj][2]), "+f"(acc[mi][nj][3])
                    : "r"(a[mi][0]), "r"(a[mi][1]), "r"(a[mi][2]), "r"(a[mi][3]),
                      "r"(b[nj][0]), "r"(b[nj][1]));
            }
    }
}

// fp32-A double-buffered main loop
__device__ __forceinline__ void gemm16_main_f(const float* __restrict__ A,
                                              const float* __restrict__ W,
                                              int row0, int tid, int warp_m, int warp_n,
                                              int lane, float acc[4][4][4],
                                              unsigned* dyn) {
    unsigned* As[2] = {dyn, dyn + STAGE2};
    unsigned* Ws[2] = {dyn + 128 * AS2, dyn + STAGE2 + 128 * AS2};
    float4 va[4], vw0[2], vw1[2];
    ldg2_f(A, W, row0, 0, tid, va, vw0, vw1);
    sts2(va, vw0, vw1, As[0], Ws[0], tid, 0, nullptr, nullptr);
    __syncthreads();
#pragma unroll
    for (int kc = 0; kc < 4; kc++) {
        if (kc < 3) ldg2_f(A, W, row0, kc + 1, tid, va, vw0, vw1);
        mma2_chunk(As[kc & 1], Ws[kc & 1], acc, warp_m, warp_n, lane);
        if (kc < 3) {
            sts2(va, vw0, vw1, As[(kc + 1) & 1], Ws[(kc + 1) & 1], tid, kc + 1,
                 nullptr, nullptr);
            __syncthreads();
        }
    }
}

// fp16-A (+ BN/ReLU) double-buffered main loop
__device__ __forceinline__ void gemm16_main_h(const __half* __restrict__ A,
                                              const float* __restrict__ W,
                                              int row0, int tid, int warp_m, int warp_n,
                                              int lane, float acc[4][4][4],
                                              unsigned* dyn,
                                              const float* scale, const float* shift) {
    unsigned* As[2] = {dyn, dyn + STAGE2};
    unsigned* Ws[2] = {dyn + 128 * AS2, dyn + STAGE2 + 128 * AS2};
    float4 va[4], vw0[2], vw1[2];
    ldg2_h(A, W, row0, 0, tid, va, vw0, vw1);
    sts2(va, vw0, vw1, As[0], Ws[0], tid, 0, scale, shift);
    __syncthreads();
#pragma unroll
    for (int kc = 0; kc < 4; kc++) {
        if (kc < 3) ldg2_h(A, W, row0, kc + 1, tid, va, vw0, vw1);
        mma2_chunk(As[kc & 1], Ws[kc & 1], acc, warp_m, warp_n, lane);
        if (kc < 3) {
            sts2(va, vw0, vw1, As[(kc + 1) & 1], Ws[(kc + 1) & 1], tid, kc + 1,
                 scale, shift);
            __syncthreads();
        }
    }
}

// sup(fp16) = x(fp32) @ W
__global__ __launch_bounds__(256) void gemm_sup(const float* __restrict__ A,
                                                const float* __restrict__ W,
                                                __half* __restrict__ C) {
    extern __shared__ unsigned dyn[];
    int tid = threadIdx.x, wid = tid >> 5, lane = tid & 31;
    int warp_m = wid & 1, warp_n = wid >> 1;
    int row0 = blockIdx.x * 128;

    float acc[4][4][4];
#pragma unroll
    for (int mi = 0; mi < 4; mi++)
#pragma unroll
        for (int nj = 0; nj < 4; nj++)
#pragma unroll
            for (int q = 0; q < 4; q++) acc[mi][nj][q] = 0.f;

    gemm16_main_f(A, W, row0, tid, warp_m, warp_n, lane, acc, dyn);

    int g = lane >> 2, c = lane & 3;
#pragma unroll
    for (int mi = 0; mi < 4; mi++) {
        int r0 = row0 + warp_m * 64 + mi * 16 + g;
#pragma unroll
        for (int nj = 0; nj < 4; nj++) {
            int col = warp_n * 32 + nj * 8 + c * 2;
            if (r0 < NN)
                *reinterpret_cast<__half2*>(C + (size_t)r0 * 128 + col) =
                    __floats2half2_rn(acc[mi][nj][0], acc[mi][nj][1]);
            if (r0 + 8 < NN)
                *reinterpret_cast<__half2*>(C + (size_t)(r0 + 8) * 128 + col) =
                    __floats2half2_rn(acc[mi][nj][2], acc[mi][nj][3]);
        }
    }
}

// gl(fp32) = x(fp32) @ W
__global__ __launch_bounds__(256) void gemm_gl(const float* __restrict__ A,
                                               const float* __restrict__ W,
                                               float* __restrict__ C) {
    extern __shared__ unsigned dyn[];
    int tid = threadIdx.x, wid = tid >> 5, lane = tid & 31;
    int warp_m = wid & 1, warp_n = wid >> 1;
    int row0 = blockIdx.x * 128;

    float acc[4][4][4];
#pragma unroll
    for (int mi = 0; mi < 4; mi++)
#pragma unroll
        for (int nj = 0; nj < 4; nj++)
#pragma unroll
            for (int q = 0; q < 4; q++) acc[mi][nj][q] = 0.f;

    gemm16_main_f(A, W, row0, tid, warp_m, warp_n, lane, acc, dyn);

    int g = lane >> 2, c = lane & 3;
#pragma unroll
    for (int mi = 0; mi < 4; mi++) {
        int r0 = row0 + warp_m * 64 + mi * 16 + g;
#pragma unroll
        for (int nj = 0; nj < 4; nj++) {
            int col = warp_n * 32 + nj * 8 + c * 2;
            if (r0 < NN)
                *reinterpret_cast<float2*>(C + (size_t)r0 * 128 + col) =
                    make_float2(acc[mi][nj][0], acc[mi][nj][1]);
            if (r0 + 8 < NN)
                *reinterpret_cast<float2*>(C + (size_t)(r0 + 8) * 128 + col) =
                    make_float2(acc[mi][nj][2], acc[mi][nj][3]);
        }
    }
}

// Fused: hn = relu(BN(h)); acc = hn @ wc; g = sigmoid(acc + gl + teb); x = g*hn + (1-g)*x
__global__ __launch_bounds__(256) void gate_gemm2(float* __restrict__ x,
                                                  const __half* __restrict__ h,
                                                  const float* __restrict__ wc,
                                                  const float* __restrict__ gl,
                                                  const float* __restrict__ teb,
                                                  const float* __restrict__ stats,
                                                  const float* __restrict__ gamma,
                                                  const float* __restrict__ beta) {
    extern __shared__ unsigned dyn[];
    __shared__ float s_scale[128], s_shift[128];
    int tid = threadIdx.x, wid = tid >> 5, lane = tid & 31;
    int warp_m = wid & 1, warp_n = wid >> 1;
    int row0 = blockIdx.x * 128;

    if (tid < 128) {
        float m = stats[tid] * (1.f / NN);
        float var = stats[128 + tid] * (1.f / NN) - m * m;
        float sc = rsqrtf(var + BN_EPS) * gamma[tid];
        s_scale[tid] = sc;
        s_shift[tid] = beta[tid] - m * sc;
    }
    __syncthreads();

    float acc[4][4][4];
#pragma unroll
    for (int mi = 0; mi < 4; mi++)
#pragma unroll
        for (int nj = 0; nj < 4; nj++)
#pragma unroll
            for (int q = 0; q < 4; q++) acc[mi][nj][q] = 0.f;

    gemm16_main_h(h, wc, row0, tid, warp_m, warp_n, lane, acc, dyn, s_scale, s_shift);

    int g = lane >> 2, c = lane & 3;
#pragma unroll
    for (int mi = 0; mi < 4; mi++) {
#pragma unroll
        for (int nj = 0; nj < 4; nj++) {
            int col = warp_n * 32 + nj * 8 + c * 2;
            float b0 = teb[col], b1 = teb[col + 1];
            float sc0 = s_scale[col], sc1 = s_scale[col + 1];
            float sh0 = s_shift[col], sh1 = s_shift[col + 1];
#pragma unroll
            for (int half = 0; half < 2; half++) {
                int r = row0 + warp_m * 64 + mi * 16 + g + half * 8;
                if (r < NN) {
                    size_t o = (size_t)r * 128 + col;
                    float2 hv = __half22float2(
                        *reinterpret_cast<const __half2*>(h + o));
                    float2 gv = *reinterpret_cast<const float2*>(gl + o);
                    float2 xv = *reinterpret_cast<const float2*>(x + o);
                    float hn0 = fmaxf(fmaf(hv.x, sc0, sh0), 0.f);
                    float hn1 = fmaxf(fmaf(hv.y, sc1, sh1), 0.f);
                    float ga = 1.f / (1.f + expf(-(acc[mi][nj][half * 2 + 0] + gv.x + b0)));
                    float gb = 1.f / (1.f + expf(-(acc[mi][nj][half * 2 + 1] + gv.y + b1)));
                    float2 r2;
                    r2.x = ga * hn0 + (1.f - ga) * xv.x;
                    r2.y = gb * hn1 + (1.f - gb) * xv.y;
                    *reinterpret_cast<float2*>(x + o) = r2;
                }
            }
        }
    }
}

// ---------------- CSR build ----------------

__global__ void hist_kernel(const int* __restrict__ dst, int* __restrict__ cnt) {
    int e4 = blockIdx.x * 256 + threadIdx.x;
    if (e4 >= NE / 4) return;
    int4 d = __ldg(&reinterpret_cast<const int4*>(dst)[e4]);
    atomicAdd(&cnt[d.x], 1);
    atomicAdd(&cnt[d.y], 1);
    atomicAdd(&cnt[d.z], 1);
    atomicAdd(&cnt[d.w], 1);
}

__global__ __launch_bounds__(1024) void exscan_kernel(const int* __restrict__ cnt,
                                                      int* __restrict__ rowptr,
                                                      int* __restrict__ woff) {
    __shared__ int wsum[32];
    __shared__ int s_carry;
    int t = threadIdx.x, lane = t & 31, w = t >> 5;
    if (t == 0) s_carry = 0;
    __syncthreads();
    const int NT = (NN + 1023) / 1024;   // 49
    for (int tile = 0; tile < NT; tile++) {
        int idx = tile * 1024 + t;
        int v = (idx < NN) ? cnt[idx] : 0;
        int xs = v;
#pragma unroll
        for (int o = 1; o < 32; o <<= 1) {
            int y = __shfl_up_sync(0xffffffffu, xs, o);
            if (lane >= o) xs += y;
        }
        if (lane == 31) wsum[w] = xs;
        __syncthreads();
        if (w == 0) {
            int s = wsum[lane];
#pragma unroll
            for (int o = 1; o < 32; o <<= 1) {
                int y = __shfl_up_sync(0xffffffffu, s, o);
                if (lane >= o) s += y;
            }
            wsum[lane] = s;
        }
        __syncthreads();
        int base = s_carry + (w > 0 ? wsum[w - 1] : 0);
        int excl = base + xs - v;
        if (idx < NN) { rowptr[idx] = excl; woff[idx] = excl; }
        __syncthreads();
        if (t == 0) s_carry += wsum[31];
        __syncthreads();
    }
    if (t == 0) rowptr[NN] = s_carry;
}

__global__ void scatter_kernel(const int* __restrict__ src, const int* __restrict__ dst,
                               const float* __restrict__ w, int* __restrict__ woff,
                               long long* __restrict__ esw) {
    int e = blockIdx.x * 256 + threadIdx.x;
    if (e >= NE) return;
    int d = dst[e];
    int pos = atomicAdd(&woff[d], 1);
    unsigned long long pk =
        ((unsigned long long)__float_as_uint(w[e]) << 32) | (unsigned)src[e];
    esw[pos] = (long long)pk;
}

// CSR spmm: warp per dst row, fp16 sup in, fp16 h out, fp32 fused column stats
__global__ __launch_bounds__(256) void spmm_csr(const long long* __restrict__ esw,
                                                const int* __restrict__ rowptr,
                                                const __half* __restrict__ sup,
                                                __half* __restrict__ h,
                                                float* __restrict__ stats) {
    int w = threadIdx.x >> 5, lane = threadIdx.x & 31;
    int row = blockIdx.x * 8 + w;
    const uint2* sup2 = reinterpret_cast<const uint2*>(sup);  // 4 halfs per uint2
    float4 acc = make_float4(0.f, 0.f, 0.f, 0.f);
    int b = rowptr[row], e = rowptr[row + 1];
    int i = b;
    for (; i + 3 < e; i += 4) {
        long long p0 = __ldg(&esw[i]);
        long long p1 = __ldg(&esw[i + 1]);
        long long p2 = __ldg(&esw[i + 2]);
        long long p3 = __ldg(&esw[i + 3]);
        int s0 = (int)((unsigned long long)p0 & 0xffffffffull);
        int s1 = (int)((unsigned long long)p1 & 0xffffffffull);
        int s2 = (int)((unsigned long long)p2 & 0xffffffffull);
        int s3 = (int)((unsigned long long)p3 & 0xffffffffull);
        float w0 = __uint_as_float((unsigned)((unsigned long long)p0 >> 32));
        float w1 = __uint_as_float((unsigned)((unsigned long long)p1 >> 32));
        float w2 = __uint_as_float((unsigned)((unsigned long long)p2 >> 32));
        float w3 = __uint_as_float((unsigned)((unsigned long long)p3 >> 32));
        uint2 r0 = __ldg(&sup2[(size_t)s0 * 32 + lane]);
        uint2 r1 = __ldg(&sup2[(size_t)s1 * 32 + lane]);
        uint2 r2 = __ldg(&sup2[(size_t)s2 * 32 + lane]);
        uint2 r3 = __ldg(&sup2[(size_t)s3 * 32 + lane]);
        float2 a01 = __half22float2(*reinterpret_cast<__half2*>(&r0.x));
        float2 a23 = __half22float2(*reinterpret_cast<__half2*>(&r0.y));
        acc.x += w0 * a01.x; acc.y += w0 * a01.y; acc.z += w0 * a23.x; acc.w += w0 * a23.y;
        float2 b01 = __half22float2(*reinterpret_cast<__half2*>(&r1.x));
        float2 b23 = __half22float2(*reinterpret_cast<__half2*>(&r1.y));
        acc.x += w1 * b01.x; acc.y += w1 * b01.y; acc.z += w1 * b23.x; acc.w += w1 * b23.y;
        float2 c01 = __half22float2(*reinterpret_cast<__half2*>(&r2.x));
        float2 c23 = __half22float2(*reinterpret_cast<__half2*>(&r2.y));
        acc.x += w2 * c01.x; acc.y += w2 * c01.y; acc.z += w2 * c23.x; acc.w += w2 * c23.y;
        float2 d01 = __half22float2(*reinterpret_cast<__half2*>(&r3.x));
        float2 d23 = __half22float2(*reinterpret_cast<__half2*>(&r3.y));
        acc.x += w3 * d01.x; acc.y += w3 * d01.y; acc.z += w3 * d23.x; acc.w += w3 * d23.y;
    }
    for (; i < e; i++) {
        long long p0 = __ldg(&esw[i]);
        int s0 = (int)((unsigned long long)p0 & 0xffffffffull);
        float w0 = __uint_as_float((unsigned)((unsigned long long)p0 >> 32));
        uint2 r0 = __ldg(&sup2[(size_t)s0 * 32 + lane]);
        float2 a01 = __half22float2(*reinterpret_cast<__half2*>(&r0.x));
        float2 a23 = __half22float2(*reinterpret_cast<__half2*>(&r0.y));
        acc.x += w0 * a01.x; acc.y += w0 * a01.y; acc.z += w0 * a23.x; acc.w += w0 * a23.y;
    }
    uint2 o;
    *reinterpret_cast<__half2*>(&o.x) = __floats2half2_rn(acc.x, acc.y);
    *reinterpret_cast<__half2*>(&o.y) = __floats2half2_rn(acc.z, acc.w);
    reinterpret_cast<uint2*>(h)[(size_t)row * 32 + lane] = o;

    __shared__ float sm_s[8][128];
    __shared__ float sm_q[8][128];
    float* ps = &sm_s[w][lane * 4];
    float* pq = &sm_q[w][lane * 4];
    ps[0] = acc.x; ps[1] = acc.y; ps[2] = acc.z; ps[3] = acc.w;
    pq[0] = acc.x * acc.x; pq[1] = acc.y * acc.y;
    pq[2] = acc.z * acc.z; pq[3] = acc.w * acc.w;
    __syncthreads();
    int t = threadIdx.x;
    if (t < 128) {
        float a = 0.f;
#pragma unroll
        for (int r = 0; r < 8; r++) a += sm_s[r][t];
        atomicAdd(&stats[t], a);
    } else {
        int c = t - 128;
        float a = 0.f;
#pragma unroll
        for (int r = 0; r < 8; r++) a += sm_q[r][c];
        atomicAdd(&stats[128 + c], a);
    }
}

// CSR spmm for 20-wide output (fp32), fused stats
__global__ __launch_bounds__(256) void spmm20_csr(const long long* __restrict__ esw,
                                                  const int* __restrict__ rowptr,
                                                  const float* __restrict__ sup,
                                                  float* __restrict__ h,
                                                  float* __restrict__ stats) {
    int w = threadIdx.x >> 5, lane = threadIdx.x & 31;
    int row = blockIdx.x * 8 + w;
    float acc = 0.f;
    int b = rowptr[row], e = rowptr[row + 1];
    for (int i = b; i < e; i++) {
        long long p0 = __ldg(&esw[i]);
        int s0 = (int)((unsigned long long)p0 & 0xffffffffull);
        float w0 = __uint_as_float((unsigned)((unsigned long long)p0 >> 32));
        if (lane < NO) acc += w0 * sup[(size_t)s0 * NO + lane];
    }
    if (lane < NO) h[(size_t)row * NO + lane] = acc;

    __shared__ float sm_s[8][NO];
    __shared__ float sm_q[8][NO];
    if (lane < NO) {
        sm_s[w][lane] = acc;
        sm_q[w][lane] = acc * acc;
    }
    __syncthreads();
    int t = threadIdx.x;
    if (t < NO) {
        float a = 0.f;
#pragma unroll
        for (int r = 0; r < 8; r++) a += sm_s[r][t];
        atomicAdd(&stats[t], a);
    } else if (t >= 32 && t < 32 + NO) {
        int c = t - 32;
        float a = 0.f;
#pragma unroll
        for (int r = 0; r < 8; r++) a += sm_q[r][c];
        atomicAdd(&stats[128 + c], a);
    }
}

// ---------------- other kernels ----------------

__global__ void gather_kernel(const int* __restrict__ verts,
                              const float* __restrict__ emb,
                              float* __restrict__ x) {
    int idx = blockIdx.x * blockDim.x + threadIdx.x;
    if (idx >= NN * 32) return;
    int row = idx >> 5, q = idx & 31;
    reinterpret_cast<float4*>(x)[idx] =
        reinterpret_cast<const float4*>(emb)[(size_t)verts[row] * 32 + q];
}

// C[NN,20] = A[NN,128] @ W[128,20] — warp per row
__global__ __launch_bounds__(256) void gemm_out_w(const float* __restrict__ A,
                                                  const float* __restrict__ W,
                                                  float* __restrict__ C) {
    __shared__ float Ws[128 * NO];
    for (int l = threadIdx.x; l < 128 * NO; l += 256) Ws[l] = W[l];
    __syncthreads();
    int w = threadIdx.x >> 5, lane = threadIdx.x & 31;
    int row = blockIdx.x * 8 + w;
    float4 a = reinterpret_cast<const float4*>(A)[(size_t)row * 32 + lane];
    float acc[NO];
    const float* w0 = &Ws[(4 * lane + 0) * NO];
    const float* w1 = &Ws[(4 * lane + 1) * NO];
    const float* w2 = &Ws[(4 * lane + 2) * NO];
    const float* w3 = &Ws[(4 * lane + 3) * NO];
#pragma unroll
    for (int c = 0; c < NO; c++)
        acc[c] = a.x * w0[c] + a.y * w1[c] + a.z * w2[c] + a.w * w3[c];
#pragma unroll
    for (int o = 16; o; o >>= 1)
#pragma unroll
        for (int c = 0; c < NO; c++)
            acc[c] += __shfl_xor_sync(0xffffffffu, acc[c], o);
    if (lane < NO) C[(size_t)row * NO + lane] = acc[lane];
}

// fused BN+relu+mask reduce
__global__ void maskreduce_f(const float* __restrict__ h20, const int* __restrict__ verts,
                             const float* __restrict__ mask_w,
                             const float* __restrict__ stats,
                             const float* __restrict__ gamma, const float* __restrict__ beta,
                             float* __restrict__ acc) {
    int gw = (blockIdx.x * blockDim.x + threadIdx.x) >> 5;
    int lane = threadIdx.x & 31;
    int nwarps = (gridDim.x * blockDim.x) >> 5;
    float sc = 0.f, sh = 0.f;
    if (lane < NO) {
        float m = stats[lane] * (1.f / NN);
        float var = stats[128 + lane] * (1.f / NN) - m * m;
        sc = rsqrtf(var + BN_EPS) * gamma[lane];
        sh = beta[lane] - m * sc;
    }
    float a = 0.f;
    for (int r = gw; r < NN; r += nwarps) {
        float mw = mask_w[verts[r]];
        if (lane < NO) {
            float hn = fmaxf(fmaf(h20[(size_t)r * NO + lane], sc, sh), 0.f);
            a += mw * hn;
        }
    }
    if (lane < NO) atomicAdd(&acc[lane], a);
}

__global__ void finalize(const float* __restrict__ acc, const float* __restrict__ mask_b,
                         float* __restrict__ out) {
    int o = threadIdx.x;
    if (o < NO) out[o] = 1.f / (1.f + expf(-(acc[o] + mask_b[o])));
}

// ---------------- one-time host resources ----------------
struct HostRes {
    cudaStream_t s1, s2;
    cudaEvent_t evRoot, evX, evGL;
    cudaEvent_t evSort[7], evSpmm[7];
    HostRes() {
        cudaStreamCreateWithFlags(&s1, cudaStreamNonBlocking);
        cudaStreamCreateWithFlags(&s2, cudaStreamNonBlocking);
        cudaEventCreateWithFlags(&evRoot, cudaEventDisableTiming);
        cudaEventCreateWithFlags(&evX, cudaEventDisableTiming);
        cudaEventCreateWithFlags(&evGL, cudaEventDisableTiming);
        for (int i = 0; i < 7; i++) {
            cudaEventCreateWithFlags(&evSort[i], cudaEventDisableTiming);
            cudaEventCreateWithFlags(&evSpmm[i], cudaEventDisableTiming);
        }
        cudaFuncSetAttribute(gemm_sup, cudaFuncAttributeMaxDynamicSharedMemorySize, DYN2);
        cudaFuncSetAttribute(gemm_gl, cudaFuncAttributeMaxDynamicSharedMemorySize, DYN2);
        cudaFuncSetAttribute(gate_gemm2, cudaFuncAttributeMaxDynamicSharedMemorySize, DYN2);
    }
};
static HostRes g_res;

// ---------------- launch ----------------
extern "C" void kernel_launch(void* const* d_in, const int* in_sizes, int n_in,
                              void* d_out, int out_size) {
    const int*   vertices    = (const int*)d_in[0];
    const int*   edge_index  = (const int*)d_in[1];   // [7,2,NE]
    const float* edge_weight = (const float*)d_in[2]; // [7,NE]
    const float* emb         = (const float*)d_in[3];
    const float* w_h         = (const float*)d_in[4]; // [6,128,128]
    const float* w_out       = (const float*)d_in[6]; // [128,20]
    const float* bng         = (const float*)d_in[8];
    const float* bnb         = (const float*)d_in[9];
    const float* bng_o       = (const float*)d_in[10];
    const float* bnb_o       = (const float*)d_in[11];
    const float* te_wl       = (const float*)d_in[12];
    const float* te_wc       = (const float*)d_in[13];
    const float* te_b        = (const float*)d_in[14];
    const float* mask_w      = (const float*)d_in[15];
    const float* mask_b      = (const float*)d_in[16];
    float* out = (float*)d_out;

    float *x, *gl, *sup20, *h20, *stats, *acc;
    __half *sup, *h;
    long long *esw0, *esw1;
    int *rp0, *rp1, *cnt, *woff;
    cudaGetSymbolAddress((void**)&x,     g_x);
    cudaGetSymbolAddress((void**)&sup,   g_sup);
    cudaGetSymbolAddress((void**)&h,     g_h);
    cudaGetSymbolAddress((void**)&gl,    g_gl);
    cudaGetSymbolAddress((void**)&sup20, g_sup20);
    cudaGetSymbolAddress((void**)&h20,   g_h20);
    cudaGetSymbolAddress((void**)&stats, g_stats);
    cudaGetSymbolAddress((void**)&acc,   g_acc);
    cudaGetSymbolAddress((void**)&esw0,  g_esw);
    esw1 = esw0 + NE;
    cudaGetSymbolAddress((void**)&rp0,   g_rowptr);
    rp1 = rp0 + (NN + 1);
    cudaGetSymbolAddress((void**)&cnt,   g_cnt);
    cudaGetSymbolAddress((void**)&woff,  g_woff);

    long long* eswS[2] = {esw0, esw1};
    int* rpS[2] = {rp0, rp1};

    cudaStream_t s1 = g_res.s1, s2 = g_res.s2;
    const int TC_BLOCKS = (NN + 127) / 128;   // 391
    const int EB = (NE + 255) / 256;

    auto do_sort = [&](int L, cudaStream_t st) {
        const int* src = edge_index + (size_t)L * 2 * NE;
        const int* dst = src + NE;
        const float* ew = edge_weight + (size_t)L * NE;
        cudaMemsetAsync(cnt, 0, NN * sizeof(int), st);
        hist_kernel<<<(NE / 4 + 255) / 256, 256, 0, st>>>(dst, cnt);
        exscan_kernel<<<1, 1024, 0, st>>>(cnt, rpS[L & 1], woff);
        scatter_kernel<<<EB, 256, 0, st>>>(src, dst, ew, woff, eswS[L & 1]);
        cudaEventRecord(g_res.evSort[L], st);
    };

    // ---- fork point: side streams branch off the capture stream ----
    cudaEventRecord(g_res.evRoot, 0);
    cudaStreamWaitEvent(s2, g_res.evRoot, 0);

    // prologue: sort layers 0 and 1 on s2
    do_sort(0, s2);
    do_sort(1, s2);

    cudaMemsetAsync(stats, 0, 7 * 256 * sizeof(float));
    cudaMemsetAsync(acc, 0, 32 * sizeof(float));
    gather_kernel<<<(NN * 32 + 255) / 256, 256>>>(vertices, emb, x);
    cudaEventRecord(g_res.evX, 0);

    for (int i = 0; i < NLH; i++) {
        int j = (i + 5) % 6;  // faithful to reference's (i-1) % (L-1)

        // sort layer i+1 one iteration ahead
        if (i >= 1) {
            cudaStreamWaitEvent(s2, g_res.evSpmm[i - 1], 0);
            do_sort(i + 1, s2);
        }

        // side stream s1: gl = x @ te_wl (fp32 out)
        cudaStreamWaitEvent(s1, g_res.evX, 0);
        gemm_gl<<<TC_BLOCKS, 256, DYN2, s1>>>(x, te_wl + (size_t)j * DD * DD, gl);
        cudaEventRecord(g_res.evGL, s1);

        // main: sup gemm -> spmm_csr(+stats) -> fused BN+gate gemm
        gemm_sup<<<TC_BLOCKS, 256, DYN2>>>(x, w_h + (size_t)i * DD * DD, sup);
        cudaStreamWaitEvent(0, g_res.evSort[i], 0);
        spmm_csr<<<NN / 8, 256>>>(eswS[i & 1], rpS[i & 1], sup, h, stats + i * 256);
        cudaEventRecord(g_res.evSpmm[i], 0);
        cudaStreamWaitEvent(0, g_res.evGL, 0);
        gate_gemm2<<<TC_BLOCKS, 256, DYN2>>>(x, h,
                                             te_wc + (size_t)j * DD * DD,
                                             gl, te_b + j * DD,
                                             stats + i * 256,
                                             bng + i * DD, bnb + i * DD);
        cudaEventRecord(g_res.evX, 0);
    }

    // output layer (i = 6), sorted edges in slot 6&1 = 0
    {
        gemm_out_w<<<NN / 8, 256>>>(x, w_out, sup20);
        cudaStreamWaitEvent(0, g_res.evSort[6], 0);
        spmm20_csr<<<NN / 8, 256>>>(eswS[0], rpS[0], sup20, h20, stats + 6 * 256);
        maskreduce_f<<<200, 256>>>(h20, vertices, mask_w, stats + 6 * 256,
                                   bng_o, bnb_o, acc);
    }

    finalize<<<1, 32>>>(acc, mask_b, out);
}

// round 16
// speedup vs baseline: 1.9189x; 1.0336x over previous
#include <cuda_runtime.h>
#include <cuda_fp16.h>
#include <math.h>

#define NN 50000      // nodes
#define NE 800000     // edges per layer
#define DD 128        // feature dim
#define NO 20         // output dim
#define NLH 6         // hidden (gated) layers
#define BN_EPS 1e-5f

// ---------------- scratch (static device globals; no allocation) ----------------
__device__ __align__(16) float  g_x[NN * DD];
__device__ __align__(16) __half g_sup[NN * DD];
__device__ __align__(16) __half g_h[NN * DD];
__device__ __align__(16) float  g_gl[NN * DD];
__device__ __align__(16) float  g_sup20[NN * NO];
__device__ __align__(16) float  g_h20[NN * NO];
__device__ float g_stats[7 * 256];
__device__ float g_acc[32];
__device__ __align__(16) long long g_esw[2][NE];
__device__ int g_rowptr[2][NN + 1];
__device__ int g_cnt[NN];
__device__ int g_woff[NN];

// ---------------- fp16 GEMM tiles ----------------
#define AS2 20          // phase-1 A chunk: 128 rows x 16 u32, stride 20
#define WS2 136         // W chunk: 16 k-pairs x 128 n, stride 136
#define AFS 68          // full A tile: 128 rows x 64 u32, stride 68
#define DYN2 ((2 * (128 * AS2 + 16 * WS2)) * 4)                    // prologue gemms
#define DYN3 ((2 * 128 * AS2 + 2 * 16 * WS2 + 128 * AFS) * 4)      // fused layer

__device__ __forceinline__ unsigned packh2(float a, float b) {
    __half2 h = __floats2half2_rn(a, b);
    return *reinterpret_cast<unsigned*>(&h);
}

// W-only chunk prefetch / store
__device__ __forceinline__ void ldgW(const float* __restrict__ W, int kc, int tid,
                                     float4 vw0[2], float4 vw1[2]) {
#pragma unroll
    for (int t = 0; t < 2; t++) {
        int e = tid + 256 * t;
        int k2r = e >> 5, nq = e & 31;
        const float* Wr = W + (size_t)(kc * 32 + 2 * k2r) * 128 + 4 * nq;
        vw0[t] = __ldg(reinterpret_cast<const float4*>(Wr));
        vw1[t] = __ldg(reinterpret_cast<const float4*>(Wr + 128));
    }
}
__device__ __forceinline__ void stsW(const float4 vw0[2], const float4 vw1[2],
                                     unsigned* Ws, int tid) {
#pragma unroll
    for (int t = 0; t < 2; t++) {
        int e = tid + 256 * t;
        int k2r = e >> 5, nq = e & 31;
        unsigned* p = Ws + k2r * WS2 + 4 * nq;
        p[0] = packh2(vw0[t].x, vw1[t].x);
        p[1] = packh2(vw0[t].y, vw1[t].y);
        p[2] = packh2(vw0[t].z, vw1[t].z);
        p[3] = packh2(vw0[t].w, vw1[t].w);
    }
}

// A-chunk prefetch from fp32 / fp16 sources
__device__ __forceinline__ void ldgA_f(const float* __restrict__ A, int row0, int kc,
                                       int tid, float4 va[4]) {
#pragma unroll
    for (int t = 0; t < 4; t++) {
        int e = tid + 256 * t;
        int r = e >> 3, q = e & 7;
        int gr = row0 + r;
        va[t] = (gr < NN)
            ? __ldg(&reinterpret_cast<const float4*>(A)[(size_t)gr * 32 + kc * 8 + q])
            : make_float4(0.f, 0.f, 0.f, 0.f);
    }
}
__device__ __forceinline__ void ldgA_h(const __half* __restrict__ A, int row0, int kc,
                                       int tid, float4 va[4]) {
#pragma unroll
    for (int t = 0; t < 4; t++) {
        int e = tid + 256 * t;
        int r = e >> 3, q = e & 7;
        int gr = row0 + r;
        if (gr < NN) {
            uint2 raw = __ldg(&reinterpret_cast<const uint2*>(A)[(size_t)gr * 32 + kc * 8 + q]);
            float2 f01 = __half22float2(*reinterpret_cast<__half2*>(&raw.x));
            float2 f23 = __half22float2(*reinterpret_cast<__half2*>(&raw.y));
            va[t] = make_float4(f01.x, f01.y, f23.x, f23.y);
        } else {
            va[t] = make_float4(0.f, 0.f, 0.f, 0.f);
        }
    }
}
__device__ __forceinline__ void stsA(const float4 va[4], unsigned* As, int tid, int kc,
                                     const float* scale, const float* shift) {
#pragma unroll
    for (int t = 0; t < 4; t++) {
        int e = tid + 256 * t;
        int r = e >> 3, q = e & 7;
        float4 v = va[t];
        if (scale) {
            int c = kc * 32 + q * 4;
            v.x = fmaxf(fmaf(v.x, scale[c + 0], shift[c + 0]), 0.f);
            v.y = fmaxf(fmaf(v.y, scale[c + 1], shift[c + 1]), 0.f);
            v.z = fmaxf(fmaf(v.z, scale[c + 2], shift[c + 2]), 0.f);
            v.w = fmaxf(fmaf(v.w, scale[c + 3], shift[c + 3]), 0.f);
        }
        As[r * AS2 + 2 * q]     = packh2(v.x, v.y);
        As[r * AS2 + 2 * q + 1] = packh2(v.z, v.w);
    }
}

// one BK=32 chunk of m16n8k16 mma; A at given stride/base, warp tile 64x32
__device__ __forceinline__ void mma_chunk_g(const unsigned* As, int lda,
                                            const unsigned* Ws,
                                            float acc[4][4][4],
                                            int warp_m, int warp_n, int lane) {
    int g = lane >> 2, c = lane & 3;
#pragma unroll
    for (int kk = 0; kk < 2; kk++) {
        unsigned a[4][4];
#pragma unroll
        for (int mi = 0; mi < 4; mi++) {
            const unsigned* base = As + (warp_m * 64 + mi * 16 + g) * lda + kk * 8 + c;
            a[mi][0] = base[0];
            a[mi][1] = base[8 * lda];
            a[mi][2] = base[4];
            a[mi][3] = base[8 * lda + 4];
        }
        unsigned b[4][2];
#pragma unroll
        for (int nj = 0; nj < 4; nj++) {
            const unsigned* base = Ws + (kk * 8 + c) * WS2 + warp_n * 32 + nj * 8 + g;
            b[nj][0] = base[0];
            b[nj][1] = base[4 * WS2];
        }
#pragma unroll
        for (int mi = 0; mi < 4; mi++)
#pragma unroll
            for (int nj = 0; nj < 4; nj++) {
                asm volatile(
                    "mma.sync.aligned.m16n8k16.row.col.f32.f16.f16.f32 "
                    "{%0,%1,%2,%3}, {%4,%5,%6,%7}, {%8,%9}, {%0,%1,%2,%3};\n"
                    : "+f"(acc[mi][nj][0]), "+f"(acc[mi][nj][1]),
                      "+f"(acc[mi][nj][2]), "+f"(acc[mi][nj][3])
                    : "r"(a[mi][0]), "r"(a[mi][1]), "r"(a[mi][2]), "r"(a[mi][3]),
                      "r"(b[nj][0]), "r"(b[nj][1]));
            }
    }
}

#define ZERO_ACC(acc)                                   \
    _Pragma("unroll")                                   \
    for (int mi = 0; mi < 4; mi++)                      \
        _Pragma("unroll")                               \
        for (int nj = 0; nj < 4; nj++)                  \
            _Pragma("unroll")                           \
            for (int q = 0; q < 4; q++) acc[mi][nj][q] = 0.f;

// ---------------- prologue GEMMs (x fp32 -> sup fp16 / gl fp32) ----------------
__device__ __forceinline__ void gemm16_core_f(const float* __restrict__ A,
                                              const float* __restrict__ W,
                                              int row0, int tid, int warp_m, int warp_n,
                                              int lane, float acc[4][4][4],
                                              unsigned* dyn) {
    unsigned* As[2] = {dyn, dyn + 128 * AS2 + 16 * WS2};
    unsigned* Ws[2] = {dyn + 128 * AS2, dyn + 2 * 128 * AS2 + 16 * WS2};
    float4 va[4], vw0[2], vw1[2];
    ldgA_f(A, row0, 0, tid, va);
    ldgW(W, 0, tid, vw0, vw1);
    stsA(va, As[0], tid, 0, nullptr, nullptr);
    stsW(vw0, vw1, Ws[0], tid);
    __syncthreads();
#pragma unroll
    for (int kc = 0; kc < 4; kc++) {
        if (kc < 3) { ldgA_f(A, row0, kc + 1, tid, va); ldgW(W, kc + 1, tid, vw0, vw1); }
        mma_chunk_g(As[kc & 1], AS2, Ws[kc & 1], acc, warp_m, warp_n, lane);
        if (kc < 3) {
            stsA(va, As[(kc + 1) & 1], tid, kc + 1, nullptr, nullptr);
            stsW(vw0, vw1, Ws[(kc + 1) & 1], tid);
            __syncthreads();
        }
    }
}

__global__ __launch_bounds__(256) void gemm_sup(const float* __restrict__ A,
                                                const float* __restrict__ W,
                                                __half* __restrict__ C) {
    extern __shared__ unsigned dyn[];
    int tid = threadIdx.x, wid = tid >> 5, lane = tid & 31;
    int warp_m = wid & 1, warp_n = wid >> 1;
    int row0 = blockIdx.x * 128;
    float acc[4][4][4];
    ZERO_ACC(acc)
    gemm16_core_f(A, W, row0, tid, warp_m, warp_n, lane, acc, dyn);
    int g = lane >> 2, c = lane & 3;
#pragma unroll
    for (int mi = 0; mi < 4; mi++) {
        int r0 = row0 + warp_m * 64 + mi * 16 + g;
#pragma unroll
        for (int nj = 0; nj < 4; nj++) {
            int col = warp_n * 32 + nj * 8 + c * 2;
            if (r0 < NN)
                *reinterpret_cast<__half2*>(C + (size_t)r0 * 128 + col) =
                    __floats2half2_rn(acc[mi][nj][0], acc[mi][nj][1]);
            if (r0 + 8 < NN)
                *reinterpret_cast<__half2*>(C + (size_t)(r0 + 8) * 128 + col) =
                    __floats2half2_rn(acc[mi][nj][2], acc[mi][nj][3]);
        }
    }
}

__global__ __launch_bounds__(256) void gemm_gl(const float* __restrict__ A,
                                               const float* __restrict__ W,
                                               float* __restrict__ C) {
    extern __shared__ unsigned dyn[];
    int tid = threadIdx.x, wid = tid >> 5, lane = tid & 31;
    int warp_m = wid & 1, warp_n = wid >> 1;
    int row0 = blockIdx.x * 128;
    float acc[4][4][4];
    ZERO_ACC(acc)
    gemm16_core_f(A, W, row0, tid, warp_m, warp_n, lane, acc, dyn);
    int g = lane >> 2, c = lane & 3;
#pragma unroll
    for (int mi = 0; mi < 4; mi++) {
        int r0 = row0 + warp_m * 64 + mi * 16 + g;
#pragma unroll
        for (int nj = 0; nj < 4; nj++) {
            int col = warp_n * 32 + nj * 8 + c * 2;
            if (r0 < NN)
                *reinterpret_cast<float2*>(C + (size_t)r0 * 128 + col) =
                    make_float2(acc[mi][nj][0], acc[mi][nj][1]);
            if (r0 + 8 < NN)
                *reinterpret_cast<float2*>(C + (size_t)(r0 + 8) * 128 + col) =
                    make_float2(acc[mi][nj][2], acc[mi][nj][3]);
        }
    }
}

// ---------------- fused layer ----------------
// phase1: acc = relu(BN(h)) @ wc; gate: x_new = g*hn + (1-g)*x  (writes x, and
//         x_new fp16 into smem A_full)
// phase2: sup_next = x_new @ w_next   (fp16 out)
// phase3: gl_next  = x_new @ wl_next  (fp32 out)
__global__ __launch_bounds__(256) void fused_layer(
        float* __restrict__ x, const __half* __restrict__ h,
        const float* __restrict__ wc, const float* __restrict__ gl,
        const float* __restrict__ teb, const float* __restrict__ stats,
        const float* __restrict__ gamma, const float* __restrict__ beta,
        const float* __restrict__ w_next, const float* __restrict__ wl_next,
        __half* __restrict__ sup_next, float* __restrict__ gl_next, int has_next) {
    extern __shared__ unsigned dyn[];
    unsigned* Ach[2] = {dyn, dyn + 128 * AS2};
    unsigned* Wb[2]  = {dyn + 2 * 128 * AS2, dyn + 2 * 128 * AS2 + 16 * WS2};
    unsigned* Af     = dyn + 2 * 128 * AS2 + 2 * 16 * WS2;
    __shared__ float s_scale[128], s_shift[128];

    int tid = threadIdx.x, wid = tid >> 5, lane = tid & 31;
    int warp_m = wid & 1, warp_n = wid >> 1;
    int row0 = blockIdx.x * 128;
    int g = lane >> 2, c = lane & 3;

    if (tid < 128) {
        float m = stats[tid] * (1.f / NN);
        float var = stats[128 + tid] * (1.f / NN) - m * m;
        float sc = rsqrtf(var + BN_EPS) * gamma[tid];
        s_scale[tid] = sc;
        s_shift[tid] = beta[tid] - m * sc;
    }
    __syncthreads();

    float acc[4][4][4];
    ZERO_ACC(acc)

    // ---- phase 1: relu(BN(h)) @ wc (double-buffered chunks) ----
    {
        float4 va[4], vw0[2], vw1[2];
        ldgA_h(h, row0, 0, tid, va);
        ldgW(wc, 0, tid, vw0, vw1);
        stsA(va, Ach[0], tid, 0, s_scale, s_shift);
        stsW(vw0, vw1, Wb[0], tid);
        __syncthreads();
#pragma unroll
        for (int kc = 0; kc < 4; kc++) {
            if (kc < 3) { ldgA_h(h, row0, kc + 1, tid, va); ldgW(wc, kc + 1, tid, vw0, vw1); }
            mma_chunk_g(Ach[kc & 1], AS2, Wb[kc & 1], acc, warp_m, warp_n, lane);
            if (kc < 3) {
                stsA(va, Ach[(kc + 1) & 1], tid, kc + 1, s_scale, s_shift);
                stsW(vw0, vw1, Wb[(kc + 1) & 1], tid);
                __syncthreads();
            }
        }
    }

    // ---- gate epilogue: x_new -> gmem x (fp32) and Af (fp16) ----
#pragma unroll
    for (int mi = 0; mi < 4; mi++) {
#pragma unroll
        for (int nj = 0; nj < 4; nj++) {
            int col = warp_n * 32 + nj * 8 + c * 2;
            float b0 = teb[col], b1 = teb[col + 1];
            float sc0 = s_scale[col], sc1 = s_scale[col + 1];
            float sh0 = s_shift[col], sh1 = s_shift[col + 1];
#pragma unroll
            for (int half = 0; half < 2; half++) {
                int r = row0 + warp_m * 64 + mi * 16 + g + half * 8;
                int rl = warp_m * 64 + mi * 16 + g + half * 8;  // local row
                float2 r2 = make_float2(0.f, 0.f);
                if (r < NN) {
                    size_t o = (size_t)r * 128 + col;
                    float2 hv = __half22float2(*reinterpret_cast<const __half2*>(h + o));
                    float2 gv = *reinterpret_cast<const float2*>(gl + o);
                    float2 xv = *reinterpret_cast<const float2*>(x + o);
                    float hn0 = fmaxf(fmaf(hv.x, sc0, sh0), 0.f);
                    float hn1 = fmaxf(fmaf(hv.y, sc1, sh1), 0.f);
                    float ga = 1.f / (1.f + expf(-(acc[mi][nj][half * 2 + 0] + gv.x + b0)));
                    float gb = 1.f / (1.f + expf(-(acc[mi][nj][half * 2 + 1] + gv.y + b1)));
                    r2.x = ga * hn0 + (1.f - ga) * xv.x;
                    r2.y = gb * hn1 + (1.f - gb) * xv.y;
                    *reinterpret_cast<float2*>(x + o) = r2;
                }
                Af[rl * AFS + (col >> 1)] = packh2(r2.x, r2.y);
            }
        }
    }

    if (!has_next) return;

    // ---- phase 2: sup_next = x_new @ w_next (A resident in Af) ----
    ZERO_ACC(acc)
    {
        float4 vw0[2], vw1[2];
        ldgW(w_next, 0, tid, vw0, vw1);
        stsW(vw0, vw1, Wb[0], tid);
        __syncthreads();   // also orders Af writes before reads
#pragma unroll
        for (int kc = 0; kc < 4; kc++) {
            if (kc < 3) ldgW(w_next, kc + 1, tid, vw0, vw1);
            mma_chunk_g(Af + kc * 16, AFS, Wb[kc & 1], acc, warp_m, warp_n, lane);
            if (kc < 3) { stsW(vw0, vw1, Wb[(kc + 1) & 1], tid); __syncthreads(); }
        }
    }
#pragma unroll
    for (int mi = 0; mi < 4; mi++) {
        int r0 = row0 + warp_m * 64 + mi * 16 + g;
#pragma unroll
        for (int nj = 0; nj < 4; nj++) {
            int col = warp_n * 32 + nj * 8 + c * 2;
            if (r0 < NN)
                *reinterpret_cast<__half2*>(sup_next + (size_t)r0 * 128 + col) =
                    __floats2half2_rn(acc[mi][nj][0], acc[mi][nj][1]);
            if (r0 + 8 < NN)
                *reinterpret_cast<__half2*>(sup_next + (size_t)(r0 + 8) * 128 + col) =
                    __floats2half2_rn(acc[mi][nj][2], acc[mi][nj][3]);
        }
    }

    // ---- phase 3: gl_next = x_new @ wl_next ----
    ZERO_ACC(acc)
    {
        float4 vw0[2], vw1[2];
        ldgW(wl_next, 0, tid, vw0, vw1);
        stsW(vw0, vw1, Wb[0], tid);
        __syncthreads();
#pragma unroll
        for (int kc = 0; kc < 4; kc++) {
            if (kc < 3) ldgW(wl_next, kc + 1, tid, vw0, vw1);
            mma_chunk_g(Af + kc * 16, AFS, Wb[kc & 1], acc, warp_m, warp_n, lane);
            if (kc < 3) { stsW(vw0, vw1, Wb[(kc + 1) & 1], tid); __syncthreads(); }
        }
    }
#pragma unroll
    for (int mi = 0; mi < 4; mi++) {
        int r0 = row0 + warp_m * 64 + mi * 16 + g;
#pragma unroll
        for (int nj = 0; nj < 4; nj++) {
            int col = warp_n * 32 + nj * 8 + c * 2;
            if (r0 < NN)
                *reinterpret_cast<float2*>(gl_next + (size_t)r0 * 128 + col) =
                    make_float2(acc[mi][nj][0], acc[mi][nj][1]);
            if (r0 + 8 < NN)
                *reinterpret_cast<float2*>(gl_next + (size_t)(r0 + 8) * 128 + col) =
                    make_float2(acc[mi][nj][2], acc[mi][nj][3]);
        }
    }
}

// ---------------- CSR build ----------------

__global__ void hist_kernel(const int* __restrict__ dst, int* __restrict__ cnt) {
    int e4 = blockIdx.x * 256 + threadIdx.x;
    if (e4 >= NE / 4) return;
    int4 d = __ldg(&reinterpret_cast<const int4*>(dst)[e4]);
    atomicAdd(&cnt[d.x], 1);
    atomicAdd(&cnt[d.y], 1);
    atomicAdd(&cnt[d.z], 1);
    atomicAdd(&cnt[d.w], 1);
}

__global__ __launch_bounds__(1024) void exscan_kernel(const int* __restrict__ cnt,
                                                      int* __restrict__ rowptr,
                                                      int* __restrict__ woff) {
    __shared__ int wsum[32];
    __shared__ int s_carry;
    int t = threadIdx.x, lane = t & 31, w = t >> 5;
    if (t == 0) s_carry = 0;
    __syncthreads();
    const int NT = (NN + 1023) / 1024;
    for (int tile = 0; tile < NT; tile++) {
        int idx = tile * 1024 + t;
        int v = (idx < NN) ? cnt[idx] : 0;
        int xs = v;
#pragma unroll
        for (int o = 1; o < 32; o <<= 1) {
            int y = __shfl_up_sync(0xffffffffu, xs, o);
            if (lane >= o) xs += y;
        }
        if (lane == 31) wsum[w] = xs;
        __syncthreads();
        if (w == 0) {
            int s = wsum[lane];
#pragma unroll
            for (int o = 1; o < 32; o <<= 1) {
                int y = __shfl_up_sync(0xffffffffu, s, o);
                if (lane >= o) s += y;
            }
            wsum[lane] = s;
        }
        __syncthreads();
        int base = s_carry + (w > 0 ? wsum[w - 1] : 0);
        int excl = base + xs - v;
        if (idx < NN) { rowptr[idx] = excl; woff[idx] = excl; }
        __syncthreads();
        if (t == 0) s_carry += wsum[31];
        __syncthreads();
    }
    if (t == 0) rowptr[NN] = s_carry;
}

__global__ void scatter_kernel(const int* __restrict__ src, const int* __restrict__ dst,
                               const float* __restrict__ w, int* __restrict__ woff,
                               long long* __restrict__ esw) {
    int e = blockIdx.x * 256 + threadIdx.x;
    if (e >= NE) return;
    int d = dst[e];
    int pos = atomicAdd(&woff[d], 1);
    unsigned long long pk =
        ((unsigned long long)__float_as_uint(w[e]) << 32) | (unsigned)src[e];
    esw[pos] = (long long)pk;
}

// CSR spmm: warp per dst row, fp16 sup in, fp16 h out, fp32 fused column stats
__global__ __launch_bounds__(256) void spmm_csr(const long long* __restrict__ esw,
                                                const int* __restrict__ rowptr,
                                                const __half* __restrict__ sup,
                                                __half* __restrict__ h,
                                                float* __restrict__ stats) {
    int w = threadIdx.x >> 5, lane = threadIdx.x & 31;
    int row = blockIdx.x * 8 + w;
    const uint2* sup2 = reinterpret_cast<const uint2*>(sup);
    float4 acc = make_float4(0.f, 0.f, 0.f, 0.f);
    int b = rowptr[row], e = rowptr[row + 1];
    int i = b;
    for (; i + 3 < e; i += 4) {
        long long p0 = __ldg(&esw[i]);
        long long p1 = __ldg(&esw[i + 1]);
        long long p2 = __ldg(&esw[i + 2]);
        long long p3 = __ldg(&esw[i + 3]);
        int s0 = (int)((unsigned long long)p0 & 0xffffffffull);
        int s1 = (int)((unsigned long long)p1 & 0xffffffffull);
        int s2 = (int)((unsigned long long)p2 & 0xffffffffull);
        int s3 = (int)((unsigned long long)p3 & 0xffffffffull);
        float w0 = __uint_as_float((unsigned)((unsigned long long)p0 >> 32));
        float w1 = __uint_as_float((unsigned)((unsigned long long)p1 >> 32));
        float w2 = __uint_as_float((unsigned)((unsigned long long)p2 >> 32));
        float w3 = __uint_as_float((unsigned)((unsigned long long)p3 >> 32));
        uint2 r0 = __ldg(&sup2[(size_t)s0 * 32 + lane]);
        uint2 r1 = __ldg(&sup2[(size_t)s1 * 32 + lane]);
        uint2 r2 = __ldg(&sup2[(size_t)s2 * 32 + lane]);
        uint2 r3 = __ldg(&sup2[(size_t)s3 * 32 + lane]);
        float2 a01 = __half22float2(*reinterpret_cast<__half2*>(&r0.x));
        float2 a23 = __half22float2(*reinterpret_cast<__half2*>(&r0.y));
        acc.x += w0 * a01.x; acc.y += w0 * a01.y; acc.z += w0 * a23.x; acc.w += w0 * a23.y;
        float2 b01 = __half22float2(*reinterpret_cast<__half2*>(&r1.x));
        float2 b23 = __half22float2(*reinterpret_cast<__half2*>(&r1.y));
        acc.x += w1 * b01.x; acc.y += w1 * b01.y; acc.z += w1 * b23.x; acc.w += w1 * b23.y;
        float2 c01 = __half22float2(*reinterpret_cast<__half2*>(&r2.x));
        float2 c23 = __half22float2(*reinterpret_cast<__half2*>(&r2.y));
        acc.x += w2 * c01.x; acc.y += w2 * c01.y; acc.z += w2 * c23.x; acc.w += w2 * c23.y;
        float2 d01 = __half22float2(*reinterpret_cast<__half2*>(&r3.x));
        float2 d23 = __half22float2(*reinterpret_cast<__half2*>(&r3.y));
        acc.x += w3 * d01.x; acc.y += w3 * d01.y; acc.z += w3 * d23.x; acc.w += w3 * d23.y;
    }
    for (; i < e; i++) {
        long long p0 = __ldg(&esw[i]);
        int s0 = (int)((unsigned long long)p0 & 0xffffffffull);
        float w0 = __uint_as_float((unsigned)((unsigned long long)p0 >> 32));
        uint2 r0 = __ldg(&sup2[(size_t)s0 * 32 + lane]);
        float2 a01 = __half22float2(*reinterpret_cast<__half2*>(&r0.x));
        float2 a23 = __half22float2(*reinterpret_cast<__half2*>(&r0.y));
        acc.x += w0 * a01.x; acc.y += w0 * a01.y; acc.z += w0 * a23.x; acc.w += w0 * a23.y;
    }
    uint2 o;
    *reinterpret_cast<__half2*>(&o.x) = __floats2half2_rn(acc.x, acc.y);
    *reinterpret_cast<__half2*>(&o.y) = __floats2half2_rn(acc.z, acc.w);
    reinterpret_cast<uint2*>(h)[(size_t)row * 32 + lane] = o;

    __shared__ float sm_s[8][128];
    __shared__ float sm_q[8][128];
    float* ps = &sm_s[w][lane * 4];
    float* pq = &sm_q[w][lane * 4];
    ps[0] = acc.x; ps[1] = acc.y; ps[2] = acc.z; ps[3] = acc.w;
    pq[0] = acc.x * acc.x; pq[1] = acc.y * acc.y;
    pq[2] = acc.z * acc.z; pq[3] = acc.w * acc.w;
    __syncthreads();
    int t = threadIdx.x;
    if (t < 128) {
        float a = 0.f;
#pragma unroll
        for (int r = 0; r < 8; r++) a += sm_s[r][t];
        atomicAdd(&stats[t], a);
    } else {
        int c = t - 128;
        float a = 0.f;
#pragma unroll
        for (int r = 0; r < 8; r++) a += sm_q[r][c];
        atomicAdd(&stats[128 + c], a);
    }
}

__global__ __launch_bounds__(256) void spmm20_csr(const long long* __restrict__ esw,
                                                  const int* __restrict__ rowptr,
                                                  const float* __restrict__ sup,
                                                  float* __restrict__ h,
                                                  float* __restrict__ stats) {
    int w = threadIdx.x >> 5, lane = threadIdx.x & 31;
    int row = blockIdx.x * 8 + w;
    float acc = 0.f;
    int b = rowptr[row], e = rowptr[row + 1];
    for (int i = b; i < e; i++) {
        long long p0 = __ldg(&esw[i]);
        int s0 = (int)((unsigned long long)p0 & 0xffffffffull);
        float w0 = __uint_as_float((unsigned)((unsigned long long)p0 >> 32));
        if (lane < NO) acc += w0 * sup[(size_t)s0 * NO + lane];
    }
    if (lane < NO) h[(size_t)row * NO + lane] = acc;

    __shared__ float sm_s[8][NO];
    __shared__ float sm_q[8][NO];
    if (lane < NO) {
        sm_s[w][lane] = acc;
        sm_q[w][lane] = acc * acc;
    }
    __syncthreads();
    int t = threadIdx.x;
    if (t < NO) {
        float a = 0.f;
#pragma unroll
        for (int r = 0; r < 8; r++) a += sm_s[r][t];
        atomicAdd(&stats[t], a);
    } else if (t >= 32 && t < 32 + NO) {
        int c = t - 32;
        float a = 0.f;
#pragma unroll
        for (int r = 0; r < 8; r++) a += sm_q[r][c];
        atomicAdd(&stats[128 + c], a);
    }
}

// ---------------- other kernels ----------------

__global__ void gather_kernel(const int* __restrict__ verts,
                              const float* __restrict__ emb,
                              float* __restrict__ x) {
    int idx = blockIdx.x * blockDim.x + threadIdx.x;
    if (idx >= NN * 32) return;
    int row = idx >> 5, q = idx & 31;
    reinterpret_cast<float4*>(x)[idx] =
        reinterpret_cast<const float4*>(emb)[(size_t)verts[row] * 32 + q];
}

__global__ __launch_bounds__(256) void gemm_out_w(const float* __restrict__ A,
                                                  const float* __restrict__ W,
                                                  float* __restrict__ C) {
    __shared__ float Ws[128 * NO];
    for (int l = threadIdx.x; l < 128 * NO; l += 256) Ws[l] = W[l];
    __syncthreads();
    int w = threadIdx.x >> 5, lane = threadIdx.x & 31;
    int row = blockIdx.x * 8 + w;
    float4 a = reinterpret_cast<const float4*>(A)[(size_t)row * 32 + lane];
    float acc[NO];
    const float* w0 = &Ws[(4 * lane + 0) * NO];
    const float* w1 = &Ws[(4 * lane + 1) * NO];
    const float* w2 = &Ws[(4 * lane + 2) * NO];
    const float* w3 = &Ws[(4 * lane + 3) * NO];
#pragma unroll
    for (int c = 0; c < NO; c++)
        acc[c] = a.x * w0[c] + a.y * w1[c] + a.z * w2[c] + a.w * w3[c];
#pragma unroll
    for (int o = 16; o; o >>= 1)
#pragma unroll
        for (int c = 0; c < NO; c++)
            acc[c] += __shfl_xor_sync(0xffffffffu, acc[c], o);
    if (lane < NO) C[(size_t)row * NO + lane] = acc[lane];
}

__global__ void maskreduce_f(const float* __restrict__ h20, const int* __restrict__ verts,
                             const float* __restrict__ mask_w,
                             const float* __restrict__ stats,
                             const float* __restrict__ gamma, const float* __restrict__ beta,
                             float* __restrict__ acc) {
    int gw = (blockIdx.x * blockDim.x + threadIdx.x) >> 5;
    int lane = threadIdx.x & 31;
    int nwarps = (gridDim.x * blockDim.x) >> 5;
    float sc = 0.f, sh = 0.f;
    if (lane < NO) {
        float m = stats[lane] * (1.f / NN);
        float var = stats[128 + lane] * (1.f / NN) - m * m;
        sc = rsqrtf(var + BN_EPS) * gamma[lane];
        sh = beta[lane] - m * sc;
    }
    float a = 0.f;
    for (int r = gw; r < NN; r += nwarps) {
        float mw = mask_w[verts[r]];
        if (lane < NO) {
            float hn = fmaxf(fmaf(h20[(size_t)r * NO + lane], sc, sh), 0.f);
            a += mw * hn;
        }
    }
    if (lane < NO) atomicAdd(&acc[lane], a);
}

__global__ void finalize(const float* __restrict__ acc, const float* __restrict__ mask_b,
                         float* __restrict__ out) {
    int o = threadIdx.x;
    if (o < NO) out[o] = 1.f / (1.f + expf(-(acc[o] + mask_b[o])));
}

// ---------------- one-time host resources ----------------
struct HostRes {
    cudaStream_t s2;
    cudaEvent_t evRoot;
    cudaEvent_t evSort[7], evSpmm[7];
    HostRes() {
        cudaStreamCreateWithFlags(&s2, cudaStreamNonBlocking);
        cudaEventCreateWithFlags(&evRoot, cudaEventDisableTiming);
        for (int i = 0; i < 7; i++) {
            cudaEventCreateWithFlags(&evSort[i], cudaEventDisableTiming);
            cudaEventCreateWithFlags(&evSpmm[i], cudaEventDisableTiming);
        }
        cudaFuncSetAttribute(gemm_sup, cudaFuncAttributeMaxDynamicSharedMemorySize, DYN2);
        cudaFuncSetAttribute(gemm_gl, cudaFuncAttributeMaxDynamicSharedMemorySize, DYN2);
        cudaFuncSetAttribute(fused_layer, cudaFuncAttributeMaxDynamicSharedMemorySize, DYN3);
    }
};
static HostRes g_res;

// ---------------- launch ----------------
extern "C" void kernel_launch(void* const* d_in, const int* in_sizes, int n_in,
                              void* d_out, int out_size) {
    const int*   vertices    = (const int*)d_in[0];
    const int*   edge_index  = (const int*)d_in[1];   // [7,2,NE]
    const float* edge_weight = (const float*)d_in[2]; // [7,NE]
    const float* emb         = (const float*)d_in[3];
    const float* w_h         = (const float*)d_in[4]; // [6,128,128]
    const float* w_out       = (const float*)d_in[6]; // [128,20]
    const float* bng         = (const float*)d_in[8];
    const float* bnb         = (const float*)d_in[9];
    const float* bng_o       = (const float*)d_in[10];
    const float* bnb_o       = (const float*)d_in[11];
    const float* te_wl       = (const float*)d_in[12];
    const float* te_wc       = (const float*)d_in[13];
    const float* te_b        = (const float*)d_in[14];
    const float* mask_w      = (const float*)d_in[15];
    const float* mask_b      = (const float*)d_in[16];
    float* out = (float*)d_out;

    float *x, *gl, *sup20, *h20, *stats, *acc;
    __half *sup, *h;
    long long *esw0, *esw1;
    int *rp0, *rp1, *cnt, *woff;
    cudaGetSymbolAddress((void**)&x,     g_x);
    cudaGetSymbolAddress((void**)&sup,   g_sup);
    cudaGetSymbolAddress((void**)&h,     g_h);
    cudaGetSymbolAddress((void**)&gl,    g_gl);
    cudaGetSymbolAddress((void**)&sup20, g_sup20);
    cudaGetSymbolAddress((void**)&h20,   g_h20);
    cudaGetSymbolAddress((void**)&stats, g_stats);
    cudaGetSymbolAddress((void**)&acc,   g_acc);
    cudaGetSymbolAddress((void**)&esw0,  g_esw);
    esw1 = esw0 + NE;
    cudaGetSymbolAddress((void**)&rp0,   g_rowptr);
    rp1 = rp0 + (NN + 1);
    cudaGetSymbolAddress((void**)&cnt,   g_cnt);
    cudaGetSymbolAddress((void**)&woff,  g_woff);

    long long* eswS[2] = {esw0, esw1};
    int* rpS[2] = {rp0, rp1};

    cudaStream_t s2 = g_res.s2;
    const int TC_BLOCKS = (NN + 127) / 128;   // 391
    const int EB = (NE + 255) / 256;

    auto do_sort = [&](int L, cudaStream_t st) {
        const int* src = edge_index + (size_t)L * 2 * NE;
        const int* dst = src + NE;
        const float* ew = edge_weight + (size_t)L * NE;
        cudaMemsetAsync(cnt, 0, NN * sizeof(int), st);
        hist_kernel<<<(NE / 4 + 255) / 256, 256, 0, st>>>(dst, cnt);
        exscan_kernel<<<1, 1024, 0, st>>>(cnt, rpS[L & 1], woff);
        scatter_kernel<<<EB, 256, 0, st>>>(src, dst, ew, woff, eswS[L & 1]);
        cudaEventRecord(g_res.evSort[L], st);
    };

    // ---- fork point for sort stream ----
    cudaEventRecord(g_res.evRoot, 0);
    cudaStreamWaitEvent(s2, g_res.evRoot, 0);

    // sort layer 0 first (launches 1-4) so launch #6 = gemm_sup for ncu
    do_sort(0, s2);

    gather_kernel<<<(NN * 32 + 255) / 256, 256>>>(vertices, emb, x);     // #5
    gemm_sup<<<TC_BLOCKS, 256, DYN2>>>(x, w_h, sup);                     // #6 (ncu)
    gemm_gl<<<TC_BLOCKS, 256, DYN2>>>(x, te_wl + (size_t)5 * DD * DD, gl);
    cudaMemsetAsync(stats, 0, 7 * 256 * sizeof(float));
    cudaMemsetAsync(acc, 0, 32 * sizeof(float));

    do_sort(1, s2);

    for (int i = 0; i < NLH; i++) {
        int j = (i + 5) % 6;  // faithful to reference's (i-1) % (L-1)

        if (i >= 1) {
            cudaStreamWaitEvent(s2, g_res.evSpmm[i - 1], 0);
            do_sort(i + 1, s2);
        }

        cudaStreamWaitEvent(0, g_res.evSort[i], 0);
        spmm_csr<<<NN / 8, 256>>>(eswS[i & 1], rpS[i & 1], sup, h, stats + i * 256);
        cudaEventRecord(g_res.evSpmm[i], 0);

        if (i < NLH - 1) {
            // next layer weights: w_h[i+1], te_wl[j(i+1)] where j(i+1) == i
            fused_layer<<<TC_BLOCKS, 256, DYN3>>>(
                x, h, te_wc + (size_t)j * DD * DD, gl, te_b + j * DD,
                stats + i * 256, bng + i * DD, bnb + i * DD,
                w_h + (size_t)(i + 1) * DD * DD, te_wl + (size_t)i * DD * DD,
                sup, gl, 1);
        } else {
            fused_layer<<<TC_BLOCKS, 256, DYN3>>>(
                x, h, te_wc + (size_t)j * DD * DD, gl, te_b + j * DD,
                stats + i * 256, bng + i * DD, bnb + i * DD,
                nullptr, nullptr, nullptr, nullptr, 0);
        }
    }

    // output layer (i = 6), sorted edges in slot 6&1 = 0
    {
        gemm_out_w<<<NN / 8, 256>>>(x, w_out, sup20);
        cudaStreamWaitEvent(0, g_res.evSort[6], 0);
        spmm20_csr<<<NN / 8, 256>>>(eswS[0], rpS[0], sup20, h20, stats + 6 * 256);
        maskreduce_f<<<200, 256>>>(h20, vertices, mask_w, stats + 6 * 256,
                                   bng_o, bnb_o, acc);
    }

    finalize<<<1, 32>>>(acc, mask_b, out);
}